// round 1
// baseline (speedup 1.0000x reference)
#include <cuda_runtime.h>
#include <math.h>
#include <math_constants.h>

// Problem constants
#define BB    4
#define NN    2048
#define CC    512
#define HH    8
#define DH    64
#define HID   2048
#define MROWS (BB * NN)   // 8192
#define C3    (3 * CC)    // 1536

// ---------------------------------------------------------------------------
// Device scratch (allocation-free rule: use __device__ globals)
// ---------------------------------------------------------------------------
__device__ float g_h1  [MROWS * CC];    // ln1 output
__device__ float g_qkv [MROWS * C3];    // qkv projections
__device__ float g_attn[MROWS * CC];    // attention output (head-concat)
__device__ float g_x1  [MROWS * CC];    // residual after attention
__device__ float g_h2  [MROWS * CC];    // ln2 output
__device__ float g_hid [MROWS * HID];   // gelu(fc1)

// ---------------------------------------------------------------------------
// LayerNorm: one block per row, 256 threads, 2 elems/thread (C=512)
// ---------------------------------------------------------------------------
__global__ void ln_kernel(const float* __restrict__ x,
                          const float* __restrict__ w,
                          const float* __restrict__ b,
                          float* __restrict__ out) {
    const int row = blockIdx.x;
    const float* xr = x + (size_t)row * CC;
    float* orow = out + (size_t)row * CC;
    const int t = threadIdx.x;

    float v0 = xr[t];
    float v1 = xr[t + 256];

    __shared__ float red1[8];
    __shared__ float red2[8];

    float s = v0 + v1;
    #pragma unroll
    for (int o = 16; o > 0; o >>= 1) s += __shfl_xor_sync(0xffffffffu, s, o);
    if ((t & 31) == 0) red1[t >> 5] = s;
    __syncthreads();
    float tot = 0.f;
    #pragma unroll
    for (int i = 0; i < 8; i++) tot += red1[i];
    const float mean = tot * (1.0f / CC);

    float d0 = v0 - mean, d1 = v1 - mean;
    float s2 = d0 * d0 + d1 * d1;
    #pragma unroll
    for (int o = 16; o > 0; o >>= 1) s2 += __shfl_xor_sync(0xffffffffu, s2, o);
    if ((t & 31) == 0) red2[t >> 5] = s2;
    __syncthreads();
    float tot2 = 0.f;
    #pragma unroll
    for (int i = 0; i < 8; i++) tot2 += red2[i];
    const float inv = rsqrtf(tot2 * (1.0f / CC) + 1e-5f);

    orow[t]       = d0 * inv * w[t]       + b[t];
    orow[t + 256] = d1 * inv * w[t + 256] + b[t + 256];
}

// ---------------------------------------------------------------------------
// NT GEMM: C[M,Nn] = A[M,K] * W[Nn,K]^T  (+ epilogue)
//   EPI 0: none
//   EPI 1: + bias[n] + res[m,n]
//   EPI 2: gelu(. + bias[n])          (exact gelu via normcdf)
// Tiles: 64x64 output, BK=16. 256 threads, 4x4 per thread.
// Assumes M%64==0, Nn%64==0, K%16==0 (true for all calls).
// ---------------------------------------------------------------------------
#define FMA16(ACC, A4, B4)                                                     \
    ACC[0][0] += A4.x * B4.x; ACC[0][1] += A4.x * B4.y;                        \
    ACC[0][2] += A4.x * B4.z; ACC[0][3] += A4.x * B4.w;                        \
    ACC[1][0] += A4.y * B4.x; ACC[1][1] += A4.y * B4.y;                        \
    ACC[1][2] += A4.y * B4.z; ACC[1][3] += A4.y * B4.w;                        \
    ACC[2][0] += A4.z * B4.x; ACC[2][1] += A4.z * B4.y;                        \
    ACC[2][2] += A4.z * B4.z; ACC[2][3] += A4.z * B4.w;                        \
    ACC[3][0] += A4.w * B4.x; ACC[3][1] += A4.w * B4.y;                        \
    ACC[3][2] += A4.w * B4.z; ACC[3][3] += A4.w * B4.w;

template <int EPI>
__global__ void gemm_nt(const float* __restrict__ A,
                        const float* __restrict__ W,
                        const float* __restrict__ bias,
                        const float* __restrict__ res,
                        float* __restrict__ Cout,
                        int M, int Nn, int K) {
    __shared__ __align__(16) float As[16][64];
    __shared__ __align__(16) float Bs[16][64];

    const int tid = threadIdx.x;
    const int tx = tid & 15;
    const int ty = tid >> 4;
    const int m0 = blockIdx.y * 64;
    const int n0 = blockIdx.x * 64;

    const int lrow = tid >> 2;          // 0..63
    const int lkq  = (tid & 3) * 4;     // 0,4,8,12

    const float* Ap = A + (size_t)(m0 + lrow) * K + lkq;
    const float* Wp = W + (size_t)(n0 + lrow) * K + lkq;

    float acc[4][4] = {};

    for (int k0 = 0; k0 < K; k0 += 16) {
        float4 av = *(const float4*)(Ap + k0);
        float4 wv = *(const float4*)(Wp + k0);
        As[lkq + 0][lrow] = av.x; As[lkq + 1][lrow] = av.y;
        As[lkq + 2][lrow] = av.z; As[lkq + 3][lrow] = av.w;
        Bs[lkq + 0][lrow] = wv.x; Bs[lkq + 1][lrow] = wv.y;
        Bs[lkq + 2][lrow] = wv.z; Bs[lkq + 3][lrow] = wv.w;
        __syncthreads();
        #pragma unroll
        for (int k = 0; k < 16; k++) {
            float4 a4 = *(const float4*)&As[k][ty * 4];
            float4 b4 = *(const float4*)&Bs[k][tx * 4];
            FMA16(acc, a4, b4);
        }
        __syncthreads();
    }

    const int n = n0 + tx * 4;
    float4 bv = make_float4(0.f, 0.f, 0.f, 0.f);
    if (EPI >= 1) bv = *(const float4*)&bias[n];

    #pragma unroll
    for (int i = 0; i < 4; i++) {
        const size_t orow = (size_t)(m0 + ty * 4 + i) * Nn + n;
        float4 o;
        o.x = acc[i][0]; o.y = acc[i][1]; o.z = acc[i][2]; o.w = acc[i][3];
        if (EPI >= 1) { o.x += bv.x; o.y += bv.y; o.z += bv.z; o.w += bv.w; }
        if (EPI == 1) {
            float4 r = *(const float4*)&res[orow];
            o.x += r.x; o.y += r.y; o.z += r.z; o.w += r.w;
        }
        if (EPI == 2) {
            o.x = o.x * normcdff(o.x);
            o.y = o.y * normcdff(o.y);
            o.z = o.z * normcdff(o.z);
            o.w = o.w * normcdff(o.w);
        }
        *(float4*)&Cout[orow] = o;
    }
}

// ---------------------------------------------------------------------------
// Flash attention with relative position bias.
// grid = (N/64, B*H); block = 256 threads.
// Per block: 64 queries for one (b,h). KV processed in chunks of 64.
// Bias(q,k) = rpb[(k - q + N - 1) * H + h]  -> 127 distinct values per chunk.
// ---------------------------------------------------------------------------
#define SS_STRIDE 68   // padded score stride (16B-aligned, conflict-spread)
#define ATTN_SMEM_FLOATS (3 * 64 * 64 + 64 * SS_STRIDE + 128 + 3 * 64)
#define ATTN_SMEM_BYTES  (ATTN_SMEM_FLOATS * 4)

__global__ void attn_kernel(const float* __restrict__ qkv,
                            const float* __restrict__ rpb,
                            float* __restrict__ out) {
    extern __shared__ __align__(16) float sm[];
    float* Qs    = sm;                     // [d][q]  (transposed, pre-scaled)
    float* Ks    = Qs + 64 * 64;           // [d][k]  (transposed)
    float* Vs    = Ks + 64 * 64;           // [k][d]
    float* Ss    = Vs + 64 * 64;           // [k][q], stride SS_STRIDE
    float* biasb = Ss + 64 * SS_STRIDE;    // 127 (padded 128)
    float* mrow  = biasb + 128;            // 64
    float* lrow  = mrow + 64;              // 64
    float* srow  = lrow + 64;              // 64

    const int q0 = blockIdx.x * 64;
    const int bh = blockIdx.y;
    const int b = bh >> 3;
    const int h = bh & 7;

    const int tid = threadIdx.x;
    const int tx = tid & 15;
    const int ty = tid >> 4;

    const float scale = 0.125f;  // DH^-0.5

    // Load Q tile transposed + scaled
    #pragma unroll
    for (int it = 0; it < 4; it++) {
        int idx = tid + it * 256;
        int r = idx >> 4;
        int c = (idx & 15) * 4;
        float4 qv = *(const float4*)&qkv[(size_t)(b * NN + q0 + r) * C3 + h * DH + c];
        Qs[(c + 0) * 64 + r] = qv.x * scale;
        Qs[(c + 1) * 64 + r] = qv.y * scale;
        Qs[(c + 2) * 64 + r] = qv.z * scale;
        Qs[(c + 3) * 64 + r] = qv.w * scale;
    }
    if (tid < 64) { mrow[tid] = -CUDART_INF_F; lrow[tid] = 0.f; }

    float acco[4][4] = {};

    for (int k0 = 0; k0 < NN; k0 += 64) {
        __syncthreads();  // protect Ks/Vs/biasb against previous iteration readers

        // Load K (transposed) and V chunk
        #pragma unroll
        for (int it = 0; it < 4; it++) {
            int idx = tid + it * 256;
            int r = idx >> 4;
            int c = (idx & 15) * 4;
            const size_t base = (size_t)(b * NN + k0 + r) * C3 + h * DH + c;
            float4 kv = *(const float4*)&qkv[base + CC];
            Ks[(c + 0) * 64 + r] = kv.x;
            Ks[(c + 1) * 64 + r] = kv.y;
            Ks[(c + 2) * 64 + r] = kv.z;
            Ks[(c + 3) * 64 + r] = kv.w;
            float4 vv = *(const float4*)&qkv[base + 2 * CC];
            *(float4*)&Vs[r * 64 + c] = vv;
        }
        if (tid < 127)
            biasb[tid] = rpb[(size_t)(k0 - q0 + tid - 63 + NN - 1) * HH + h];
        __syncthreads();

        // S[k][q] = K . Q  (+bias applied at store)
        {
            float accs[4][4] = {};
            #pragma unroll 8
            for (int d = 0; d < 64; d++) {
                float4 k4 = *(const float4*)&Ks[d * 64 + ty * 4];
                float4 q4 = *(const float4*)&Qs[d * 64 + tx * 4];
                FMA16(accs, k4, q4);
            }
            #pragma unroll
            for (int i = 0; i < 4; i++)
                #pragma unroll
                for (int j = 0; j < 4; j++) {
                    int kl = ty * 4 + i, ql = tx * 4 + j;
                    Ss[kl * SS_STRIDE + ql] = accs[i][j] + biasb[kl - ql + 63];
                }
        }
        __syncthreads();

        // Online softmax over each q-row (4 threads per row)
        {
            const int r = tid >> 2;
            const int j = tid & 3;
            const float mold = mrow[r];
            float vals[16];
            float cmax = -CUDART_INF_F;
            #pragma unroll
            for (int kk = 0; kk < 16; kk++) {
                float v = Ss[(j * 16 + kk) * SS_STRIDE + r];
                vals[kk] = v;
                cmax = fmaxf(cmax, v);
            }
            cmax = fmaxf(cmax, __shfl_xor_sync(0xffffffffu, cmax, 1));
            cmax = fmaxf(cmax, __shfl_xor_sync(0xffffffffu, cmax, 2));
            const float mnew = fmaxf(mold, cmax);
            float sum = 0.f;
            #pragma unroll
            for (int kk = 0; kk < 16; kk++) {
                float p = __expf(vals[kk] - mnew);
                sum += p;
                Ss[(j * 16 + kk) * SS_STRIDE + r] = p;
            }
            sum += __shfl_xor_sync(0xffffffffu, sum, 1);
            sum += __shfl_xor_sync(0xffffffffu, sum, 2);
            if (j == 0) {
                float fac = __expf(mold - mnew);
                lrow[r] = lrow[r] * fac + sum;
                mrow[r] = mnew;
                srow[r] = fac;
            }
        }
        __syncthreads();

        // O += P @ V   (rescale running acc first)
        {
            float f0 = srow[ty * 4 + 0], f1 = srow[ty * 4 + 1];
            float f2 = srow[ty * 4 + 2], f3 = srow[ty * 4 + 3];
            #pragma unroll
            for (int j = 0; j < 4; j++) {
                acco[0][j] *= f0; acco[1][j] *= f1;
                acco[2][j] *= f2; acco[3][j] *= f3;
            }
            #pragma unroll 8
            for (int kk = 0; kk < 64; kk++) {
                float4 p4 = *(const float4*)&Ss[kk * SS_STRIDE + ty * 4];
                float4 v4 = *(const float4*)&Vs[kk * 64 + tx * 4];
                FMA16(acco, p4, v4);
            }
        }
    }

    // Final normalize + write (head-concat layout)
    const float i0 = 1.0f / lrow[ty * 4 + 0];
    const float i1 = 1.0f / lrow[ty * 4 + 1];
    const float i2 = 1.0f / lrow[ty * 4 + 2];
    const float i3 = 1.0f / lrow[ty * 4 + 3];
    float invs[4] = {i0, i1, i2, i3};
    #pragma unroll
    for (int i = 0; i < 4; i++) {
        float4 o;
        o.x = acco[i][0] * invs[i];
        o.y = acco[i][1] * invs[i];
        o.z = acco[i][2] * invs[i];
        o.w = acco[i][3] * invs[i];
        *(float4*)&out[(size_t)(b * NN + q0 + ty * 4 + i) * CC + h * DH + tx * 4] = o;
    }
}

// ---------------------------------------------------------------------------
// Launcher
// ---------------------------------------------------------------------------
extern "C" void kernel_launch(void* const* d_in, const int* in_sizes, int n_in,
                              void* d_out, int out_size) {
    const float* x      = (const float*)d_in[0];
    const float* qkv_w  = (const float*)d_in[1];
    const float* proj_w = (const float*)d_in[2];
    const float* proj_b = (const float*)d_in[3];
    const float* rpb    = (const float*)d_in[4];
    const float* n1_w   = (const float*)d_in[5];
    const float* n1_b   = (const float*)d_in[6];
    const float* n2_w   = (const float*)d_in[7];
    const float* n2_b   = (const float*)d_in[8];
    const float* fc1_w  = (const float*)d_in[9];
    const float* fc1_b  = (const float*)d_in[10];
    const float* fc2_w  = (const float*)d_in[11];
    const float* fc2_b  = (const float*)d_in[12];
    float* out = (float*)d_out;

    float *h1, *qkv, *attn, *x1, *h2, *hid;
    cudaGetSymbolAddress((void**)&h1,   g_h1);
    cudaGetSymbolAddress((void**)&qkv,  g_qkv);
    cudaGetSymbolAddress((void**)&attn, g_attn);
    cudaGetSymbolAddress((void**)&x1,   g_x1);
    cudaGetSymbolAddress((void**)&h2,   g_h2);
    cudaGetSymbolAddress((void**)&hid,  g_hid);

    cudaFuncSetAttribute(attn_kernel,
                         cudaFuncAttributeMaxDynamicSharedMemorySize,
                         ATTN_SMEM_BYTES);

    // 1) ln1
    ln_kernel<<<MROWS, 256>>>(x, n1_w, n1_b, h1);
    // 2) qkv = h1 @ qkv_w^T
    gemm_nt<0><<<dim3(C3 / 64, MROWS / 64), 256>>>(h1, qkv_w, nullptr, nullptr,
                                                   qkv, MROWS, C3, CC);
    // 3) attention
    attn_kernel<<<dim3(NN / 64, BB * HH), 256, ATTN_SMEM_BYTES>>>(qkv, rpb, attn);
    // 4) x1 = x + attn @ proj_w^T + proj_b
    gemm_nt<1><<<dim3(CC / 64, MROWS / 64), 256>>>(attn, proj_w, proj_b, x,
                                                   x1, MROWS, CC, CC);
    // 5) ln2
    ln_kernel<<<MROWS, 256>>>(x1, n2_w, n2_b, h2);
    // 6) hid = gelu(h2 @ fc1_w^T + fc1_b)
    gemm_nt<2><<<dim3(HID / 64, MROWS / 64), 256>>>(h2, fc1_w, fc1_b, nullptr,
                                                    hid, MROWS, HID, CC);
    // 7) out = x1 + hid @ fc2_w^T + fc2_b
    gemm_nt<1><<<dim3(CC / 64, MROWS / 64), 256>>>(hid, fc2_w, fc2_b, x1,
                                                   out, MROWS, CC, HID);
}

// round 3
// speedup vs baseline: 1.4633x; 1.4633x over previous
#include <cuda_runtime.h>
#include <cuda_bf16.h>
#include <math.h>
#include <math_constants.h>
#include <stdint.h>

// Problem constants
#define BB    4
#define NN    2048
#define CC    512
#define HH    8
#define DH    64
#define HID   2048
#define MROWS (BB * NN)   // 8192
#define C3    (3 * CC)    // 1536

// ---------------------------------------------------------------------------
// Device scratch (allocation-free rule: __device__ globals)
// ---------------------------------------------------------------------------
__device__ float g_qkv[MROWS * C3];     // fp32 qkv (consumed by fp32 attention)
__device__ float g_x1 [MROWS * CC];     // fp32 residual after attention

__device__ __nv_bfloat16 g_h1h[MROWS * CC],  g_h1l[MROWS * CC];
__device__ __nv_bfloat16 g_ath[MROWS * CC],  g_atl[MROWS * CC];
__device__ __nv_bfloat16 g_h2h[MROWS * CC],  g_h2l[MROWS * CC];
__device__ __nv_bfloat16 g_hdh[MROWS * HID], g_hdl[MROWS * HID];

__device__ __nv_bfloat16 g_wqh[C3 * CC],   g_wql[C3 * CC];
__device__ __nv_bfloat16 g_wph[CC * CC],   g_wpl[CC * CC];
__device__ __nv_bfloat16 g_w1h[HID * CC],  g_w1l[HID * CC];
__device__ __nv_bfloat16 g_w2h[CC * HID],  g_w2l[CC * HID];

// ---------------------------------------------------------------------------
// PTX helpers (sm_80-level only: cp.async, ldmatrix, mma.sync)
// ---------------------------------------------------------------------------
__device__ __forceinline__ uint32_t smem_u32(const void* p) {
    uint32_t a;
    asm("{ .reg .u64 t; cvta.to.shared.u64 t, %1; cvt.u32.u64 %0, t; }"
        : "=r"(a) : "l"(p));
    return a;
}

#define CP16(dst, src)                                                        \
    asm volatile("cp.async.cg.shared.global [%0], [%1], 16;"                  \
                 :: "r"(dst), "l"(src))
#define CP_COMMIT() asm volatile("cp.async.commit_group;" ::: "memory")
#define CP_WAIT1()  asm volatile("cp.async.wait_group 1;" ::: "memory")
#define CP_WAIT0()  asm volatile("cp.async.wait_group 0;" ::: "memory")

__device__ __forceinline__ void ldsm4(uint32_t* r, uint32_t addr) {
    asm volatile("ldmatrix.sync.aligned.m8n8.x4.shared.b16 {%0,%1,%2,%3}, [%4];"
                 : "=r"(r[0]), "=r"(r[1]), "=r"(r[2]), "=r"(r[3]) : "r"(addr));
}

__device__ __forceinline__ void mma16816(float* d, const uint32_t* a,
                                         uint32_t b0, uint32_t b1) {
    asm volatile(
        "mma.sync.aligned.m16n8k16.row.col.f32.bf16.bf16.f32 "
        "{%0,%1,%2,%3}, {%4,%5,%6,%7}, {%8,%9}, {%0,%1,%2,%3};"
        : "+f"(d[0]), "+f"(d[1]), "+f"(d[2]), "+f"(d[3])
        : "r"(a[0]), "r"(a[1]), "r"(a[2]), "r"(a[3]), "r"(b0), "r"(b1));
}

__device__ __forceinline__ uint32_t sw128(uint32_t off) {
    return off ^ ((off >> 3) & 0x70u);
}

// ---------------------------------------------------------------------------
// fp32 -> bf16 hi/lo split (weights)
// ---------------------------------------------------------------------------
__global__ void cvt_kernel(const float* __restrict__ x,
                           __nv_bfloat16* __restrict__ hi,
                           __nv_bfloat16* __restrict__ lo, int n4) {
    int i = blockIdx.x * blockDim.x + threadIdx.x;
    if (i >= n4) return;
    float4 v = *(const float4*)(x + 4 * (size_t)i);
    __nv_bfloat16 h0 = __float2bfloat16(v.x), h1 = __float2bfloat16(v.y);
    __nv_bfloat16 h2 = __float2bfloat16(v.z), h3 = __float2bfloat16(v.w);
    __nv_bfloat16 l0 = __float2bfloat16(v.x - __bfloat162float(h0));
    __nv_bfloat16 l1 = __float2bfloat16(v.y - __bfloat162float(h1));
    __nv_bfloat16 l2 = __float2bfloat16(v.z - __bfloat162float(h2));
    __nv_bfloat16 l3 = __float2bfloat16(v.w - __bfloat162float(h3));
    __nv_bfloat162 ph0; ph0.x = h0; ph0.y = h1;
    __nv_bfloat162 ph1; ph1.x = h2; ph1.y = h3;
    __nv_bfloat162 pl0; pl0.x = l0; pl0.y = l1;
    __nv_bfloat162 pl1; pl1.x = l2; pl1.y = l3;
    *(__nv_bfloat162*)(hi + 4 * (size_t)i)     = ph0;
    *(__nv_bfloat162*)(hi + 4 * (size_t)i + 2) = ph1;
    *(__nv_bfloat162*)(lo + 4 * (size_t)i)     = pl0;
    *(__nv_bfloat162*)(lo + 4 * (size_t)i + 2) = pl1;
}

// ---------------------------------------------------------------------------
// LayerNorm -> bf16 hi/lo
// ---------------------------------------------------------------------------
__global__ void ln_kernel(const float* __restrict__ x,
                          const float* __restrict__ w,
                          const float* __restrict__ b,
                          __nv_bfloat16* __restrict__ ohi,
                          __nv_bfloat16* __restrict__ olo) {
    const int row = blockIdx.x;
    const float* xr = x + (size_t)row * CC;
    const int t = threadIdx.x;

    float v0 = xr[t];
    float v1 = xr[t + 256];

    __shared__ float red1[8];
    __shared__ float red2[8];

    float s = v0 + v1;
    #pragma unroll
    for (int o = 16; o > 0; o >>= 1) s += __shfl_xor_sync(0xffffffffu, s, o);
    if ((t & 31) == 0) red1[t >> 5] = s;
    __syncthreads();
    float tot = 0.f;
    #pragma unroll
    for (int i = 0; i < 8; i++) tot += red1[i];
    const float mean = tot * (1.0f / CC);

    float d0 = v0 - mean, d1 = v1 - mean;
    float s2 = d0 * d0 + d1 * d1;
    #pragma unroll
    for (int o = 16; o > 0; o >>= 1) s2 += __shfl_xor_sync(0xffffffffu, s2, o);
    if ((t & 31) == 0) red2[t >> 5] = s2;
    __syncthreads();
    float tot2 = 0.f;
    #pragma unroll
    for (int i = 0; i < 8; i++) tot2 += red2[i];
    const float inv = rsqrtf(tot2 * (1.0f / CC) + 1e-5f);

    float y0 = d0 * inv * w[t]       + b[t];
    float y1 = d1 * inv * w[t + 256] + b[t + 256];

    __nv_bfloat16 h0 = __float2bfloat16(y0);
    __nv_bfloat16 h1 = __float2bfloat16(y1);
    ohi[(size_t)row * CC + t]       = h0;
    ohi[(size_t)row * CC + t + 256] = h1;
    olo[(size_t)row * CC + t]       = __float2bfloat16(y0 - __bfloat162float(h0));
    olo[(size_t)row * CC + t + 256] = __float2bfloat16(y1 - __bfloat162float(h1));
}

// ---------------------------------------------------------------------------
// mma.sync split-bf16 NT GEMM:  C[M,Nn] = A[M,K] * W[Nn,K]^T
// CTA tile 128x128, BK=64, 8 warps (warp tile 64x32), double-buffered cp.async.
// 3-pass split precision: D = Ah*Bh + Ah*Bl + Al*Bh   (fp32 accum)
//   EPI 0: fp32 out
//   EPI 1: fp32 out = acc + bias[n] + res[m,n]
//   EPI 2: bf16 hi/lo out = gelu(acc + bias[n])
// SMEM stage layout: [Ah 16K][Al 16K][Bh 16K][Bl 16K], rows of 128B, SW128.
// ---------------------------------------------------------------------------
#define GEMM_SMEM_BYTES (2 * 65536)

__device__ __forceinline__ void load_chunk(
    const __nv_bfloat16* __restrict__ Ah, const __nv_bfloat16* __restrict__ Al,
    const __nv_bfloat16* __restrict__ Bh, const __nv_bfloat16* __restrict__ Bl,
    int K, int m0, int n0, int kc, uint32_t sbuf, int tid) {
    const int base = tid * 4;
    #pragma unroll
    for (int j = 0; j < 4; j++) {
        int idx = base + j;
        int r = idx >> 3;       // 0..127
        int c = idx & 7;        // 0..7 (16B chunk within 128B row)
        uint32_t sw = sw128((uint32_t)(r * 128 + c * 16));
        size_t eA = ((size_t)(m0 + r) * K + (size_t)kc * 64 + c * 8) * 2;
        size_t eB = ((size_t)(n0 + r) * K + (size_t)kc * 64 + c * 8) * 2;
        CP16(sbuf + sw,          (const char*)Ah + eA);
        CP16(sbuf + 16384 + sw,  (const char*)Al + eA);
        CP16(sbuf + 32768 + sw,  (const char*)Bh + eB);
        CP16(sbuf + 49152 + sw,  (const char*)Bl + eB);
    }
}

template <int EPI>
__global__ __launch_bounds__(256, 1)
void gemm_tc(const __nv_bfloat16* __restrict__ Ah,
             const __nv_bfloat16* __restrict__ Al,
             const __nv_bfloat16* __restrict__ Bh,
             const __nv_bfloat16* __restrict__ Bl,
             const float* __restrict__ bias,
             const float* __restrict__ res,
             float* __restrict__ outF,
             __nv_bfloat16* __restrict__ outHi,
             __nv_bfloat16* __restrict__ outLo,
             int M, int Nn, int K) {
    extern __shared__ char dsm[];
    const uint32_t buf0 = smem_u32(dsm);
    const uint32_t buf1 = buf0 + 65536;

    const int tid  = threadIdx.x;
    const int wid  = tid >> 5;
    const int lane = tid & 31;

    const int m0 = blockIdx.y * 128;
    const int n0 = blockIdx.x * 128;
    const int NK = K >> 6;

    const int warp_m = (wid & 1) * 64;
    const int warp_n = (wid >> 1) * 32;

    // ldmatrix per-lane addressing pattern (x4):
    //  lanes 0-7: rows 0-7 k+0 | 8-15: rows 8-15 k+0 | 16-23: rows 0-7 k+8 | 24-31: rows 8-15 k+8
    const int lrow = lane & 7;
    const int sel  = lane >> 3;
    const int rofs = lrow + ((sel & 1) ? 8 : 0);
    const int kofs = (sel & 2) ? 8 : 0;

    float d[4][4][4] = {};

    load_chunk(Ah, Al, Bh, Bl, K, m0, n0, 0, buf0, tid);
    CP_COMMIT();

    for (int kc = 0; kc < NK; kc++) {
        const uint32_t bufc = (kc & 1) ? buf1 : buf0;
        if (kc + 1 < NK) {
            load_chunk(Ah, Al, Bh, Bl, K, m0, n0, kc + 1,
                       (kc & 1) ? buf0 : buf1, tid);
            CP_COMMIT();
            CP_WAIT1();
        } else {
            CP_WAIT0();
        }
        __syncthreads();

        const uint32_t aH = bufc;
        const uint32_t aL = bufc + 16384;
        const uint32_t bH = bufc + 32768;
        const uint32_t bL = bufc + 49152;

        #pragma unroll
        for (int ks = 0; ks < 4; ks++) {
            const int kk = ks * 16 + kofs;
            uint32_t ah[4][4], al[4][4], bh[2][4], bl[2][4];
            #pragma unroll
            for (int mi = 0; mi < 4; mi++) {
                uint32_t off = sw128((uint32_t)((warp_m + 16 * mi + rofs) * 128 + kk * 2));
                ldsm4(ah[mi], aH + off);
                ldsm4(al[mi], aL + off);
            }
            #pragma unroll
            for (int nj = 0; nj < 2; nj++) {
                uint32_t off = sw128((uint32_t)((warp_n + 16 * nj + rofs) * 128 + kk * 2));
                ldsm4(bh[nj], bH + off);
                ldsm4(bl[nj], bL + off);
            }
            // b-frag extraction: x4 regs = {n0-7/k0-7, n8-15/k0-7, n0-7/k8-15, n8-15/k8-15}
            #pragma unroll
            for (int mi = 0; mi < 4; mi++) {
                #pragma unroll
                for (int nt = 0; nt < 4; nt++) {
                    const int nj = nt >> 1;
                    const int p  = nt & 1;
                    mma16816(d[mi][nt], ah[mi], bh[nj][p], bh[nj][p + 2]);
                    mma16816(d[mi][nt], ah[mi], bl[nj][p], bl[nj][p + 2]);
                    mma16816(d[mi][nt], al[mi], bh[nj][p], bh[nj][p + 2]);
                }
            }
        }
        __syncthreads();
    }

    // Epilogue: lane l of mma tile holds rows (l/4, l/4+8), cols (l%4)*2+{0,1}
    const int erow0 = m0 + warp_m + (lane >> 2);
    const int ecol0 = n0 + warp_n + (lane & 3) * 2;

    #pragma unroll
    for (int mi = 0; mi < 4; mi++) {
        #pragma unroll
        for (int nt = 0; nt < 4; nt++) {
            const int col = ecol0 + nt * 8;
            #pragma unroll
            for (int half = 0; half < 2; half++) {
                const int row = erow0 + mi * 16 + half * 8;
                float v0 = d[mi][nt][2 * half + 0];
                float v1 = d[mi][nt][2 * half + 1];
                const size_t ob = (size_t)row * Nn + col;
                if (EPI == 0) {
                    *(float2*)(outF + ob) = make_float2(v0, v1);
                } else if (EPI == 1) {
                    float2 rv = *(const float2*)(res + ob);
                    v0 += bias[col]     + rv.x;
                    v1 += bias[col + 1] + rv.y;
                    *(float2*)(outF + ob) = make_float2(v0, v1);
                } else {
                    v0 += bias[col];
                    v1 += bias[col + 1];
                    float g0 = v0 * normcdff(v0);
                    float g1 = v1 * normcdff(v1);
                    __nv_bfloat16 h0 = __float2bfloat16(g0);
                    __nv_bfloat16 h1 = __float2bfloat16(g1);
                    __nv_bfloat162 ph; ph.x = h0; ph.y = h1;
                    __nv_bfloat162 pl;
                    pl.x = __float2bfloat16(g0 - __bfloat162float(h0));
                    pl.y = __float2bfloat16(g1 - __bfloat162float(h1));
                    *(__nv_bfloat162*)(outHi + ob) = ph;
                    *(__nv_bfloat162*)(outLo + ob) = pl;
                }
            }
        }
    }
}

// ---------------------------------------------------------------------------
// Flash attention (fp32) with bf16 hi/lo output
// ---------------------------------------------------------------------------
#define FMA16(ACC, A4, B4)                                                     \
    ACC[0][0] += A4.x * B4.x; ACC[0][1] += A4.x * B4.y;                        \
    ACC[0][2] += A4.x * B4.z; ACC[0][3] += A4.x * B4.w;                        \
    ACC[1][0] += A4.y * B4.x; ACC[1][1] += A4.y * B4.y;                        \
    ACC[1][2] += A4.y * B4.z; ACC[1][3] += A4.y * B4.w;                        \
    ACC[2][0] += A4.z * B4.x; ACC[2][1] += A4.z * B4.y;                        \
    ACC[2][2] += A4.z * B4.z; ACC[2][3] += A4.z * B4.w;                        \
    ACC[3][0] += A4.w * B4.x; ACC[3][1] += A4.w * B4.y;                        \
    ACC[3][2] += A4.w * B4.z; ACC[3][3] += A4.w * B4.w;

#define SS_STRIDE 68
#define ATTN_SMEM_FLOATS (3 * 64 * 64 + 64 * SS_STRIDE + 128 + 3 * 64)
#define ATTN_SMEM_BYTES  (ATTN_SMEM_FLOATS * 4)

__global__ void attn_kernel(const float* __restrict__ qkv,
                            const float* __restrict__ rpb,
                            __nv_bfloat16* __restrict__ outHi,
                            __nv_bfloat16* __restrict__ outLo) {
    extern __shared__ __align__(16) float sm[];
    float* Qs    = sm;
    float* Ks    = Qs + 64 * 64;
    float* Vs    = Ks + 64 * 64;
    float* Ss    = Vs + 64 * 64;
    float* biasb = Ss + 64 * SS_STRIDE;
    float* mrow  = biasb + 128;
    float* lrow  = mrow + 64;
    float* srow  = lrow + 64;

    const int q0 = blockIdx.x * 64;
    const int bh = blockIdx.y;
    const int b = bh >> 3;
    const int h = bh & 7;

    const int tid = threadIdx.x;
    const int tx = tid & 15;
    const int ty = tid >> 4;

    const float scale = 0.125f;

    #pragma unroll
    for (int it = 0; it < 4; it++) {
        int idx = tid + it * 256;
        int r = idx >> 4;
        int c = (idx & 15) * 4;
        float4 qv = *(const float4*)&qkv[(size_t)(b * NN + q0 + r) * C3 + h * DH + c];
        Qs[(c + 0) * 64 + r] = qv.x * scale;
        Qs[(c + 1) * 64 + r] = qv.y * scale;
        Qs[(c + 2) * 64 + r] = qv.z * scale;
        Qs[(c + 3) * 64 + r] = qv.w * scale;
    }
    if (tid < 64) { mrow[tid] = -CUDART_INF_F; lrow[tid] = 0.f; }

    float acco[4][4] = {};

    for (int k0 = 0; k0 < NN; k0 += 64) {
        __syncthreads();
        #pragma unroll
        for (int it = 0; it < 4; it++) {
            int idx = tid + it * 256;
            int r = idx >> 4;
            int c = (idx & 15) * 4;
            const size_t base = (size_t)(b * NN + k0 + r) * C3 + h * DH + c;
            float4 kv = *(const float4*)&qkv[base + CC];
            Ks[(c + 0) * 64 + r] = kv.x;
            Ks[(c + 1) * 64 + r] = kv.y;
            Ks[(c + 2) * 64 + r] = kv.z;
            Ks[(c + 3) * 64 + r] = kv.w;
            float4 vv = *(const float4*)&qkv[base + 2 * CC];
            *(float4*)&Vs[r * 64 + c] = vv;
        }
        if (tid < 127)
            biasb[tid] = rpb[(size_t)(k0 - q0 + tid - 63 + NN - 1) * HH + h];
        __syncthreads();

        {
            float accs[4][4] = {};
            #pragma unroll 8
            for (int d = 0; d < 64; d++) {
                float4 k4 = *(const float4*)&Ks[d * 64 + ty * 4];
                float4 q4 = *(const float4*)&Qs[d * 64 + tx * 4];
                FMA16(accs, k4, q4);
            }
            #pragma unroll
            for (int i = 0; i < 4; i++)
                #pragma unroll
                for (int j = 0; j < 4; j++) {
                    int kl = ty * 4 + i, ql = tx * 4 + j;
                    Ss[kl * SS_STRIDE + ql] = accs[i][j] + biasb[kl - ql + 63];
                }
        }
        __syncthreads();

        {
            const int r = tid >> 2;
            const int j = tid & 3;
            const float mold = mrow[r];
            float vals[16];
            float cmax = -CUDART_INF_F;
            #pragma unroll
            for (int kk = 0; kk < 16; kk++) {
                float v = Ss[(j * 16 + kk) * SS_STRIDE + r];
                vals[kk] = v;
                cmax = fmaxf(cmax, v);
            }
            cmax = fmaxf(cmax, __shfl_xor_sync(0xffffffffu, cmax, 1));
            cmax = fmaxf(cmax, __shfl_xor_sync(0xffffffffu, cmax, 2));
            const float mnew = fmaxf(mold, cmax);
            float sum = 0.f;
            #pragma unroll
            for (int kk = 0; kk < 16; kk++) {
                float p = __expf(vals[kk] - mnew);
                sum += p;
                Ss[(j * 16 + kk) * SS_STRIDE + r] = p;
            }
            sum += __shfl_xor_sync(0xffffffffu, sum, 1);
            sum += __shfl_xor_sync(0xffffffffu, sum, 2);
            if (j == 0) {
                float fac = __expf(mold - mnew);
                lrow[r] = lrow[r] * fac + sum;
                mrow[r] = mnew;
                srow[r] = fac;
            }
        }
        __syncthreads();

        {
            float f0 = srow[ty * 4 + 0], f1 = srow[ty * 4 + 1];
            float f2 = srow[ty * 4 + 2], f3 = srow[ty * 4 + 3];
            #pragma unroll
            for (int j = 0; j < 4; j++) {
                acco[0][j] *= f0; acco[1][j] *= f1;
                acco[2][j] *= f2; acco[3][j] *= f3;
            }
            #pragma unroll 8
            for (int kk = 0; kk < 64; kk++) {
                float4 p4 = *(const float4*)&Ss[kk * SS_STRIDE + ty * 4];
                float4 v4 = *(const float4*)&Vs[kk * 64 + tx * 4];
                FMA16(acco, p4, v4);
            }
        }
    }

    const float i0 = 1.0f / lrow[ty * 4 + 0];
    const float i1 = 1.0f / lrow[ty * 4 + 1];
    const float i2 = 1.0f / lrow[ty * 4 + 2];
    const float i3 = 1.0f / lrow[ty * 4 + 3];
    float invs[4] = {i0, i1, i2, i3};
    #pragma unroll
    for (int i = 0; i < 4; i++) {
        const size_t obase = (size_t)(b * NN + q0 + ty * 4 + i) * CC + h * DH + tx * 4;
        #pragma unroll
        for (int j = 0; j < 4; j += 2) {
            float o0 = acco[i][j]     * invs[i];
            float o1 = acco[i][j + 1] * invs[i];
            __nv_bfloat16 h0 = __float2bfloat16(o0);
            __nv_bfloat16 h1 = __float2bfloat16(o1);
            __nv_bfloat162 ph; ph.x = h0; ph.y = h1;
            __nv_bfloat162 pl;
            pl.x = __float2bfloat16(o0 - __bfloat162float(h0));
            pl.y = __float2bfloat16(o1 - __bfloat162float(h1));
            *(__nv_bfloat162*)(outHi + obase + j) = ph;
            *(__nv_bfloat162*)(outLo + obase + j) = pl;
        }
    }
}

// ---------------------------------------------------------------------------
// Launcher
// ---------------------------------------------------------------------------
extern "C" void kernel_launch(void* const* d_in, const int* in_sizes, int n_in,
                              void* d_out, int out_size) {
    const float* x      = (const float*)d_in[0];
    const float* qkv_w  = (const float*)d_in[1];
    const float* proj_w = (const float*)d_in[2];
    const float* proj_b = (const float*)d_in[3];
    const float* rpb    = (const float*)d_in[4];
    const float* n1_w   = (const float*)d_in[5];
    const float* n1_b   = (const float*)d_in[6];
    const float* n2_w   = (const float*)d_in[7];
    const float* n2_b   = (const float*)d_in[8];
    const float* fc1_w  = (const float*)d_in[9];
    const float* fc1_b  = (const float*)d_in[10];
    const float* fc2_w  = (const float*)d_in[11];
    const float* fc2_b  = (const float*)d_in[12];
    float* out = (float*)d_out;

    float *qkv, *x1;
    __nv_bfloat16 *h1h, *h1l, *ath, *atl, *h2h, *h2l, *hdh, *hdl;
    __nv_bfloat16 *wqh, *wql, *wph, *wpl, *w1h, *w1l, *w2h, *w2l;
    cudaGetSymbolAddress((void**)&qkv, g_qkv);
    cudaGetSymbolAddress((void**)&x1,  g_x1);
    cudaGetSymbolAddress((void**)&h1h, g_h1h); cudaGetSymbolAddress((void**)&h1l, g_h1l);
    cudaGetSymbolAddress((void**)&ath, g_ath); cudaGetSymbolAddress((void**)&atl, g_atl);
    cudaGetSymbolAddress((void**)&h2h, g_h2h); cudaGetSymbolAddress((void**)&h2l, g_h2l);
    cudaGetSymbolAddress((void**)&hdh, g_hdh); cudaGetSymbolAddress((void**)&hdl, g_hdl);
    cudaGetSymbolAddress((void**)&wqh, g_wqh); cudaGetSymbolAddress((void**)&wql, g_wql);
    cudaGetSymbolAddress((void**)&wph, g_wph); cudaGetSymbolAddress((void**)&wpl, g_wpl);
    cudaGetSymbolAddress((void**)&w1h, g_w1h); cudaGetSymbolAddress((void**)&w1l, g_w1l);
    cudaGetSymbolAddress((void**)&w2h, g_w2h); cudaGetSymbolAddress((void**)&w2l, g_w2l);

    cudaFuncSetAttribute(gemm_tc<0>, cudaFuncAttributeMaxDynamicSharedMemorySize, GEMM_SMEM_BYTES);
    cudaFuncSetAttribute(gemm_tc<1>, cudaFuncAttributeMaxDynamicSharedMemorySize, GEMM_SMEM_BYTES);
    cudaFuncSetAttribute(gemm_tc<2>, cudaFuncAttributeMaxDynamicSharedMemorySize, GEMM_SMEM_BYTES);
    cudaFuncSetAttribute(attn_kernel, cudaFuncAttributeMaxDynamicSharedMemorySize, ATTN_SMEM_BYTES);

    // Weight conversions (fp32 -> bf16 hi/lo)
    cvt_kernel<<<(C3 * CC) / 1024, 256>>>(qkv_w, wqh, wql, (C3 * CC) / 4);
    cvt_kernel<<<(CC * CC) / 1024, 256>>>(proj_w, wph, wpl, (CC * CC) / 4);
    cvt_kernel<<<(HID * CC) / 1024, 256>>>(fc1_w, w1h, w1l, (HID * CC) / 4);
    cvt_kernel<<<(CC * HID) / 1024, 256>>>(fc2_w, w2h, w2l, (CC * HID) / 4);

    // 1) ln1 -> h1 (hi/lo)
    ln_kernel<<<MROWS, 256>>>(x, n1_w, n1_b, h1h, h1l);
    // 2) qkv = h1 @ qkv_w^T  (fp32 out)
    gemm_tc<0><<<dim3(C3 / 128, MROWS / 128), 256, GEMM_SMEM_BYTES>>>(
        h1h, h1l, wqh, wql, nullptr, nullptr, qkv, nullptr, nullptr,
        MROWS, C3, CC);
    // 3) attention -> attn (hi/lo)
    attn_kernel<<<dim3(NN / 64, BB * HH), 256, ATTN_SMEM_BYTES>>>(qkv, rpb, ath, atl);
    // 4) x1 = x + attn @ proj_w^T + proj_b
    gemm_tc<1><<<dim3(CC / 128, MROWS / 128), 256, GEMM_SMEM_BYTES>>>(
        ath, atl, wph, wpl, proj_b, x, x1, nullptr, nullptr,
        MROWS, CC, CC);
    // 5) ln2 -> h2 (hi/lo)
    ln_kernel<<<MROWS, 256>>>(x1, n2_w, n2_b, h2h, h2l);
    // 6) hid = gelu(h2 @ fc1_w^T + fc1_b)  (hi/lo out)
    gemm_tc<2><<<dim3(HID / 128, MROWS / 128), 256, GEMM_SMEM_BYTES>>>(
        h2h, h2l, w1h, w1l, fc1_b, nullptr, nullptr, hdh, hdl,
        MROWS, HID, CC);
    // 7) out = x1 + hid @ fc2_w^T + fc2_b
    gemm_tc<1><<<dim3(CC / 128, MROWS / 128), 256, GEMM_SMEM_BYTES>>>(
        hdh, hdl, w2h, w2l, fc2_b, x1, out, nullptr, nullptr,
        MROWS, CC, HID);
}

// round 4
// speedup vs baseline: 2.7653x; 1.8898x over previous
#include <cuda_runtime.h>
#include <cuda_bf16.h>
#include <math.h>
#include <math_constants.h>
#include <stdint.h>

// Problem constants
#define BB    4
#define NN    2048
#define CC    512
#define HH    8
#define DH    64
#define HID   2048
#define MROWS (BB * NN)   // 8192
#define C3    (3 * CC)    // 1536

// ---------------------------------------------------------------------------
// Device scratch
// ---------------------------------------------------------------------------
__device__ float g_x1 [MROWS * CC];     // fp32 residual after attention

__device__ __nv_bfloat16 g_qvh[MROWS * C3],  g_qvl[MROWS * C3];
__device__ __nv_bfloat16 g_h1h[MROWS * CC],  g_h1l[MROWS * CC];
__device__ __nv_bfloat16 g_ath[MROWS * CC],  g_atl[MROWS * CC];
__device__ __nv_bfloat16 g_h2h[MROWS * CC],  g_h2l[MROWS * CC];
__device__ __nv_bfloat16 g_hdh[MROWS * HID], g_hdl[MROWS * HID];

__device__ __nv_bfloat16 g_wqh[C3 * CC],   g_wql[C3 * CC];
__device__ __nv_bfloat16 g_wph[CC * CC],   g_wpl[CC * CC];
__device__ __nv_bfloat16 g_w1h[HID * CC],  g_w1l[HID * CC];
__device__ __nv_bfloat16 g_w2h[CC * HID],  g_w2l[CC * HID];

// ---------------------------------------------------------------------------
// PTX helpers (sm_80-level: cp.async, ldmatrix, mma.sync)
// ---------------------------------------------------------------------------
__device__ __forceinline__ uint32_t smem_u32(const void* p) {
    uint32_t a;
    asm("{ .reg .u64 t; cvta.to.shared.u64 t, %1; cvt.u32.u64 %0, t; }"
        : "=r"(a) : "l"(p));
    return a;
}

#define CP16(dst, src)                                                        \
    asm volatile("cp.async.cg.shared.global [%0], [%1], 16;"                  \
                 :: "r"(dst), "l"(src))
#define CP4(dst, src)                                                         \
    asm volatile("cp.async.ca.shared.global [%0], [%1], 4;"                   \
                 :: "r"(dst), "l"(src))
#define CP_COMMIT() asm volatile("cp.async.commit_group;" ::: "memory")
#define CP_WAIT1()  asm volatile("cp.async.wait_group 1;" ::: "memory")
#define CP_WAIT0()  asm volatile("cp.async.wait_group 0;" ::: "memory")

__device__ __forceinline__ void ldsm4(uint32_t* r, uint32_t addr) {
    asm volatile("ldmatrix.sync.aligned.m8n8.x4.shared.b16 {%0,%1,%2,%3}, [%4];"
                 : "=r"(r[0]), "=r"(r[1]), "=r"(r[2]), "=r"(r[3]) : "r"(addr));
}

__device__ __forceinline__ void ldsm4t(uint32_t* r, uint32_t addr) {
    asm volatile("ldmatrix.sync.aligned.m8n8.x4.trans.shared.b16 {%0,%1,%2,%3}, [%4];"
                 : "=r"(r[0]), "=r"(r[1]), "=r"(r[2]), "=r"(r[3]) : "r"(addr));
}

__device__ __forceinline__ void mma16816(float* d, const uint32_t* a,
                                         uint32_t b0, uint32_t b1) {
    asm volatile(
        "mma.sync.aligned.m16n8k16.row.col.f32.bf16.bf16.f32 "
        "{%0,%1,%2,%3}, {%4,%5,%6,%7}, {%8,%9}, {%0,%1,%2,%3};"
        : "+f"(d[0]), "+f"(d[1]), "+f"(d[2]), "+f"(d[3])
        : "r"(a[0]), "r"(a[1]), "r"(a[2]), "r"(a[3]), "r"(b0), "r"(b1));
}

__device__ __forceinline__ uint32_t sw128(uint32_t off) {
    return off ^ ((off >> 3) & 0x70u);
}

__device__ __forceinline__ uint32_t pack_bf16(float a, float b) {
    __nv_bfloat162 p;
    p.x = __float2bfloat16(a);
    p.y = __float2bfloat16(b);
    return *(uint32_t*)&p;
}

// ---------------------------------------------------------------------------
// fp32 -> bf16 hi/lo split (weights)
// ---------------------------------------------------------------------------
__global__ void cvt_kernel(const float* __restrict__ x,
                           __nv_bfloat16* __restrict__ hi,
                           __nv_bfloat16* __restrict__ lo, int n4) {
    int i = blockIdx.x * blockDim.x + threadIdx.x;
    if (i >= n4) return;
    float4 v = *(const float4*)(x + 4 * (size_t)i);
    __nv_bfloat16 h0 = __float2bfloat16(v.x), h1 = __float2bfloat16(v.y);
    __nv_bfloat16 h2 = __float2bfloat16(v.z), h3 = __float2bfloat16(v.w);
    __nv_bfloat162 ph0; ph0.x = h0; ph0.y = h1;
    __nv_bfloat162 ph1; ph1.x = h2; ph1.y = h3;
    __nv_bfloat162 pl0;
    pl0.x = __float2bfloat16(v.x - __bfloat162float(h0));
    pl0.y = __float2bfloat16(v.y - __bfloat162float(h1));
    __nv_bfloat162 pl1;
    pl1.x = __float2bfloat16(v.z - __bfloat162float(h2));
    pl1.y = __float2bfloat16(v.w - __bfloat162float(h3));
    *(__nv_bfloat162*)(hi + 4 * (size_t)i)     = ph0;
    *(__nv_bfloat162*)(hi + 4 * (size_t)i + 2) = ph1;
    *(__nv_bfloat162*)(lo + 4 * (size_t)i)     = pl0;
    *(__nv_bfloat162*)(lo + 4 * (size_t)i + 2) = pl1;
}

// ---------------------------------------------------------------------------
// LayerNorm -> bf16 hi/lo
// ---------------------------------------------------------------------------
__global__ void ln_kernel(const float* __restrict__ x,
                          const float* __restrict__ w,
                          const float* __restrict__ b,
                          __nv_bfloat16* __restrict__ ohi,
                          __nv_bfloat16* __restrict__ olo) {
    const int row = blockIdx.x;
    const float* xr = x + (size_t)row * CC;
    const int t = threadIdx.x;

    float v0 = xr[t];
    float v1 = xr[t + 256];

    __shared__ float red1[8];
    __shared__ float red2[8];

    float s = v0 + v1;
    #pragma unroll
    for (int o = 16; o > 0; o >>= 1) s += __shfl_xor_sync(0xffffffffu, s, o);
    if ((t & 31) == 0) red1[t >> 5] = s;
    __syncthreads();
    float tot = 0.f;
    #pragma unroll
    for (int i = 0; i < 8; i++) tot += red1[i];
    const float mean = tot * (1.0f / CC);

    float d0 = v0 - mean, d1 = v1 - mean;
    float s2 = d0 * d0 + d1 * d1;
    #pragma unroll
    for (int o = 16; o > 0; o >>= 1) s2 += __shfl_xor_sync(0xffffffffu, s2, o);
    if ((t & 31) == 0) red2[t >> 5] = s2;
    __syncthreads();
    float tot2 = 0.f;
    #pragma unroll
    for (int i = 0; i < 8; i++) tot2 += red2[i];
    const float inv = rsqrtf(tot2 * (1.0f / CC) + 1e-5f);

    float y0 = d0 * inv * w[t]       + b[t];
    float y1 = d1 * inv * w[t + 256] + b[t + 256];

    __nv_bfloat16 h0 = __float2bfloat16(y0);
    __nv_bfloat16 h1 = __float2bfloat16(y1);
    ohi[(size_t)row * CC + t]       = h0;
    ohi[(size_t)row * CC + t + 256] = h1;
    olo[(size_t)row * CC + t]       = __float2bfloat16(y0 - __bfloat162float(h0));
    olo[(size_t)row * CC + t + 256] = __float2bfloat16(y1 - __bfloat162float(h1));
}

// ---------------------------------------------------------------------------
// mma.sync split-bf16 NT GEMM (unchanged from R3 except EPI 3 added)
//   EPI 0: fp32 out   EPI 1: +bias+res fp32   EPI 2: gelu->hi/lo   EPI 3: hi/lo
// ---------------------------------------------------------------------------
#define GEMM_SMEM_BYTES (2 * 65536)

__device__ __forceinline__ void load_chunk(
    const __nv_bfloat16* __restrict__ Ah, const __nv_bfloat16* __restrict__ Al,
    const __nv_bfloat16* __restrict__ Bh, const __nv_bfloat16* __restrict__ Bl,
    int K, int m0, int n0, int kc, uint32_t sbuf, int tid) {
    const int base = tid * 4;
    #pragma unroll
    for (int j = 0; j < 4; j++) {
        int idx = base + j;
        int r = idx >> 3;
        int c = idx & 7;
        uint32_t sw = sw128((uint32_t)(r * 128 + c * 16));
        size_t eA = ((size_t)(m0 + r) * K + (size_t)kc * 64 + c * 8) * 2;
        size_t eB = ((size_t)(n0 + r) * K + (size_t)kc * 64 + c * 8) * 2;
        CP16(sbuf + sw,          (const char*)Ah + eA);
        CP16(sbuf + 16384 + sw,  (const char*)Al + eA);
        CP16(sbuf + 32768 + sw,  (const char*)Bh + eB);
        CP16(sbuf + 49152 + sw,  (const char*)Bl + eB);
    }
}

template <int EPI>
__global__ __launch_bounds__(256, 1)
void gemm_tc(const __nv_bfloat16* __restrict__ Ah,
             const __nv_bfloat16* __restrict__ Al,
             const __nv_bfloat16* __restrict__ Bh,
             const __nv_bfloat16* __restrict__ Bl,
             const float* __restrict__ bias,
             const float* __restrict__ res,
             float* __restrict__ outF,
             __nv_bfloat16* __restrict__ outHi,
             __nv_bfloat16* __restrict__ outLo,
             int M, int Nn, int K) {
    extern __shared__ char dsm[];
    const uint32_t buf0 = smem_u32(dsm);
    const uint32_t buf1 = buf0 + 65536;

    const int tid  = threadIdx.x;
    const int wid  = tid >> 5;
    const int lane = tid & 31;

    const int m0 = blockIdx.y * 128;
    const int n0 = blockIdx.x * 128;
    const int NK = K >> 6;

    const int warp_m = (wid & 1) * 64;
    const int warp_n = (wid >> 1) * 32;

    const int lrow = lane & 7;
    const int sel  = lane >> 3;
    const int rofs = lrow + ((sel & 1) ? 8 : 0);
    const int kofs = (sel & 2) ? 8 : 0;

    float d[4][4][4] = {};

    load_chunk(Ah, Al, Bh, Bl, K, m0, n0, 0, buf0, tid);
    CP_COMMIT();

    for (int kc = 0; kc < NK; kc++) {
        const uint32_t bufc = (kc & 1) ? buf1 : buf0;
        if (kc + 1 < NK) {
            load_chunk(Ah, Al, Bh, Bl, K, m0, n0, kc + 1,
                       (kc & 1) ? buf0 : buf1, tid);
            CP_COMMIT();
            CP_WAIT1();
        } else {
            CP_WAIT0();
        }
        __syncthreads();

        const uint32_t aH = bufc;
        const uint32_t aL = bufc + 16384;
        const uint32_t bH = bufc + 32768;
        const uint32_t bL = bufc + 49152;

        #pragma unroll
        for (int ks = 0; ks < 4; ks++) {
            const int kk = ks * 16 + kofs;
            uint32_t ah[4][4], al[4][4], bh[2][4], bl[2][4];
            #pragma unroll
            for (int mi = 0; mi < 4; mi++) {
                uint32_t off = sw128((uint32_t)((warp_m + 16 * mi + rofs) * 128 + kk * 2));
                ldsm4(ah[mi], aH + off);
                ldsm4(al[mi], aL + off);
            }
            #pragma unroll
            for (int nj = 0; nj < 2; nj++) {
                uint32_t off = sw128((uint32_t)((warp_n + 16 * nj + rofs) * 128 + kk * 2));
                ldsm4(bh[nj], bH + off);
                ldsm4(bl[nj], bL + off);
            }
            #pragma unroll
            for (int mi = 0; mi < 4; mi++) {
                #pragma unroll
                for (int nt = 0; nt < 4; nt++) {
                    const int nj = nt >> 1;
                    const int p  = nt & 1;
                    mma16816(d[mi][nt], ah[mi], bh[nj][p], bh[nj][p + 2]);
                    mma16816(d[mi][nt], ah[mi], bl[nj][p], bl[nj][p + 2]);
                    mma16816(d[mi][nt], al[mi], bh[nj][p], bh[nj][p + 2]);
                }
            }
        }
        __syncthreads();
    }

    const int erow0 = m0 + warp_m + (lane >> 2);
    const int ecol0 = n0 + warp_n + (lane & 3) * 2;

    #pragma unroll
    for (int mi = 0; mi < 4; mi++) {
        #pragma unroll
        for (int nt = 0; nt < 4; nt++) {
            const int col = ecol0 + nt * 8;
            #pragma unroll
            for (int half = 0; half < 2; half++) {
                const int row = erow0 + mi * 16 + half * 8;
                float v0 = d[mi][nt][2 * half + 0];
                float v1 = d[mi][nt][2 * half + 1];
                const size_t ob = (size_t)row * Nn + col;
                if (EPI == 0) {
                    *(float2*)(outF + ob) = make_float2(v0, v1);
                } else if (EPI == 1) {
                    float2 rv = *(const float2*)(res + ob);
                    v0 += bias[col]     + rv.x;
                    v1 += bias[col + 1] + rv.y;
                    *(float2*)(outF + ob) = make_float2(v0, v1);
                } else if (EPI == 2) {
                    v0 += bias[col];
                    v1 += bias[col + 1];
                    float g0 = v0 * normcdff(v0);
                    float g1 = v1 * normcdff(v1);
                    __nv_bfloat16 h0 = __float2bfloat16(g0);
                    __nv_bfloat16 h1 = __float2bfloat16(g1);
                    __nv_bfloat162 ph; ph.x = h0; ph.y = h1;
                    __nv_bfloat162 pl;
                    pl.x = __float2bfloat16(g0 - __bfloat162float(h0));
                    pl.y = __float2bfloat16(g1 - __bfloat162float(h1));
                    *(__nv_bfloat162*)(outHi + ob) = ph;
                    *(__nv_bfloat162*)(outLo + ob) = pl;
                } else {
                    __nv_bfloat16 h0 = __float2bfloat16(v0);
                    __nv_bfloat16 h1 = __float2bfloat16(v1);
                    __nv_bfloat162 ph; ph.x = h0; ph.y = h1;
                    __nv_bfloat162 pl;
                    pl.x = __float2bfloat16(v0 - __bfloat162float(h0));
                    pl.y = __float2bfloat16(v1 - __bfloat162float(h1));
                    *(__nv_bfloat162*)(outHi + ob) = ph;
                    *(__nv_bfloat162*)(outLo + ob) = pl;
                }
            }
        }
    }
}

// ---------------------------------------------------------------------------
// Tensor-core flash attention, split bf16 (3-pass QK^T and PV).
// grid = (NN/128, BB*HH); block 256 (8 warps x 16 q-rows).
// SMEM: Qh/Ql [128x64] + 2 stages of (Kh,Kl,Vh,Vl)[64x64] + 2 bias stages.
// ---------------------------------------------------------------------------
#define AT_QH     0
#define AT_QL     16384
#define AT_STAGE  32768          // + s*32768 : Kh, Kl, Vh, Vl (8K each)
#define AT_BIAS   98304          // + s*1024 : 192 floats
#define AT_SMEM_BYTES (98304 + 2048)

__device__ __forceinline__ void attn_prefetch(
    const __nv_bfloat16* __restrict__ qh, const __nv_bfloat16* __restrict__ ql,
    const float* __restrict__ rpb,
    int b, int h, int q0, int k0, uint32_t sbase, uint32_t stage, int tid) {
    // K/V hi/lo: 4 arrays x 64 rows x 8 x 16B
    #pragma unroll
    for (int j = 0; j < 8; j++) {
        int linear = tid + j * 256;
        int arr = linear >> 9;            // 0:Kh 1:Kl 2:Vh 3:Vl
        int within = linear & 511;
        int row = within >> 3;
        int c = within & 7;
        uint32_t dst = stage + arr * 8192 + sw128((uint32_t)(row * 128 + c * 16));
        const __nv_bfloat16* src = (arr & 1) ? ql : qh;
        int colbase = (arr >> 1) ? (2 * CC) : CC;   // V : K
        CP16(dst, (const char*)(src + (size_t)(b * NN + k0 + row) * C3
                                + colbase + h * DH + c * 8));
    }
    // bias diagonal band: 192 values (191 used)
    if (tid < 192) {
        int idx = k0 - q0 + 1920 + tid;   // in [0, 4094+...] always valid for tid<191
        if (tid >= 191) idx = k0 - q0 + 1920;  // harmless duplicate for tid 191
        CP4(sbase + AT_BIAS + (stage == sbase + AT_STAGE ? 0 : 1024) + tid * 4,
            rpb + (size_t)idx * HH + h);
    }
}

__global__ __launch_bounds__(256, 1)
void attn_tc(const __nv_bfloat16* __restrict__ qh,
             const __nv_bfloat16* __restrict__ ql,
             const float* __restrict__ rpb,
             __nv_bfloat16* __restrict__ outHi,
             __nv_bfloat16* __restrict__ outLo) {
    extern __shared__ char dsm[];
    const uint32_t sbase = smem_u32(dsm);

    const int q0 = blockIdx.x * 128;
    const int bh = blockIdx.y;
    const int b = bh >> 3;
    const int h = bh & 7;

    const int tid  = threadIdx.x;
    const int wid  = tid >> 5;
    const int lane = tid & 31;

    const int lrow = lane & 7;
    const int sel  = lane >> 3;
    const int rofs = lrow + ((sel & 1) ? 8 : 0);
    const int kofs = (sel & 2) ? 8 : 0;

    // --- load Q tile (hi/lo) ---
    #pragma unroll
    for (int j = 0; j < 8; j++) {
        int linear = tid + j * 256;
        int arr = linear >> 10;           // 0:Qh 1:Ql
        int within = linear & 1023;
        int row = within >> 3;
        int c = within & 7;
        uint32_t dst = sbase + (arr ? AT_QL : AT_QH)
                     + sw128((uint32_t)(row * 128 + c * 16));
        const __nv_bfloat16* src = arr ? ql : qh;
        CP16(dst, (const char*)(src + (size_t)(b * NN + q0 + row) * C3
                                + h * DH + c * 8));
    }
    attn_prefetch(qh, ql, rpb, b, h, q0, 0, sbase, sbase + AT_STAGE, tid);
    CP_COMMIT();

    uint32_t qfh[4][4], qfl[4][4];
    float oacc[8][4] = {};
    float m0 = -CUDART_INF_F, m1 = -CUDART_INF_F;
    float l0 = 0.f, l1 = 0.f;

    const int NCHUNK = NN / 64;
    for (int c = 0; c < NCHUNK; c++) {
        const int s = c & 1;
        const uint32_t stage = sbase + AT_STAGE + s * 32768;
        const uint32_t bstage = sbase + AT_BIAS + s * 1024;
        if (c + 1 < NCHUNK) {
            attn_prefetch(qh, ql, rpb, b, h, q0, (c + 1) * 64, sbase,
                          sbase + AT_STAGE + (s ^ 1) * 32768, tid);
            CP_COMMIT();
            CP_WAIT1();
        } else {
            CP_WAIT0();
        }
        __syncthreads();

        if (c == 0) {
            // build Q fragments once
            #pragma unroll
            for (int kc = 0; kc < 4; kc++) {
                uint32_t off = sw128((uint32_t)((wid * 16 + rofs) * 128
                                                + (kc * 16 + kofs) * 2));
                ldsm4(qfh[kc], sbase + AT_QH + off);
                ldsm4(qfl[kc], sbase + AT_QL + off);
            }
        }

        // ---- S = Q K^T (3-pass) ----
        float sacc[8][4] = {};
        #pragma unroll
        for (int kc = 0; kc < 4; kc++) {
            #pragma unroll
            for (int npair = 0; npair < 4; npair++) {
                uint32_t off = sw128((uint32_t)((npair * 16 + rofs) * 128
                                                + (kc * 16 + kofs) * 2));
                uint32_t kh[4], kl[4];
                ldsm4(kh, stage + off);           // Kh
                ldsm4(kl, stage + 8192 + off);    // Kl
                #pragma unroll
                for (int p = 0; p < 2; p++) {
                    const int nt = npair * 2 + p;
                    mma16816(sacc[nt], qfh[kc], kh[p], kh[p + 2]);
                    mma16816(sacc[nt], qfh[kc], kl[p], kl[p + 2]);
                    mma16816(sacc[nt], qfl[kc], kh[p], kh[p + 2]);
                }
            }
        }

        // ---- bias + online softmax ----
        const int r0 = wid * 16 + (lane >> 2);     // q row within tile (half 0)
        const int cb = (lane & 3) * 2;
        float mx0 = -CUDART_INF_F, mx1 = -CUDART_INF_F;
        #pragma unroll
        for (int nt = 0; nt < 8; nt++) {
            const int kk = nt * 8 + cb;
            float b00 = *(float*)(uintptr_t)0;  // placeholder avoided below
            (void)b00;
            float bv0, bv1, bv2, bv3;
            asm volatile("ld.shared.f32 %0, [%1];" : "=f"(bv0)
                         : "r"(bstage + (kk - r0 + 127) * 4));
            asm volatile("ld.shared.f32 %0, [%1];" : "=f"(bv1)
                         : "r"(bstage + (kk + 1 - r0 + 127) * 4));
            asm volatile("ld.shared.f32 %0, [%1];" : "=f"(bv2)
                         : "r"(bstage + (kk - (r0 + 8) + 127) * 4));
            asm volatile("ld.shared.f32 %0, [%1];" : "=f"(bv3)
                         : "r"(bstage + (kk + 1 - (r0 + 8) + 127) * 4));
            sacc[nt][0] = fmaf(sacc[nt][0], 0.125f, bv0);
            sacc[nt][1] = fmaf(sacc[nt][1], 0.125f, bv1);
            sacc[nt][2] = fmaf(sacc[nt][2], 0.125f, bv2);
            sacc[nt][3] = fmaf(sacc[nt][3], 0.125f, bv3);
            mx0 = fmaxf(mx0, fmaxf(sacc[nt][0], sacc[nt][1]));
            mx1 = fmaxf(mx1, fmaxf(sacc[nt][2], sacc[nt][3]));
        }
        mx0 = fmaxf(mx0, __shfl_xor_sync(0xffffffffu, mx0, 1));
        mx0 = fmaxf(mx0, __shfl_xor_sync(0xffffffffu, mx0, 2));
        mx1 = fmaxf(mx1, __shfl_xor_sync(0xffffffffu, mx1, 1));
        mx1 = fmaxf(mx1, __shfl_xor_sync(0xffffffffu, mx1, 2));
        const float mn0 = fmaxf(m0, mx0);
        const float mn1 = fmaxf(m1, mx1);
        const float fac0 = __expf(m0 - mn0);
        const float fac1 = __expf(m1 - mn1);
        float sum0 = 0.f, sum1 = 0.f;
        #pragma unroll
        for (int nt = 0; nt < 8; nt++) {
            sacc[nt][0] = __expf(sacc[nt][0] - mn0);
            sacc[nt][1] = __expf(sacc[nt][1] - mn0);
            sacc[nt][2] = __expf(sacc[nt][2] - mn1);
            sacc[nt][3] = __expf(sacc[nt][3] - mn1);
            sum0 += sacc[nt][0] + sacc[nt][1];
            sum1 += sacc[nt][2] + sacc[nt][3];
        }
        sum0 += __shfl_xor_sync(0xffffffffu, sum0, 1);
        sum0 += __shfl_xor_sync(0xffffffffu, sum0, 2);
        sum1 += __shfl_xor_sync(0xffffffffu, sum1, 1);
        sum1 += __shfl_xor_sync(0xffffffffu, sum1, 2);
        l0 = l0 * fac0 + sum0;
        l1 = l1 * fac1 + sum1;
        m0 = mn0;
        m1 = mn1;
        #pragma unroll
        for (int nt = 0; nt < 8; nt++) {
            oacc[nt][0] *= fac0;
            oacc[nt][1] *= fac0;
            oacc[nt][2] *= fac1;
            oacc[nt][3] *= fac1;
        }

        // ---- O += P V (3-pass), P fragments built in registers ----
        #pragma unroll
        for (int kc = 0; kc < 4; kc++) {
            uint32_t pah[4], pal[4];
            #pragma unroll
            for (int g = 0; g < 2; g++) {        // g: n-tile 2kc+g -> a regs 2g,2g+1
                const float* sv = sacc[2 * kc + g];
                float h0f = __bfloat162float(__float2bfloat16(sv[0]));
                float h1f = __bfloat162float(__float2bfloat16(sv[1]));
                float h2f = __bfloat162float(__float2bfloat16(sv[2]));
                float h3f = __bfloat162float(__float2bfloat16(sv[3]));
                pah[2 * g + 0] = pack_bf16(sv[0], sv[1]);
                pah[2 * g + 1] = pack_bf16(sv[2], sv[3]);
                pal[2 * g + 0] = pack_bf16(sv[0] - h0f, sv[1] - h1f);
                pal[2 * g + 1] = pack_bf16(sv[2] - h2f, sv[3] - h3f);
            }
            // NOTE: a-frag order must be {r0 k0-7, r1 k0-7, r0 k8-15, r1 k8-15}
            uint32_t pAh[4] = {pah[0], pah[1], pah[2], pah[3]};
            uint32_t pAl[4] = {pal[0], pal[1], pal[2], pal[3]};
            #pragma unroll
            for (int dp = 0; dp < 4; dp++) {
                // trans-ldmatrix: rows = k within chunk, cols = head dim
                const int g = lane >> 3;
                const int rr = lane & 7;
                uint32_t off = sw128((uint32_t)((kc * 16 + (g & 1) * 8 + rr) * 128
                                                + dp * 32 + (g >> 1) * 16));
                uint32_t vh[4], vl[4];
                ldsm4t(vh, stage + 16384 + off);   // Vh
                ldsm4t(vl, stage + 24576 + off);   // Vl
                #pragma unroll
                for (int p = 0; p < 2; p++) {
                    const int dt = dp * 2 + p;
                    mma16816(oacc[dt], pAh, vh[2 * p], vh[2 * p + 1]);
                    mma16816(oacc[dt], pAh, vl[2 * p], vl[2 * p + 1]);
                    mma16816(oacc[dt], pAl, vh[2 * p], vh[2 * p + 1]);
                }
            }
        }
        __syncthreads();
    }

    // ---- epilogue: normalize, split hi/lo, store ----
    const float il0 = 1.0f / l0;
    const float il1 = 1.0f / l1;
    const int row0 = b * NN + q0 + wid * 16 + (lane >> 2);
    const int colb = h * DH + (lane & 3) * 2;
    #pragma unroll
    for (int nt = 0; nt < 8; nt++) {
        const int col = colb + nt * 8;
        float v0 = oacc[nt][0] * il0;
        float v1 = oacc[nt][1] * il0;
        float v2 = oacc[nt][2] * il1;
        float v3 = oacc[nt][3] * il1;
        __nv_bfloat16 h0 = __float2bfloat16(v0);
        __nv_bfloat16 h1 = __float2bfloat16(v1);
        __nv_bfloat16 h2 = __float2bfloat16(v2);
        __nv_bfloat16 h3 = __float2bfloat16(v3);
        __nv_bfloat162 p01; p01.x = h0; p01.y = h1;
        __nv_bfloat162 p23; p23.x = h2; p23.y = h3;
        __nv_bfloat162 q01;
        q01.x = __float2bfloat16(v0 - __bfloat162float(h0));
        q01.y = __float2bfloat16(v1 - __bfloat162float(h1));
        __nv_bfloat162 q23;
        q23.x = __float2bfloat16(v2 - __bfloat162float(h2));
        q23.y = __float2bfloat16(v3 - __bfloat162float(h3));
        *(__nv_bfloat162*)(outHi + (size_t)row0 * CC + col)       = p01;
        *(__nv_bfloat162*)(outHi + (size_t)(row0 + 8) * CC + col) = p23;
        *(__nv_bfloat162*)(outLo + (size_t)row0 * CC + col)       = q01;
        *(__nv_bfloat162*)(outLo + (size_t)(row0 + 8) * CC + col) = q23;
    }
}

// ---------------------------------------------------------------------------
// Launcher
// ---------------------------------------------------------------------------
extern "C" void kernel_launch(void* const* d_in, const int* in_sizes, int n_in,
                              void* d_out, int out_size) {
    const float* x      = (const float*)d_in[0];
    const float* qkv_w  = (const float*)d_in[1];
    const float* proj_w = (const float*)d_in[2];
    const float* proj_b = (const float*)d_in[3];
    const float* rpb    = (const float*)d_in[4];
    const float* n1_w   = (const float*)d_in[5];
    const float* n1_b   = (const float*)d_in[6];
    const float* n2_w   = (const float*)d_in[7];
    const float* n2_b   = (const float*)d_in[8];
    const float* fc1_w  = (const float*)d_in[9];
    const float* fc1_b  = (const float*)d_in[10];
    const float* fc2_w  = (const float*)d_in[11];
    const float* fc2_b  = (const float*)d_in[12];
    float* out = (float*)d_out;

    float *x1;
    __nv_bfloat16 *qvh, *qvl, *h1h, *h1l, *ath, *atl, *h2h, *h2l, *hdh, *hdl;
    __nv_bfloat16 *wqh, *wql, *wph, *wpl, *w1h, *w1l, *w2h, *w2l;
    cudaGetSymbolAddress((void**)&x1,  g_x1);
    cudaGetSymbolAddress((void**)&qvh, g_qvh); cudaGetSymbolAddress((void**)&qvl, g_qvl);
    cudaGetSymbolAddress((void**)&h1h, g_h1h); cudaGetSymbolAddress((void**)&h1l, g_h1l);
    cudaGetSymbolAddress((void**)&ath, g_ath); cudaGetSymbolAddress((void**)&atl, g_atl);
    cudaGetSymbolAddress((void**)&h2h, g_h2h); cudaGetSymbolAddress((void**)&h2l, g_h2l);
    cudaGetSymbolAddress((void**)&hdh, g_hdh); cudaGetSymbolAddress((void**)&hdl, g_hdl);
    cudaGetSymbolAddress((void**)&wqh, g_wqh); cudaGetSymbolAddress((void**)&wql, g_wql);
    cudaGetSymbolAddress((void**)&wph, g_wph); cudaGetSymbolAddress((void**)&wpl, g_wpl);
    cudaGetSymbolAddress((void**)&w1h, g_w1h); cudaGetSymbolAddress((void**)&w1l, g_w1l);
    cudaGetSymbolAddress((void**)&w2h, g_w2h); cudaGetSymbolAddress((void**)&w2l, g_w2l);

    cudaFuncSetAttribute(gemm_tc<1>, cudaFuncAttributeMaxDynamicSharedMemorySize, GEMM_SMEM_BYTES);
    cudaFuncSetAttribute(gemm_tc<2>, cudaFuncAttributeMaxDynamicSharedMemorySize, GEMM_SMEM_BYTES);
    cudaFuncSetAttribute(gemm_tc<3>, cudaFuncAttributeMaxDynamicSharedMemorySize, GEMM_SMEM_BYTES);
    cudaFuncSetAttribute(attn_tc, cudaFuncAttributeMaxDynamicSharedMemorySize, AT_SMEM_BYTES);

    // Weight conversions (fp32 -> bf16 hi/lo)
    cvt_kernel<<<(C3 * CC) / 1024, 256>>>(qkv_w, wqh, wql, (C3 * CC) / 4);
    cvt_kernel<<<(CC * CC) / 1024, 256>>>(proj_w, wph, wpl, (CC * CC) / 4);
    cvt_kernel<<<(HID * CC) / 1024, 256>>>(fc1_w, w1h, w1l, (HID * CC) / 4);
    cvt_kernel<<<(CC * HID) / 1024, 256>>>(fc2_w, w2h, w2l, (CC * HID) / 4);

    // 1) ln1 -> h1 (hi/lo)
    ln_kernel<<<MROWS, 256>>>(x, n1_w, n1_b, h1h, h1l);
    // 2) qkv = h1 @ qkv_w^T  (bf16 hi/lo out)
    gemm_tc<3><<<dim3(C3 / 128, MROWS / 128), 256, GEMM_SMEM_BYTES>>>(
        h1h, h1l, wqh, wql, nullptr, nullptr, nullptr, qvh, qvl,
        MROWS, C3, CC);
    // 3) attention -> attn (hi/lo)
    attn_tc<<<dim3(NN / 128, BB * HH), 256, AT_SMEM_BYTES>>>(qvh, qvl, rpb, ath, atl);
    // 4) x1 = x + attn @ proj_w^T + proj_b
    gemm_tc<1><<<dim3(CC / 128, MROWS / 128), 256, GEMM_SMEM_BYTES>>>(
        ath, atl, wph, wpl, proj_b, x, x1, nullptr, nullptr,
        MROWS, CC, CC);
    // 5) ln2 -> h2 (hi/lo)
    ln_kernel<<<MROWS, 256>>>(x1, n2_w, n2_b, h2h, h2l);
    // 6) hid = gelu(h2 @ fc1_w^T + fc1_b)  (hi/lo out)
    gemm_tc<2><<<dim3(HID / 128, MROWS / 128), 256, GEMM_SMEM_BYTES>>>(
        h2h, h2l, w1h, w1l, fc1_b, nullptr, nullptr, hdh, hdl,
        MROWS, HID, CC);
    // 7) out = x1 + hid @ fc2_w^T + fc2_b
    gemm_tc<1><<<dim3(CC / 128, MROWS / 128), 256, GEMM_SMEM_BYTES>>>(
        hdh, hdl, w2h, w2l, fc2_b, x1, out, nullptr, nullptr,
        MROWS, CC, HID);
}

// round 5
// speedup vs baseline: 4.3519x; 1.5738x over previous
#include <cuda_runtime.h>
#include <cuda_fp16.h>
#include <math.h>
#include <math_constants.h>
#include <stdint.h>

// Problem constants
#define BB    4
#define NN    2048
#define CC    512
#define HH    8
#define DH    64
#define HID   2048
#define MROWS (BB * NN)   // 8192
#define C3    (3 * CC)    // 1536

// ---------------------------------------------------------------------------
// Device scratch
// ---------------------------------------------------------------------------
__device__ float g_x1 [MROWS * CC];     // fp32 residual after attention

__device__ __half g_qvh[MROWS * C3],  g_qvl[MROWS * C3];
__device__ __half g_h1h[MROWS * CC],  g_h1l[MROWS * CC];
__device__ __half g_ath[MROWS * CC],  g_atl[MROWS * CC];
__device__ __half g_h2h[MROWS * CC],  g_h2l[MROWS * CC];
__device__ __half g_hdh[MROWS * HID], g_hdl[MROWS * HID];

__device__ __half g_wq[C3 * CC];
__device__ __half g_wp[CC * CC];
__device__ __half g_w1[HID * CC];
__device__ __half g_w2[CC * HID];

// ---------------------------------------------------------------------------
// PTX helpers
// ---------------------------------------------------------------------------
__device__ __forceinline__ uint32_t smem_u32(const void* p) {
    uint32_t a;
    asm("{ .reg .u64 t; cvta.to.shared.u64 t, %1; cvt.u32.u64 %0, t; }"
        : "=r"(a) : "l"(p));
    return a;
}

#define CP16(dst, src)                                                        \
    asm volatile("cp.async.cg.shared.global [%0], [%1], 16;"                  \
                 :: "r"(dst), "l"(src))
#define CP4(dst, src)                                                         \
    asm volatile("cp.async.ca.shared.global [%0], [%1], 4;"                   \
                 :: "r"(dst), "l"(src))
#define CP_COMMIT() asm volatile("cp.async.commit_group;" ::: "memory")
#define CP_WAIT1()  asm volatile("cp.async.wait_group 1;" ::: "memory")
#define CP_WAIT0()  asm volatile("cp.async.wait_group 0;" ::: "memory")

__device__ __forceinline__ void ldsm4(uint32_t* r, uint32_t addr) {
    asm volatile("ldmatrix.sync.aligned.m8n8.x4.shared.b16 {%0,%1,%2,%3}, [%4];"
                 : "=r"(r[0]), "=r"(r[1]), "=r"(r[2]), "=r"(r[3]) : "r"(addr));
}

__device__ __forceinline__ void ldsm4t(uint32_t* r, uint32_t addr) {
    asm volatile("ldmatrix.sync.aligned.m8n8.x4.trans.shared.b16 {%0,%1,%2,%3}, [%4];"
                 : "=r"(r[0]), "=r"(r[1]), "=r"(r[2]), "=r"(r[3]) : "r"(addr));
}

__device__ __forceinline__ void mma16816(float* d, const uint32_t* a,
                                         uint32_t b0, uint32_t b1) {
    asm volatile(
        "mma.sync.aligned.m16n8k16.row.col.f32.f16.f16.f32 "
        "{%0,%1,%2,%3}, {%4,%5,%6,%7}, {%8,%9}, {%0,%1,%2,%3};"
        : "+f"(d[0]), "+f"(d[1]), "+f"(d[2]), "+f"(d[3])
        : "r"(a[0]), "r"(a[1]), "r"(a[2]), "r"(a[3]), "r"(b0), "r"(b1));
}

__device__ __forceinline__ uint32_t sw128(uint32_t off) {
    return off ^ ((off >> 3) & 0x70u);
}

__device__ __forceinline__ uint32_t pack_h2(float a, float b) {
    __half2 p = __floats2half2_rn(a, b);
    return *(uint32_t*)&p;
}

// ---------------------------------------------------------------------------
// Weight conversion: fp32 -> fp16 (hi only)
// ---------------------------------------------------------------------------
__global__ void cvt_w(const float* __restrict__ x, __half* __restrict__ hi,
                      int n4) {
    int i = blockIdx.x * blockDim.x + threadIdx.x;
    if (i >= n4) return;
    float4 v = *(const float4*)(x + 4 * (size_t)i);
    __half2 p0 = __floats2half2_rn(v.x, v.y);
    __half2 p1 = __floats2half2_rn(v.z, v.w);
    *(__half2*)(hi + 4 * (size_t)i)     = p0;
    *(__half2*)(hi + 4 * (size_t)i + 2) = p1;
}

// ---------------------------------------------------------------------------
// LayerNorm -> fp16 hi/lo
// ---------------------------------------------------------------------------
__global__ void ln_kernel(const float* __restrict__ x,
                          const float* __restrict__ w,
                          const float* __restrict__ b,
                          __half* __restrict__ ohi,
                          __half* __restrict__ olo) {
    const int row = blockIdx.x;
    const float* xr = x + (size_t)row * CC;
    const int t = threadIdx.x;

    float v0 = xr[t];
    float v1 = xr[t + 256];

    __shared__ float red1[8];
    __shared__ float red2[8];

    float s = v0 + v1;
    #pragma unroll
    for (int o = 16; o > 0; o >>= 1) s += __shfl_xor_sync(0xffffffffu, s, o);
    if ((t & 31) == 0) red1[t >> 5] = s;
    __syncthreads();
    float tot = 0.f;
    #pragma unroll
    for (int i = 0; i < 8; i++) tot += red1[i];
    const float mean = tot * (1.0f / CC);

    float d0 = v0 - mean, d1 = v1 - mean;
    float s2 = d0 * d0 + d1 * d1;
    #pragma unroll
    for (int o = 16; o > 0; o >>= 1) s2 += __shfl_xor_sync(0xffffffffu, s2, o);
    if ((t & 31) == 0) red2[t >> 5] = s2;
    __syncthreads();
    float tot2 = 0.f;
    #pragma unroll
    for (int i = 0; i < 8; i++) tot2 += red2[i];
    const float inv = rsqrtf(tot2 * (1.0f / CC) + 1e-5f);

    float y0 = d0 * inv * w[t]       + b[t];
    float y1 = d1 * inv * w[t + 256] + b[t + 256];

    __half h0 = __float2half_rn(y0);
    __half h1 = __float2half_rn(y1);
    ohi[(size_t)row * CC + t]       = h0;
    ohi[(size_t)row * CC + t + 256] = h1;
    olo[(size_t)row * CC + t]       = __float2half_rn(y0 - __half2float(h0));
    olo[(size_t)row * CC + t + 256] = __float2half_rn(y1 - __half2float(h1));
}

// ---------------------------------------------------------------------------
// mma.sync 2-pass fp16 NT GEMM:  C[M,Nn] = (Ah+Al)[M,K] * Wh[Nn,K]^T
// CTA tile 128x128, BK=64, 8 warps (warp tile 64x32), double-buffered cp.async.
//   EPI 1: fp32 out = acc + bias[n] + res[m,n]
//   EPI 2: fp16 hi/lo out = gelu(acc + bias[n])
//   EPI 3: fp16 hi/lo out
// SMEM stage: [Ah 16K][Al 16K][Bh 16K], rows of 128B, SW128. 48K/stage.
// ---------------------------------------------------------------------------
#define GEMM_STAGE 49152
#define GEMM_SMEM_BYTES (2 * GEMM_STAGE)

__device__ __forceinline__ void load_chunk(
    const __half* __restrict__ Ah, const __half* __restrict__ Al,
    const __half* __restrict__ Bh,
    int K, int m0, int n0, int kc, uint32_t sbuf, int tid) {
    #pragma unroll
    for (int j = 0; j < 12; j++) {
        const int linear = j * 256 + tid;
        const int arr = j >> 2;          // 0:Ah 1:Al 2:Bh (compile-time)
        const int within = linear & 1023;
        const int r = within >> 3;
        const int c = within & 7;
        uint32_t sw = sw128((uint32_t)(r * 128 + c * 16));
        if (arr == 0) {
            CP16(sbuf + sw,
                 (const char*)(Ah + (size_t)(m0 + r) * K + (size_t)kc * 64 + c * 8));
        } else if (arr == 1) {
            CP16(sbuf + 16384 + sw,
                 (const char*)(Al + (size_t)(m0 + r) * K + (size_t)kc * 64 + c * 8));
        } else {
            CP16(sbuf + 32768 + sw,
                 (const char*)(Bh + (size_t)(n0 + r) * K + (size_t)kc * 64 + c * 8));
        }
    }
}

template <int EPI>
__global__ __launch_bounds__(256, 2)
void gemm_tc(const __half* __restrict__ Ah,
             const __half* __restrict__ Al,
             const __half* __restrict__ Bh,
             const float* __restrict__ bias,
             const float* __restrict__ res,
             float* __restrict__ outF,
             __half* __restrict__ outHi,
             __half* __restrict__ outLo,
             int M, int Nn, int K) {
    extern __shared__ char dsm[];
    const uint32_t buf0 = smem_u32(dsm);
    const uint32_t buf1 = buf0 + GEMM_STAGE;

    const int tid  = threadIdx.x;
    const int wid  = tid >> 5;
    const int lane = tid & 31;

    const int m0 = blockIdx.y * 128;
    const int n0 = blockIdx.x * 128;
    const int NK = K >> 6;

    const int warp_m = (wid & 1) * 64;
    const int warp_n = (wid >> 1) * 32;

    const int lrow = lane & 7;
    const int sel  = lane >> 3;
    const int rofs = lrow + ((sel & 1) ? 8 : 0);
    const int kofs = (sel & 2) ? 8 : 0;

    float d[4][4][4] = {};

    load_chunk(Ah, Al, Bh, K, m0, n0, 0, buf0, tid);
    CP_COMMIT();

    for (int kc = 0; kc < NK; kc++) {
        const uint32_t bufc = (kc & 1) ? buf1 : buf0;
        if (kc + 1 < NK) {
            load_chunk(Ah, Al, Bh, K, m0, n0, kc + 1,
                       (kc & 1) ? buf0 : buf1, tid);
            CP_COMMIT();
            CP_WAIT1();
        } else {
            CP_WAIT0();
        }
        __syncthreads();

        const uint32_t aH = bufc;
        const uint32_t aL = bufc + 16384;
        const uint32_t bH = bufc + 32768;

        #pragma unroll
        for (int ks = 0; ks < 4; ks++) {
            const int kk = ks * 16 + kofs;
            uint32_t ah[4][4], al[4][4], bh[2][4];
            #pragma unroll
            for (int mi = 0; mi < 4; mi++) {
                uint32_t off = sw128((uint32_t)((warp_m + 16 * mi + rofs) * 128 + kk * 2));
                ldsm4(ah[mi], aH + off);
                ldsm4(al[mi], aL + off);
            }
            #pragma unroll
            for (int nj = 0; nj < 2; nj++) {
                uint32_t off = sw128((uint32_t)((warp_n + 16 * nj + rofs) * 128 + kk * 2));
                ldsm4(bh[nj], bH + off);
            }
            #pragma unroll
            for (int mi = 0; mi < 4; mi++) {
                #pragma unroll
                for (int nt = 0; nt < 4; nt++) {
                    const int nj = nt >> 1;
                    const int p  = nt & 1;
                    mma16816(d[mi][nt], ah[mi], bh[nj][p], bh[nj][p + 2]);
                    mma16816(d[mi][nt], al[mi], bh[nj][p], bh[nj][p + 2]);
                }
            }
        }
        __syncthreads();
    }

    const int erow0 = m0 + warp_m + (lane >> 2);
    const int ecol0 = n0 + warp_n + (lane & 3) * 2;

    #pragma unroll
    for (int mi = 0; mi < 4; mi++) {
        #pragma unroll
        for (int nt = 0; nt < 4; nt++) {
            const int col = ecol0 + nt * 8;
            #pragma unroll
            for (int half = 0; half < 2; half++) {
                const int row = erow0 + mi * 16 + half * 8;
                float v0 = d[mi][nt][2 * half + 0];
                float v1 = d[mi][nt][2 * half + 1];
                const size_t ob = (size_t)row * Nn + col;
                if (EPI == 1) {
                    float2 rv = *(const float2*)(res + ob);
                    v0 += bias[col]     + rv.x;
                    v1 += bias[col + 1] + rv.y;
                    *(float2*)(outF + ob) = make_float2(v0, v1);
                } else if (EPI == 2) {
                    v0 += bias[col];
                    v1 += bias[col + 1];
                    float g0 = v0 * normcdff(v0);
                    float g1 = v1 * normcdff(v1);
                    __half h0 = __float2half_rn(g0);
                    __half h1 = __float2half_rn(g1);
                    __half2 ph; ph.x = h0; ph.y = h1;
                    __half2 pl;
                    pl.x = __float2half_rn(g0 - __half2float(h0));
                    pl.y = __float2half_rn(g1 - __half2float(h1));
                    *(__half2*)(outHi + ob) = ph;
                    *(__half2*)(outLo + ob) = pl;
                } else {
                    __half h0 = __float2half_rn(v0);
                    __half h1 = __float2half_rn(v1);
                    __half2 ph; ph.x = h0; ph.y = h1;
                    __half2 pl;
                    pl.x = __float2half_rn(v0 - __half2float(h0));
                    pl.y = __float2half_rn(v1 - __half2float(h1));
                    *(__half2*)(outHi + ob) = ph;
                    *(__half2*)(outLo + ob) = pl;
                }
            }
        }
    }
}

// ---------------------------------------------------------------------------
// Tensor-core flash attention, 2-pass fp16.
// grid = (NN/128, BB*HH); block 256 (8 warps x 16 q-rows).
// SMEM: Qh/Ql [128x64] (32K) + 2 stages of (Kh,Vh)[64x64] (16K each) + bias.
// ---------------------------------------------------------------------------
#define AT_QH     0
#define AT_QL     16384
#define AT_STAGE  32768          // + s*16384 : Kh (8K), Vh (8K)
#define AT_BIAS   65536          // + s*1024 : 192 floats
#define AT_SMEM_BYTES (65536 + 2048)

__device__ __forceinline__ void attn_prefetch(
    const __half* __restrict__ qv, const float* __restrict__ rpb,
    int b, int h, int q0, int k0, uint32_t sbase, int s, int tid) {
    const uint32_t stage = sbase + AT_STAGE + s * 16384;
    #pragma unroll
    for (int j = 0; j < 4; j++) {
        int linear = tid + j * 256;
        int arr = linear >> 9;            // 0:Kh 1:Vh
        int within = linear & 511;
        int row = within >> 3;
        int c = within & 7;
        uint32_t dst = stage + arr * 8192 + sw128((uint32_t)(row * 128 + c * 16));
        int colbase = arr ? (2 * CC) : CC;
        CP16(dst, (const char*)(qv + (size_t)(b * NN + k0 + row) * C3
                                + colbase + h * DH + c * 8));
    }
    if (tid < 192) {
        int idx = k0 - q0 + 1920 + tid;
        if (tid >= 191) idx = k0 - q0 + 1920;
        CP4(sbase + AT_BIAS + s * 1024 + tid * 4, rpb + (size_t)idx * HH + h);
    }
}

__global__ __launch_bounds__(256, 1)
void attn_tc(const __half* __restrict__ qh,
             const __half* __restrict__ ql,
             const float* __restrict__ rpb,
             __half* __restrict__ outHi,
             __half* __restrict__ outLo) {
    extern __shared__ char dsm[];
    const uint32_t sbase = smem_u32(dsm);

    const int q0 = blockIdx.x * 128;
    const int bh = blockIdx.y;
    const int b = bh >> 3;
    const int h = bh & 7;

    const int tid  = threadIdx.x;
    const int wid  = tid >> 5;
    const int lane = tid & 31;

    const int lrow = lane & 7;
    const int sel  = lane >> 3;
    const int rofs = lrow + ((sel & 1) ? 8 : 0);
    const int kofs = (sel & 2) ? 8 : 0;

    // --- load Q tile (hi/lo) ---
    #pragma unroll
    for (int j = 0; j < 8; j++) {
        int linear = tid + j * 256;
        int arr = linear >> 10;           // 0:Qh 1:Ql
        int within = linear & 1023;
        int row = within >> 3;
        int c = within & 7;
        uint32_t dst = sbase + (arr ? AT_QL : AT_QH)
                     + sw128((uint32_t)(row * 128 + c * 16));
        const __half* src = arr ? ql : qh;
        CP16(dst, (const char*)(src + (size_t)(b * NN + q0 + row) * C3
                                + h * DH + c * 8));
    }
    attn_prefetch(qh, rpb, b, h, q0, 0, sbase, 0, tid);
    CP_COMMIT();

    uint32_t qfh[4][4], qfl[4][4];
    float oacc[8][4] = {};
    float m0 = -CUDART_INF_F, m1 = -CUDART_INF_F;
    float l0 = 0.f, l1 = 0.f;

    const int NCHUNK = NN / 64;
    for (int c = 0; c < NCHUNK; c++) {
        const int s = c & 1;
        const uint32_t stage = sbase + AT_STAGE + s * 16384;
        const uint32_t bstage = sbase + AT_BIAS + s * 1024;
        if (c + 1 < NCHUNK) {
            attn_prefetch(qh, rpb, b, h, q0, (c + 1) * 64, sbase, s ^ 1, tid);
            CP_COMMIT();
            CP_WAIT1();
        } else {
            CP_WAIT0();
        }
        __syncthreads();

        if (c == 0) {
            #pragma unroll
            for (int kc = 0; kc < 4; kc++) {
                uint32_t off = sw128((uint32_t)((wid * 16 + rofs) * 128
                                                + (kc * 16 + kofs) * 2));
                ldsm4(qfh[kc], sbase + AT_QH + off);
                ldsm4(qfl[kc], sbase + AT_QL + off);
            }
        }

        // ---- S = Q K^T (2-pass) ----
        float sacc[8][4] = {};
        #pragma unroll
        for (int kc = 0; kc < 4; kc++) {
            #pragma unroll
            for (int npair = 0; npair < 4; npair++) {
                uint32_t off = sw128((uint32_t)((npair * 16 + rofs) * 128
                                                + (kc * 16 + kofs) * 2));
                uint32_t kh[4];
                ldsm4(kh, stage + off);
                #pragma unroll
                for (int p = 0; p < 2; p++) {
                    const int nt = npair * 2 + p;
                    mma16816(sacc[nt], qfh[kc], kh[p], kh[p + 2]);
                    mma16816(sacc[nt], qfl[kc], kh[p], kh[p + 2]);
                }
            }
        }

        // ---- bias + online softmax ----
        const int r0 = wid * 16 + (lane >> 2);
        const int cb = (lane & 3) * 2;
        float mx0 = -CUDART_INF_F, mx1 = -CUDART_INF_F;
        #pragma unroll
        for (int nt = 0; nt < 8; nt++) {
            const int kk = nt * 8 + cb;
            float bv0, bv1, bv2, bv3;
            asm volatile("ld.shared.f32 %0, [%1];" : "=f"(bv0)
                         : "r"(bstage + (kk - r0 + 127) * 4));
            asm volatile("ld.shared.f32 %0, [%1];" : "=f"(bv1)
                         : "r"(bstage + (kk + 1 - r0 + 127) * 4));
            asm volatile("ld.shared.f32 %0, [%1];" : "=f"(bv2)
                         : "r"(bstage + (kk - (r0 + 8) + 127) * 4));
            asm volatile("ld.shared.f32 %0, [%1];" : "=f"(bv3)
                         : "r"(bstage + (kk + 1 - (r0 + 8) + 127) * 4));
            sacc[nt][0] = fmaf(sacc[nt][0], 0.125f, bv0);
            sacc[nt][1] = fmaf(sacc[nt][1], 0.125f, bv1);
            sacc[nt][2] = fmaf(sacc[nt][2], 0.125f, bv2);
            sacc[nt][3] = fmaf(sacc[nt][3], 0.125f, bv3);
            mx0 = fmaxf(mx0, fmaxf(sacc[nt][0], sacc[nt][1]));
            mx1 = fmaxf(mx1, fmaxf(sacc[nt][2], sacc[nt][3]));
        }
        mx0 = fmaxf(mx0, __shfl_xor_sync(0xffffffffu, mx0, 1));
        mx0 = fmaxf(mx0, __shfl_xor_sync(0xffffffffu, mx0, 2));
        mx1 = fmaxf(mx1, __shfl_xor_sync(0xffffffffu, mx1, 1));
        mx1 = fmaxf(mx1, __shfl_xor_sync(0xffffffffu, mx1, 2));
        const float mn0 = fmaxf(m0, mx0);
        const float mn1 = fmaxf(m1, mx1);
        const float fac0 = __expf(m0 - mn0);
        const float fac1 = __expf(m1 - mn1);
        float sum0 = 0.f, sum1 = 0.f;
        #pragma unroll
        for (int nt = 0; nt < 8; nt++) {
            sacc[nt][0] = __expf(sacc[nt][0] - mn0);
            sacc[nt][1] = __expf(sacc[nt][1] - mn0);
            sacc[nt][2] = __expf(sacc[nt][2] - mn1);
            sacc[nt][3] = __expf(sacc[nt][3] - mn1);
            sum0 += sacc[nt][0] + sacc[nt][1];
            sum1 += sacc[nt][2] + sacc[nt][3];
        }
        sum0 += __shfl_xor_sync(0xffffffffu, sum0, 1);
        sum0 += __shfl_xor_sync(0xffffffffu, sum0, 2);
        sum1 += __shfl_xor_sync(0xffffffffu, sum1, 1);
        sum1 += __shfl_xor_sync(0xffffffffu, sum1, 2);
        l0 = l0 * fac0 + sum0;
        l1 = l1 * fac1 + sum1;
        m0 = mn0;
        m1 = mn1;
        #pragma unroll
        for (int nt = 0; nt < 8; nt++) {
            oacc[nt][0] *= fac0;
            oacc[nt][1] *= fac0;
            oacc[nt][2] *= fac1;
            oacc[nt][3] *= fac1;
        }

        // ---- O += P V (2-pass), P hi/lo built in registers ----
        #pragma unroll
        for (int kc = 0; kc < 4; kc++) {
            uint32_t pAh[4], pAl[4];
            #pragma unroll
            for (int g = 0; g < 2; g++) {
                const float* sv = sacc[2 * kc + g];
                __half e0 = __float2half_rn(sv[0]);
                __half e1 = __float2half_rn(sv[1]);
                __half e2 = __float2half_rn(sv[2]);
                __half e3 = __float2half_rn(sv[3]);
                pAh[2 * g + 0] = pack_h2(sv[0], sv[1]);
                pAh[2 * g + 1] = pack_h2(sv[2], sv[3]);
                pAl[2 * g + 0] = pack_h2(sv[0] - __half2float(e0),
                                         sv[1] - __half2float(e1));
                pAl[2 * g + 1] = pack_h2(sv[2] - __half2float(e2),
                                         sv[3] - __half2float(e3));
            }
            #pragma unroll
            for (int dp = 0; dp < 4; dp++) {
                const int g = lane >> 3;
                const int rr = lane & 7;
                uint32_t off = sw128((uint32_t)((kc * 16 + (g & 1) * 8 + rr) * 128
                                                + dp * 32 + (g >> 1) * 16));
                uint32_t vh[4];
                ldsm4t(vh, stage + 8192 + off);    // Vh
                #pragma unroll
                for (int p = 0; p < 2; p++) {
                    const int dt = dp * 2 + p;
                    mma16816(oacc[dt], pAh, vh[2 * p], vh[2 * p + 1]);
                    mma16816(oacc[dt], pAl, vh[2 * p], vh[2 * p + 1]);
                }
            }
        }
        __syncthreads();
    }

    // ---- epilogue: normalize, split hi/lo, store ----
    const float il0 = 1.0f / l0;
    const float il1 = 1.0f / l1;
    const int row0 = b * NN + q0 + wid * 16 + (lane >> 2);
    const int colb = h * DH + (lane & 3) * 2;
    #pragma unroll
    for (int nt = 0; nt < 8; nt++) {
        const int col = colb + nt * 8;
        float v0 = oacc[nt][0] * il0;
        float v1 = oacc[nt][1] * il0;
        float v2 = oacc[nt][2] * il1;
        float v3 = oacc[nt][3] * il1;
        __half h0 = __float2half_rn(v0);
        __half h1 = __float2half_rn(v1);
        __half h2 = __float2half_rn(v2);
        __half h3 = __float2half_rn(v3);
        __half2 p01; p01.x = h0; p01.y = h1;
        __half2 p23; p23.x = h2; p23.y = h3;
        __half2 q01;
        q01.x = __float2half_rn(v0 - __half2float(h0));
        q01.y = __float2half_rn(v1 - __half2float(h1));
        __half2 q23;
        q23.x = __float2half_rn(v2 - __half2float(h2));
        q23.y = __float2half_rn(v3 - __half2float(h3));
        *(__half2*)(outHi + (size_t)row0 * CC + col)       = p01;
        *(__half2*)(outHi + (size_t)(row0 + 8) * CC + col) = p23;
        *(__half2*)(outLo + (size_t)row0 * CC + col)       = q01;
        *(__half2*)(outLo + (size_t)(row0 + 8) * CC + col) = q23;
    }
}

// ---------------------------------------------------------------------------
// Launcher
// ---------------------------------------------------------------------------
extern "C" void kernel_launch(void* const* d_in, const int* in_sizes, int n_in,
                              void* d_out, int out_size) {
    const float* x      = (const float*)d_in[0];
    const float* qkv_w  = (const float*)d_in[1];
    const float* proj_w = (const float*)d_in[2];
    const float* proj_b = (const float*)d_in[3];
    const float* rpb    = (const float*)d_in[4];
    const float* n1_w   = (const float*)d_in[5];
    const float* n1_b   = (const float*)d_in[6];
    const float* n2_w   = (const float*)d_in[7];
    const float* n2_b   = (const float*)d_in[8];
    const float* fc1_w  = (const float*)d_in[9];
    const float* fc1_b  = (const float*)d_in[10];
    const float* fc2_w  = (const float*)d_in[11];
    const float* fc2_b  = (const float*)d_in[12];
    float* out = (float*)d_out;

    float *x1;
    __half *qvh, *qvl, *h1h, *h1l, *ath, *atl, *h2h, *h2l, *hdh, *hdl;
    __half *wq, *wp, *w1, *w2;
    cudaGetSymbolAddress((void**)&x1,  g_x1);
    cudaGetSymbolAddress((void**)&qvh, g_qvh); cudaGetSymbolAddress((void**)&qvl, g_qvl);
    cudaGetSymbolAddress((void**)&h1h, g_h1h); cudaGetSymbolAddress((void**)&h1l, g_h1l);
    cudaGetSymbolAddress((void**)&ath, g_ath); cudaGetSymbolAddress((void**)&atl, g_atl);
    cudaGetSymbolAddress((void**)&h2h, g_h2h); cudaGetSymbolAddress((void**)&h2l, g_h2l);
    cudaGetSymbolAddress((void**)&hdh, g_hdh); cudaGetSymbolAddress((void**)&hdl, g_hdl);
    cudaGetSymbolAddress((void**)&wq, g_wq);
    cudaGetSymbolAddress((void**)&wp, g_wp);
    cudaGetSymbolAddress((void**)&w1, g_w1);
    cudaGetSymbolAddress((void**)&w2, g_w2);

    cudaFuncSetAttribute(gemm_tc<1>, cudaFuncAttributeMaxDynamicSharedMemorySize, GEMM_SMEM_BYTES);
    cudaFuncSetAttribute(gemm_tc<2>, cudaFuncAttributeMaxDynamicSharedMemorySize, GEMM_SMEM_BYTES);
    cudaFuncSetAttribute(gemm_tc<3>, cudaFuncAttributeMaxDynamicSharedMemorySize, GEMM_SMEM_BYTES);
    cudaFuncSetAttribute(attn_tc, cudaFuncAttributeMaxDynamicSharedMemorySize, AT_SMEM_BYTES);

    // Weight conversions (fp32 -> fp16 hi)
    cvt_w<<<(C3 * CC) / 1024, 256>>>(qkv_w, wq, (C3 * CC) / 4);
    cvt_w<<<(CC * CC) / 1024, 256>>>(proj_w, wp, (CC * CC) / 4);
    cvt_w<<<(HID * CC) / 1024, 256>>>(fc1_w, w1, (HID * CC) / 4);
    cvt_w<<<(CC * HID) / 1024, 256>>>(fc2_w, w2, (CC * HID) / 4);

    // 1) ln1 -> h1 (hi/lo)
    ln_kernel<<<MROWS, 256>>>(x, n1_w, n1_b, h1h, h1l);
    // 2) qkv = h1 @ qkv_w^T  (fp16 hi/lo out)
    gemm_tc<3><<<dim3(C3 / 128, MROWS / 128), 256, GEMM_SMEM_BYTES>>>(
        h1h, h1l, wq, nullptr, nullptr, nullptr, qvh, qvl,
        MROWS, C3, CC);
    // 3) attention -> attn (hi/lo)
    attn_tc<<<dim3(NN / 128, BB * HH), 256, AT_SMEM_BYTES>>>(qvh, qvl, rpb, ath, atl);
    // 4) x1 = x + attn @ proj_w^T + proj_b
    gemm_tc<1><<<dim3(CC / 128, MROWS / 128), 256, GEMM_SMEM_BYTES>>>(
        ath, atl, wp, proj_b, x, x1, nullptr, nullptr,
        MROWS, CC, CC);
    // 5) ln2 -> h2 (hi/lo)
    ln_kernel<<<MROWS, 256>>>(x1, n2_w, n2_b, h2h, h2l);
    // 6) hid = gelu(h2 @ fc1_w^T + fc1_b)  (hi/lo out)
    gemm_tc<2><<<dim3(HID / 128, MROWS / 128), 256, GEMM_SMEM_BYTES>>>(
        h2h, h2l, w1, fc1_b, nullptr, nullptr, hdh, hdl,
        MROWS, HID, CC);
    // 7) out = x1 + hid @ fc2_w^T + fc2_b
    gemm_tc<1><<<dim3(CC / 128, MROWS / 128), 256, GEMM_SMEM_BYTES>>>(
        hdh, hdl, w2, fc2_b, x1, out, nullptr, nullptr,
        MROWS, CC, HID);
}

// round 6
// speedup vs baseline: 7.0374x; 1.6171x over previous
#include <cuda_runtime.h>
#include <cuda_fp16.h>
#include <math.h>
#include <math_constants.h>
#include <stdint.h>

// Problem constants
#define BB    4
#define NN    2048
#define CC    512
#define HH    8
#define DH    64
#define HID   2048
#define MROWS (BB * NN)   // 8192
#define C3    (3 * CC)    // 1536

// ---------------------------------------------------------------------------
// Device scratch
// ---------------------------------------------------------------------------
__device__ float g_x1 [MROWS * CC];     // fp32 residual after attention

__device__ __half g_qv[MROWS * C3];
__device__ __half g_h1[MROWS * CC];
__device__ __half g_at[MROWS * CC];
__device__ __half g_h2[MROWS * CC];
__device__ __half g_hd[MROWS * HID];

__device__ __half g_wq[C3 * CC];
__device__ __half g_wp[CC * CC];
__device__ __half g_w1[HID * CC];
__device__ __half g_w2[CC * HID];

// ---------------------------------------------------------------------------
// PTX helpers
// ---------------------------------------------------------------------------
__device__ __forceinline__ uint32_t smem_u32(const void* p) {
    uint32_t a;
    asm("{ .reg .u64 t; cvta.to.shared.u64 t, %1; cvt.u32.u64 %0, t; }"
        : "=r"(a) : "l"(p));
    return a;
}

#define CP16(dst, src)                                                        \
    asm volatile("cp.async.cg.shared.global [%0], [%1], 16;"                  \
                 :: "r"(dst), "l"(src))
#define CP4(dst, src)                                                         \
    asm volatile("cp.async.ca.shared.global [%0], [%1], 4;"                   \
                 :: "r"(dst), "l"(src))
#define CP_COMMIT() asm volatile("cp.async.commit_group;" ::: "memory")
#define CP_WAIT1()  asm volatile("cp.async.wait_group 1;" ::: "memory")
#define CP_WAIT0()  asm volatile("cp.async.wait_group 0;" ::: "memory")

__device__ __forceinline__ void ldsm4(uint32_t* r, uint32_t addr) {
    asm volatile("ldmatrix.sync.aligned.m8n8.x4.shared.b16 {%0,%1,%2,%3}, [%4];"
                 : "=r"(r[0]), "=r"(r[1]), "=r"(r[2]), "=r"(r[3]) : "r"(addr));
}

__device__ __forceinline__ void ldsm4t(uint32_t* r, uint32_t addr) {
    asm volatile("ldmatrix.sync.aligned.m8n8.x4.trans.shared.b16 {%0,%1,%2,%3}, [%4];"
                 : "=r"(r[0]), "=r"(r[1]), "=r"(r[2]), "=r"(r[3]) : "r"(addr));
}

__device__ __forceinline__ void mma16816(float* d, const uint32_t* a,
                                         uint32_t b0, uint32_t b1) {
    asm volatile(
        "mma.sync.aligned.m16n8k16.row.col.f32.f16.f16.f32 "
        "{%0,%1,%2,%3}, {%4,%5,%6,%7}, {%8,%9}, {%0,%1,%2,%3};"
        : "+f"(d[0]), "+f"(d[1]), "+f"(d[2]), "+f"(d[3])
        : "r"(a[0]), "r"(a[1]), "r"(a[2]), "r"(a[3]), "r"(b0), "r"(b1));
}

__device__ __forceinline__ uint32_t sw128(uint32_t off) {
    return off ^ ((off >> 3) & 0x70u);
}

__device__ __forceinline__ uint32_t pack_h2(float a, float b) {
    __half2 p = __floats2half2_rn(a, b);
    return *(uint32_t*)&p;
}

// ---------------------------------------------------------------------------
// Weight conversion: fp32 -> fp16
// ---------------------------------------------------------------------------
__global__ void cvt_w(const float* __restrict__ x, __half* __restrict__ hi,
                      int n4) {
    int i = blockIdx.x * blockDim.x + threadIdx.x;
    if (i >= n4) return;
    float4 v = *(const float4*)(x + 4 * (size_t)i);
    __half2 p0 = __floats2half2_rn(v.x, v.y);
    __half2 p1 = __floats2half2_rn(v.z, v.w);
    *(__half2*)(hi + 4 * (size_t)i)     = p0;
    *(__half2*)(hi + 4 * (size_t)i + 2) = p1;
}

// ---------------------------------------------------------------------------
// LayerNorm -> fp16
// ---------------------------------------------------------------------------
__global__ void ln_kernel(const float* __restrict__ x,
                          const float* __restrict__ w,
                          const float* __restrict__ b,
                          __half* __restrict__ ohi) {
    const int row = blockIdx.x;
    const float* xr = x + (size_t)row * CC;
    const int t = threadIdx.x;

    float v0 = xr[t];
    float v1 = xr[t + 256];

    __shared__ float red1[8];
    __shared__ float red2[8];

    float s = v0 + v1;
    #pragma unroll
    for (int o = 16; o > 0; o >>= 1) s += __shfl_xor_sync(0xffffffffu, s, o);
    if ((t & 31) == 0) red1[t >> 5] = s;
    __syncthreads();
    float tot = 0.f;
    #pragma unroll
    for (int i = 0; i < 8; i++) tot += red1[i];
    const float mean = tot * (1.0f / CC);

    float d0 = v0 - mean, d1 = v1 - mean;
    float s2 = d0 * d0 + d1 * d1;
    #pragma unroll
    for (int o = 16; o > 0; o >>= 1) s2 += __shfl_xor_sync(0xffffffffu, s2, o);
    if ((t & 31) == 0) red2[t >> 5] = s2;
    __syncthreads();
    float tot2 = 0.f;
    #pragma unroll
    for (int i = 0; i < 8; i++) tot2 += red2[i];
    const float inv = rsqrtf(tot2 * (1.0f / CC) + 1e-5f);

    float y0 = d0 * inv * w[t]       + b[t];
    float y1 = d1 * inv * w[t + 256] + b[t + 256];

    ohi[(size_t)row * CC + t]       = __float2half_rn(y0);
    ohi[(size_t)row * CC + t + 256] = __float2half_rn(y1);
}

// ---------------------------------------------------------------------------
// mma.sync 1-pass fp16 NT GEMM:  C[M,Nn] = A[M,K] * W[Nn,K]^T
// CTA tile 128x128, BK=64, 8 warps (warp tile 64x32), double-buffered cp.async.
//   EPI 1: fp32 out = acc + bias[n] + res[m,n]
//   EPI 2: fp16 out = gelu(acc + bias[n])
//   EPI 3: fp16 out
// SMEM stage: [A 16K][B 16K], rows of 128B, SW128. 32K/stage.
// ---------------------------------------------------------------------------
#define GEMM_STAGE 32768
#define GEMM_SMEM_BYTES (2 * GEMM_STAGE)

__device__ __forceinline__ void load_chunk(
    const __half* __restrict__ A, const __half* __restrict__ B,
    int K, int m0, int n0, int kc, uint32_t sbuf, int tid) {
    #pragma unroll
    for (int j = 0; j < 8; j++) {
        const int linear = j * 256 + tid;
        const int arr = j >> 2;          // 0:A 1:B (compile-time)
        const int within = linear & 1023;
        const int r = within >> 3;
        const int c = within & 7;
        uint32_t sw = sw128((uint32_t)(r * 128 + c * 16));
        if (arr == 0) {
            CP16(sbuf + sw,
                 (const char*)(A + (size_t)(m0 + r) * K + (size_t)kc * 64 + c * 8));
        } else {
            CP16(sbuf + 16384 + sw,
                 (const char*)(B + (size_t)(n0 + r) * K + (size_t)kc * 64 + c * 8));
        }
    }
}

template <int EPI>
__global__ __launch_bounds__(256, 2)
void gemm_tc(const __half* __restrict__ A,
             const __half* __restrict__ B,
             const float* __restrict__ bias,
             const float* __restrict__ res,
             float* __restrict__ outF,
             __half* __restrict__ outH,
             int M, int Nn, int K) {
    extern __shared__ char dsm[];
    const uint32_t buf0 = smem_u32(dsm);
    const uint32_t buf1 = buf0 + GEMM_STAGE;

    const int tid  = threadIdx.x;
    const int wid  = tid >> 5;
    const int lane = tid & 31;

    const int m0 = blockIdx.y * 128;
    const int n0 = blockIdx.x * 128;
    const int NK = K >> 6;

    const int warp_m = (wid & 1) * 64;
    const int warp_n = (wid >> 1) * 32;

    const int lrow = lane & 7;
    const int sel  = lane >> 3;
    const int rofs = lrow + ((sel & 1) ? 8 : 0);
    const int kofs = (sel & 2) ? 8 : 0;

    float d[4][4][4] = {};

    load_chunk(A, B, K, m0, n0, 0, buf0, tid);
    CP_COMMIT();

    for (int kc = 0; kc < NK; kc++) {
        const uint32_t bufc = (kc & 1) ? buf1 : buf0;
        if (kc + 1 < NK) {
            load_chunk(A, B, K, m0, n0, kc + 1, (kc & 1) ? buf0 : buf1, tid);
            CP_COMMIT();
            CP_WAIT1();
        } else {
            CP_WAIT0();
        }
        __syncthreads();

        const uint32_t aS = bufc;
        const uint32_t bS = bufc + 16384;

        #pragma unroll
        for (int ks = 0; ks < 4; ks++) {
            const int kk = ks * 16 + kofs;
            uint32_t af[4][4], bf[2][4];
            #pragma unroll
            for (int mi = 0; mi < 4; mi++) {
                uint32_t off = sw128((uint32_t)((warp_m + 16 * mi + rofs) * 128 + kk * 2));
                ldsm4(af[mi], aS + off);
            }
            #pragma unroll
            for (int nj = 0; nj < 2; nj++) {
                uint32_t off = sw128((uint32_t)((warp_n + 16 * nj + rofs) * 128 + kk * 2));
                ldsm4(bf[nj], bS + off);
            }
            #pragma unroll
            for (int mi = 0; mi < 4; mi++) {
                #pragma unroll
                for (int nt = 0; nt < 4; nt++) {
                    const int nj = nt >> 1;
                    const int p  = nt & 1;
                    mma16816(d[mi][nt], af[mi], bf[nj][p], bf[nj][p + 2]);
                }
            }
        }
        __syncthreads();
    }

    const int erow0 = m0 + warp_m + (lane >> 2);
    const int ecol0 = n0 + warp_n + (lane & 3) * 2;

    #pragma unroll
    for (int mi = 0; mi < 4; mi++) {
        #pragma unroll
        for (int nt = 0; nt < 4; nt++) {
            const int col = ecol0 + nt * 8;
            #pragma unroll
            for (int half = 0; half < 2; half++) {
                const int row = erow0 + mi * 16 + half * 8;
                float v0 = d[mi][nt][2 * half + 0];
                float v1 = d[mi][nt][2 * half + 1];
                const size_t ob = (size_t)row * Nn + col;
                if (EPI == 1) {
                    float2 rv = *(const float2*)(res + ob);
                    v0 += bias[col]     + rv.x;
                    v1 += bias[col + 1] + rv.y;
                    *(float2*)(outF + ob) = make_float2(v0, v1);
                } else if (EPI == 2) {
                    v0 += bias[col];
                    v1 += bias[col + 1];
                    float g0 = v0 * normcdff(v0);
                    float g1 = v1 * normcdff(v1);
                    *(__half2*)(outH + ob) = __floats2half2_rn(g0, g1);
                } else {
                    *(__half2*)(outH + ob) = __floats2half2_rn(v0, v1);
                }
            }
        }
    }
}

// ---------------------------------------------------------------------------
// Tensor-core flash attention, 1-pass fp16.
// grid = (NN/128, BB*HH); block 256 (8 warps x 16 q-rows).
// SMEM: Q [128x64] (16K) + 2 stages of (K,V)[64x64] (16K each) + bias.
// ---------------------------------------------------------------------------
#define AT_Q      0
#define AT_STAGE  16384          // + s*16384 : K (8K), V (8K)
#define AT_BIAS   49152          // + s*1024 : 192 floats
#define AT_SMEM_BYTES (49152 + 2048)

__device__ __forceinline__ void attn_prefetch(
    const __half* __restrict__ qv, const float* __restrict__ rpb,
    int b, int h, int q0, int k0, uint32_t sbase, int s, int tid) {
    const uint32_t stage = sbase + AT_STAGE + s * 16384;
    #pragma unroll
    for (int j = 0; j < 4; j++) {
        int linear = tid + j * 256;
        int arr = linear >> 9;            // 0:K 1:V
        int within = linear & 511;
        int row = within >> 3;
        int c = within & 7;
        uint32_t dst = stage + arr * 8192 + sw128((uint32_t)(row * 128 + c * 16));
        int colbase = arr ? (2 * CC) : CC;
        CP16(dst, (const char*)(qv + (size_t)(b * NN + k0 + row) * C3
                                + colbase + h * DH + c * 8));
    }
    if (tid < 192) {
        int idx = k0 - q0 + 1920 + tid;
        if (tid >= 191) idx = k0 - q0 + 1920;
        CP4(sbase + AT_BIAS + s * 1024 + tid * 4, rpb + (size_t)idx * HH + h);
    }
}

__global__ __launch_bounds__(256, 1)
void attn_tc(const __half* __restrict__ qv,
             const float* __restrict__ rpb,
             __half* __restrict__ outH) {
    extern __shared__ char dsm[];
    const uint32_t sbase = smem_u32(dsm);

    const int q0 = blockIdx.x * 128;
    const int bh = blockIdx.y;
    const int b = bh >> 3;
    const int h = bh & 7;

    const int tid  = threadIdx.x;
    const int wid  = tid >> 5;
    const int lane = tid & 31;

    const int lrow = lane & 7;
    const int sel  = lane >> 3;
    const int rofs = lrow + ((sel & 1) ? 8 : 0);
    const int kofs = (sel & 2) ? 8 : 0;

    // --- load Q tile ---
    #pragma unroll
    for (int j = 0; j < 4; j++) {
        int linear = tid + j * 256;
        int row = linear >> 3;
        int c = linear & 7;
        uint32_t dst = sbase + AT_Q + sw128((uint32_t)(row * 128 + c * 16));
        CP16(dst, (const char*)(qv + (size_t)(b * NN + q0 + row) * C3
                                + h * DH + c * 8));
    }
    attn_prefetch(qv, rpb, b, h, q0, 0, sbase, 0, tid);
    CP_COMMIT();

    uint32_t qf[4][4];
    float oacc[8][4] = {};
    float m0 = -CUDART_INF_F, m1 = -CUDART_INF_F;
    float l0 = 0.f, l1 = 0.f;

    const int NCHUNK = NN / 64;
    for (int c = 0; c < NCHUNK; c++) {
        const int s = c & 1;
        const uint32_t stage = sbase + AT_STAGE + s * 16384;
        const uint32_t bstage = sbase + AT_BIAS + s * 1024;
        if (c + 1 < NCHUNK) {
            attn_prefetch(qv, rpb, b, h, q0, (c + 1) * 64, sbase, s ^ 1, tid);
            CP_COMMIT();
            CP_WAIT1();
        } else {
            CP_WAIT0();
        }
        __syncthreads();

        if (c == 0) {
            #pragma unroll
            for (int kc = 0; kc < 4; kc++) {
                uint32_t off = sw128((uint32_t)((wid * 16 + rofs) * 128
                                                + (kc * 16 + kofs) * 2));
                ldsm4(qf[kc], sbase + AT_Q + off);
            }
        }

        // ---- S = Q K^T ----
        float sacc[8][4] = {};
        #pragma unroll
        for (int kc = 0; kc < 4; kc++) {
            #pragma unroll
            for (int npair = 0; npair < 4; npair++) {
                uint32_t off = sw128((uint32_t)((npair * 16 + rofs) * 128
                                                + (kc * 16 + kofs) * 2));
                uint32_t kf[4];
                ldsm4(kf, stage + off);
                #pragma unroll
                for (int p = 0; p < 2; p++) {
                    mma16816(sacc[npair * 2 + p], qf[kc], kf[p], kf[p + 2]);
                }
            }
        }

        // ---- bias + online softmax ----
        const int r0 = wid * 16 + (lane >> 2);
        const int cb = (lane & 3) * 2;
        float mx0 = -CUDART_INF_F, mx1 = -CUDART_INF_F;
        #pragma unroll
        for (int nt = 0; nt < 8; nt++) {
            const int kk = nt * 8 + cb;
            float bv0, bv1, bv2, bv3;
            asm volatile("ld.shared.f32 %0, [%1];" : "=f"(bv0)
                         : "r"(bstage + (kk - r0 + 127) * 4));
            asm volatile("ld.shared.f32 %0, [%1];" : "=f"(bv1)
                         : "r"(bstage + (kk + 1 - r0 + 127) * 4));
            asm volatile("ld.shared.f32 %0, [%1];" : "=f"(bv2)
                         : "r"(bstage + (kk - (r0 + 8) + 127) * 4));
            asm volatile("ld.shared.f32 %0, [%1];" : "=f"(bv3)
                         : "r"(bstage + (kk + 1 - (r0 + 8) + 127) * 4));
            sacc[nt][0] = fmaf(sacc[nt][0], 0.125f, bv0);
            sacc[nt][1] = fmaf(sacc[nt][1], 0.125f, bv1);
            sacc[nt][2] = fmaf(sacc[nt][2], 0.125f, bv2);
            sacc[nt][3] = fmaf(sacc[nt][3], 0.125f, bv3);
            mx0 = fmaxf(mx0, fmaxf(sacc[nt][0], sacc[nt][1]));
            mx1 = fmaxf(mx1, fmaxf(sacc[nt][2], sacc[nt][3]));
        }
        mx0 = fmaxf(mx0, __shfl_xor_sync(0xffffffffu, mx0, 1));
        mx0 = fmaxf(mx0, __shfl_xor_sync(0xffffffffu, mx0, 2));
        mx1 = fmaxf(mx1, __shfl_xor_sync(0xffffffffu, mx1, 1));
        mx1 = fmaxf(mx1, __shfl_xor_sync(0xffffffffu, mx1, 2));
        const float mn0 = fmaxf(m0, mx0);
        const float mn1 = fmaxf(m1, mx1);
        const float fac0 = __expf(m0 - mn0);
        const float fac1 = __expf(m1 - mn1);
        float sum0 = 0.f, sum1 = 0.f;
        #pragma unroll
        for (int nt = 0; nt < 8; nt++) {
            sacc[nt][0] = __expf(sacc[nt][0] - mn0);
            sacc[nt][1] = __expf(sacc[nt][1] - mn0);
            sacc[nt][2] = __expf(sacc[nt][2] - mn1);
            sacc[nt][3] = __expf(sacc[nt][3] - mn1);
            sum0 += sacc[nt][0] + sacc[nt][1];
            sum1 += sacc[nt][2] + sacc[nt][3];
        }
        sum0 += __shfl_xor_sync(0xffffffffu, sum0, 1);
        sum0 += __shfl_xor_sync(0xffffffffu, sum0, 2);
        sum1 += __shfl_xor_sync(0xffffffffu, sum1, 1);
        sum1 += __shfl_xor_sync(0xffffffffu, sum1, 2);
        l0 = l0 * fac0 + sum0;
        l1 = l1 * fac1 + sum1;
        m0 = mn0;
        m1 = mn1;
        #pragma unroll
        for (int nt = 0; nt < 8; nt++) {
            oacc[nt][0] *= fac0;
            oacc[nt][1] *= fac0;
            oacc[nt][2] *= fac1;
            oacc[nt][3] *= fac1;
        }

        // ---- O += P V, P fragments built in registers ----
        #pragma unroll
        for (int kc = 0; kc < 4; kc++) {
            uint32_t pA[4];
            #pragma unroll
            for (int g = 0; g < 2; g++) {
                const float* sv = sacc[2 * kc + g];
                pA[2 * g + 0] = pack_h2(sv[0], sv[1]);
                pA[2 * g + 1] = pack_h2(sv[2], sv[3]);
            }
            #pragma unroll
            for (int dp = 0; dp < 4; dp++) {
                const int g = lane >> 3;
                const int rr = lane & 7;
                uint32_t off = sw128((uint32_t)((kc * 16 + (g & 1) * 8 + rr) * 128
                                                + dp * 32 + (g >> 1) * 16));
                uint32_t vf[4];
                ldsm4t(vf, stage + 8192 + off);
                #pragma unroll
                for (int p = 0; p < 2; p++) {
                    mma16816(oacc[dp * 2 + p], pA, vf[2 * p], vf[2 * p + 1]);
                }
            }
        }
        __syncthreads();
    }

    // ---- epilogue ----
    const float il0 = 1.0f / l0;
    const float il1 = 1.0f / l1;
    const int row0 = b * NN + q0 + wid * 16 + (lane >> 2);
    const int colb = h * DH + (lane & 3) * 2;
    #pragma unroll
    for (int nt = 0; nt < 8; nt++) {
        const int col = colb + nt * 8;
        *(__half2*)(outH + (size_t)row0 * CC + col) =
            __floats2half2_rn(oacc[nt][0] * il0, oacc[nt][1] * il0);
        *(__half2*)(outH + (size_t)(row0 + 8) * CC + col) =
            __floats2half2_rn(oacc[nt][2] * il1, oacc[nt][3] * il1);
    }
}

// ---------------------------------------------------------------------------
// Launcher
// ---------------------------------------------------------------------------
extern "C" void kernel_launch(void* const* d_in, const int* in_sizes, int n_in,
                              void* d_out, int out_size) {
    const float* x      = (const float*)d_in[0];
    const float* qkv_w  = (const float*)d_in[1];
    const float* proj_w = (const float*)d_in[2];
    const float* proj_b = (const float*)d_in[3];
    const float* rpb    = (const float*)d_in[4];
    const float* n1_w   = (const float*)d_in[5];
    const float* n1_b   = (const float*)d_in[6];
    const float* n2_w   = (const float*)d_in[7];
    const float* n2_b   = (const float*)d_in[8];
    const float* fc1_w  = (const float*)d_in[9];
    const float* fc1_b  = (const float*)d_in[10];
    const float* fc2_w  = (const float*)d_in[11];
    const float* fc2_b  = (const float*)d_in[12];
    float* out = (float*)d_out;

    float *x1;
    __half *qv, *h1, *at, *h2, *hd, *wq, *wp, *w1, *w2;
    cudaGetSymbolAddress((void**)&x1, g_x1);
    cudaGetSymbolAddress((void**)&qv, g_qv);
    cudaGetSymbolAddress((void**)&h1, g_h1);
    cudaGetSymbolAddress((void**)&at, g_at);
    cudaGetSymbolAddress((void**)&h2, g_h2);
    cudaGetSymbolAddress((void**)&hd, g_hd);
    cudaGetSymbolAddress((void**)&wq, g_wq);
    cudaGetSymbolAddress((void**)&wp, g_wp);
    cudaGetSymbolAddress((void**)&w1, g_w1);
    cudaGetSymbolAddress((void**)&w2, g_w2);

    cudaFuncSetAttribute(gemm_tc<1>, cudaFuncAttributeMaxDynamicSharedMemorySize, GEMM_SMEM_BYTES);
    cudaFuncSetAttribute(gemm_tc<2>, cudaFuncAttributeMaxDynamicSharedMemorySize, GEMM_SMEM_BYTES);
    cudaFuncSetAttribute(gemm_tc<3>, cudaFuncAttributeMaxDynamicSharedMemorySize, GEMM_SMEM_BYTES);
    cudaFuncSetAttribute(attn_tc, cudaFuncAttributeMaxDynamicSharedMemorySize, AT_SMEM_BYTES);

    // Weight conversions (fp32 -> fp16)
    cvt_w<<<(C3 * CC) / 1024, 256>>>(qkv_w, wq, (C3 * CC) / 4);
    cvt_w<<<(CC * CC) / 1024, 256>>>(proj_w, wp, (CC * CC) / 4);
    cvt_w<<<(HID * CC) / 1024, 256>>>(fc1_w, w1, (HID * CC) / 4);
    cvt_w<<<(CC * HID) / 1024, 256>>>(fc2_w, w2, (CC * HID) / 4);

    // 1) ln1 -> h1
    ln_kernel<<<MROWS, 256>>>(x, n1_w, n1_b, h1);
    // 2) qkv = h1 @ qkv_w^T
    gemm_tc<3><<<dim3(C3 / 128, MROWS / 128), 256, GEMM_SMEM_BYTES>>>(
        h1, wq, nullptr, nullptr, nullptr, qv, MROWS, C3, CC);
    // 3) attention -> at
    attn_tc<<<dim3(NN / 128, BB * HH), 256, AT_SMEM_BYTES>>>(qv, rpb, at);
    // 4) x1 = x + at @ proj_w^T + proj_b
    gemm_tc<1><<<dim3(CC / 128, MROWS / 128), 256, GEMM_SMEM_BYTES>>>(
        at, wp, proj_b, x, x1, nullptr, MROWS, CC, CC);
    // 5) ln2 -> h2
    ln_kernel<<<MROWS, 256>>>(x1, n2_w, n2_b, h2);
    // 6) hd = gelu(h2 @ fc1_w^T + fc1_b)
    gemm_tc<2><<<dim3(HID / 128, MROWS / 128), 256, GEMM_SMEM_BYTES>>>(
        h2, w1, fc1_b, nullptr, nullptr, hd, MROWS, HID, CC);
    // 7) out = x1 + hd @ fc2_w^T + fc2_b
    gemm_tc<1><<<dim3(CC / 128, MROWS / 128), 256, GEMM_SMEM_BYTES>>>(
        hd, w2, fc2_b, x1, out, nullptr, MROWS, CC, HID);
}

// round 7
// speedup vs baseline: 7.0657x; 1.0040x over previous
#include <cuda_runtime.h>
#include <cuda_fp16.h>
#include <math.h>
#include <math_constants.h>
#include <stdint.h>

// Problem constants
#define BB    4
#define NN    2048
#define CC    512
#define HH    8
#define DH    64
#define HID   2048
#define MROWS (BB * NN)   // 8192
#define C3    (3 * CC)    // 1536

// ---------------------------------------------------------------------------
// Device scratch
// ---------------------------------------------------------------------------
__device__ float g_x1 [MROWS * CC];     // fp32 residual after attention

__device__ __half g_qv[MROWS * C3];
__device__ __half g_h1[MROWS * CC];
__device__ __half g_at[MROWS * CC];
__device__ __half g_h2[MROWS * CC];
__device__ __half g_hd[MROWS * HID];

__device__ __half g_wq[C3 * CC];
__device__ __half g_wp[CC * CC];
__device__ __half g_w1[HID * CC];
__device__ __half g_w2[CC * HID];

// ---------------------------------------------------------------------------
// PTX helpers
// ---------------------------------------------------------------------------
__device__ __forceinline__ uint32_t smem_u32(const void* p) {
    uint32_t a;
    asm("{ .reg .u64 t; cvta.to.shared.u64 t, %1; cvt.u32.u64 %0, t; }"
        : "=r"(a) : "l"(p));
    return a;
}

#define CP16(dst, src)                                                        \
    asm volatile("cp.async.cg.shared.global [%0], [%1], 16;"                  \
                 :: "r"(dst), "l"(src))
#define CP4(dst, src)                                                         \
    asm volatile("cp.async.ca.shared.global [%0], [%1], 4;"                   \
                 :: "r"(dst), "l"(src))
#define CP_COMMIT() asm volatile("cp.async.commit_group;" ::: "memory")
#define CP_WAIT1()  asm volatile("cp.async.wait_group 1;" ::: "memory")
#define CP_WAIT0()  asm volatile("cp.async.wait_group 0;" ::: "memory")

__device__ __forceinline__ void ldsm4(uint32_t* r, uint32_t addr) {
    asm volatile("ldmatrix.sync.aligned.m8n8.x4.shared.b16 {%0,%1,%2,%3}, [%4];"
                 : "=r"(r[0]), "=r"(r[1]), "=r"(r[2]), "=r"(r[3]) : "r"(addr));
}

__device__ __forceinline__ void ldsm4t(uint32_t* r, uint32_t addr) {
    asm volatile("ldmatrix.sync.aligned.m8n8.x4.trans.shared.b16 {%0,%1,%2,%3}, [%4];"
                 : "=r"(r[0]), "=r"(r[1]), "=r"(r[2]), "=r"(r[3]) : "r"(addr));
}

__device__ __forceinline__ void mma16816(float* d, const uint32_t* a,
                                         uint32_t b0, uint32_t b1) {
    asm volatile(
        "mma.sync.aligned.m16n8k16.row.col.f32.f16.f16.f32 "
        "{%0,%1,%2,%3}, {%4,%5,%6,%7}, {%8,%9}, {%0,%1,%2,%3};"
        : "+f"(d[0]), "+f"(d[1]), "+f"(d[2]), "+f"(d[3])
        : "r"(a[0]), "r"(a[1]), "r"(a[2]), "r"(a[3]), "r"(b0), "r"(b1));
}

__device__ __forceinline__ uint32_t sw128(uint32_t off) {
    return off ^ ((off >> 3) & 0x70u);
}

__device__ __forceinline__ uint32_t pack_h2(float a, float b) {
    __half2 p = __floats2half2_rn(a, b);
    return *(uint32_t*)&p;
}

// ---------------------------------------------------------------------------
// Weight conversion: fp32 -> fp16
// ---------------------------------------------------------------------------
__global__ void cvt_w(const float* __restrict__ x, __half* __restrict__ hi,
                      int n4) {
    int i = blockIdx.x * blockDim.x + threadIdx.x;
    if (i >= n4) return;
    float4 v = *(const float4*)(x + 4 * (size_t)i);
    __half2 p0 = __floats2half2_rn(v.x, v.y);
    __half2 p1 = __floats2half2_rn(v.z, v.w);
    *(__half2*)(hi + 4 * (size_t)i)     = p0;
    *(__half2*)(hi + 4 * (size_t)i + 2) = p1;
}

// ---------------------------------------------------------------------------
// LayerNorm -> fp16
// ---------------------------------------------------------------------------
__global__ void ln_kernel(const float* __restrict__ x,
                          const float* __restrict__ w,
                          const float* __restrict__ b,
                          __half* __restrict__ ohi) {
    const int row = blockIdx.x;
    const float* xr = x + (size_t)row * CC;
    const int t = threadIdx.x;

    float v0 = xr[t];
    float v1 = xr[t + 256];

    __shared__ float red1[8];
    __shared__ float red2[8];

    float s = v0 + v1;
    #pragma unroll
    for (int o = 16; o > 0; o >>= 1) s += __shfl_xor_sync(0xffffffffu, s, o);
    if ((t & 31) == 0) red1[t >> 5] = s;
    __syncthreads();
    float tot = 0.f;
    #pragma unroll
    for (int i = 0; i < 8; i++) tot += red1[i];
    const float mean = tot * (1.0f / CC);

    float d0 = v0 - mean, d1 = v1 - mean;
    float s2 = d0 * d0 + d1 * d1;
    #pragma unroll
    for (int o = 16; o > 0; o >>= 1) s2 += __shfl_xor_sync(0xffffffffu, s2, o);
    if ((t & 31) == 0) red2[t >> 5] = s2;
    __syncthreads();
    float tot2 = 0.f;
    #pragma unroll
    for (int i = 0; i < 8; i++) tot2 += red2[i];
    const float inv = rsqrtf(tot2 * (1.0f / CC) + 1e-5f);

    float y0 = d0 * inv * w[t]       + b[t];
    float y1 = d1 * inv * w[t + 256] + b[t + 256];

    ohi[(size_t)row * CC + t]       = __float2half_rn(y0);
    ohi[(size_t)row * CC + t + 256] = __float2half_rn(y1);
}

// ---------------------------------------------------------------------------
// mma.sync 1-pass fp16 NT GEMM:  C[M,Nn] = A[M,K] * W[Nn,K]^T
// CTA tile 128x128, BK=64, 8 warps (warp tile 64x32).
// 3-stage cp.async pipeline, ONE __syncthreads per k-iteration.
//   EPI 1: fp32 out = acc + bias[n] + res[m,n]
//   EPI 2: fp16 out = gelu(acc + bias[n])
//   EPI 3: fp16 out
// SMEM stage: [A 16K][B 16K], rows of 128B, SW128. 32K/stage, 3 stages.
// ---------------------------------------------------------------------------
#define GEMM_STAGE 32768
#define GEMM_SMEM_BYTES (3 * GEMM_STAGE)

__device__ __forceinline__ void load_chunk(
    const __half* __restrict__ A, const __half* __restrict__ B,
    int K, int m0, int n0, int kc, uint32_t sbuf, int tid) {
    #pragma unroll
    for (int j = 0; j < 8; j++) {
        const int linear = j * 256 + tid;
        const int arr = j >> 2;          // 0:A 1:B (compile-time)
        const int within = linear & 1023;
        const int r = within >> 3;
        const int c = within & 7;
        uint32_t sw = sw128((uint32_t)(r * 128 + c * 16));
        if (arr == 0) {
            CP16(sbuf + sw,
                 (const char*)(A + (size_t)(m0 + r) * K + (size_t)kc * 64 + c * 8));
        } else {
            CP16(sbuf + 16384 + sw,
                 (const char*)(B + (size_t)(n0 + r) * K + (size_t)kc * 64 + c * 8));
        }
    }
}

template <int EPI>
__global__ __launch_bounds__(256, 2)
void gemm_tc(const __half* __restrict__ A,
             const __half* __restrict__ B,
             const float* __restrict__ bias,
             const float* __restrict__ res,
             float* __restrict__ outF,
             __half* __restrict__ outH,
             int M, int Nn, int K) {
    extern __shared__ char dsm[];
    const uint32_t bufs = smem_u32(dsm);

    const int tid  = threadIdx.x;
    const int wid  = tid >> 5;
    const int lane = tid & 31;

    const int m0 = blockIdx.y * 128;
    const int n0 = blockIdx.x * 128;
    const int NK = K >> 6;

    const int warp_m = (wid & 1) * 64;
    const int warp_n = (wid >> 1) * 32;

    const int lrow = lane & 7;
    const int sel  = lane >> 3;
    const int rofs = lrow + ((sel & 1) ? 8 : 0);
    const int kofs = (sel & 2) ? 8 : 0;

    float d[4][4][4] = {};

    // Prologue: stages 0 and 1
    load_chunk(A, B, K, m0, n0, 0, bufs, tid);
    CP_COMMIT();
    load_chunk(A, B, K, m0, n0, 1, bufs + GEMM_STAGE, tid);
    CP_COMMIT();

    for (int kc = 0; kc < NK; kc++) {
        const uint32_t bufc = bufs + (kc % 3) * GEMM_STAGE;
        if (kc + 1 < NK) { CP_WAIT1(); } else { CP_WAIT0(); }
        __syncthreads();

        const uint32_t aS = bufc;
        const uint32_t bS = bufc + 16384;

        #pragma unroll
        for (int ks = 0; ks < 4; ks++) {
            const int kk = ks * 16 + kofs;
            uint32_t af[4][4], bf[2][4];
            #pragma unroll
            for (int mi = 0; mi < 4; mi++) {
                uint32_t off = sw128((uint32_t)((warp_m + 16 * mi + rofs) * 128 + kk * 2));
                ldsm4(af[mi], aS + off);
            }
            #pragma unroll
            for (int nj = 0; nj < 2; nj++) {
                uint32_t off = sw128((uint32_t)((warp_n + 16 * nj + rofs) * 128 + kk * 2));
                ldsm4(bf[nj], bS + off);
            }
            #pragma unroll
            for (int mi = 0; mi < 4; mi++) {
                #pragma unroll
                for (int nt = 0; nt < 4; nt++) {
                    const int nj = nt >> 1;
                    const int p  = nt & 1;
                    mma16816(d[mi][nt], af[mi], bf[nj][p], bf[nj][p + 2]);
                }
            }
        }

        if (kc + 2 < NK) {
            load_chunk(A, B, K, m0, n0, kc + 2,
                       bufs + ((kc + 2) % 3) * GEMM_STAGE, tid);
            CP_COMMIT();
        }
    }

    const int erow0 = m0 + warp_m + (lane >> 2);
    const int ecol0 = n0 + warp_n + (lane & 3) * 2;

    #pragma unroll
    for (int mi = 0; mi < 4; mi++) {
        #pragma unroll
        for (int nt = 0; nt < 4; nt++) {
            const int col = ecol0 + nt * 8;
            #pragma unroll
            for (int half = 0; half < 2; half++) {
                const int row = erow0 + mi * 16 + half * 8;
                float v0 = d[mi][nt][2 * half + 0];
                float v1 = d[mi][nt][2 * half + 1];
                const size_t ob = (size_t)row * Nn + col;
                if (EPI == 1) {
                    float2 rv = *(const float2*)(res + ob);
                    v0 += bias[col]     + rv.x;
                    v1 += bias[col + 1] + rv.y;
                    *(float2*)(outF + ob) = make_float2(v0, v1);
                } else if (EPI == 2) {
                    v0 += bias[col];
                    v1 += bias[col + 1];
                    float g0 = v0 * normcdff(v0);
                    float g1 = v1 * normcdff(v1);
                    *(__half2*)(outH + ob) = __floats2half2_rn(g0, g1);
                } else {
                    *(__half2*)(outH + ob) = __floats2half2_rn(v0, v1);
                }
            }
        }
    }
}

// ---------------------------------------------------------------------------
// Tensor-core flash attention, 1-pass fp16, 3-stage pipeline, occupancy 2.
// grid = (NN/128, BB*HH); block 256 (8 warps x 16 q-rows).
// SMEM: Q [128x64] (16K) + 3 stages of (K,V)[64x64] (16K each) + 3 bias (1K).
// ---------------------------------------------------------------------------
#define AT_Q      0
#define AT_STAGE  16384          // + s*16384 : K (8K), V (8K)
#define AT_BIAS   (16384 + 3 * 16384)   // + s*1024 : 192 floats
#define AT_SMEM_BYTES (AT_BIAS + 3 * 1024)

__device__ __forceinline__ void attn_prefetch(
    const __half* __restrict__ qv, const float* __restrict__ rpb,
    int b, int h, int q0, int k0, uint32_t sbase, int s, int tid) {
    const uint32_t stage = sbase + AT_STAGE + s * 16384;
    #pragma unroll
    for (int j = 0; j < 4; j++) {
        int linear = tid + j * 256;
        int arr = linear >> 9;            // 0:K 1:V
        int within = linear & 511;
        int row = within >> 3;
        int c = within & 7;
        uint32_t dst = stage + arr * 8192 + sw128((uint32_t)(row * 128 + c * 16));
        int colbase = arr ? (2 * CC) : CC;
        CP16(dst, (const char*)(qv + (size_t)(b * NN + k0 + row) * C3
                                + colbase + h * DH + c * 8));
    }
    if (tid < 192) {
        int idx = k0 - q0 + 1920 + tid;
        if (tid >= 191) idx = k0 - q0 + 1920;
        CP4(sbase + AT_BIAS + s * 1024 + tid * 4, rpb + (size_t)idx * HH + h);
    }
}

__global__ __launch_bounds__(256, 2)
void attn_tc(const __half* __restrict__ qv,
             const float* __restrict__ rpb,
             __half* __restrict__ outH) {
    extern __shared__ char dsm[];
    const uint32_t sbase = smem_u32(dsm);

    const int q0 = blockIdx.x * 128;
    const int bh = blockIdx.y;
    const int b = bh >> 3;
    const int h = bh & 7;

    const int tid  = threadIdx.x;
    const int wid  = tid >> 5;
    const int lane = tid & 31;

    const int lrow = lane & 7;
    const int sel  = lane >> 3;
    const int rofs = lrow + ((sel & 1) ? 8 : 0);
    const int kofs = (sel & 2) ? 8 : 0;

    // --- load Q tile (group 0, together with chunk-0 prefetch) ---
    #pragma unroll
    for (int j = 0; j < 4; j++) {
        int linear = tid + j * 256;
        int row = linear >> 3;
        int c = linear & 7;
        uint32_t dst = sbase + AT_Q + sw128((uint32_t)(row * 128 + c * 16));
        CP16(dst, (const char*)(qv + (size_t)(b * NN + q0 + row) * C3
                                + h * DH + c * 8));
    }
    attn_prefetch(qv, rpb, b, h, q0, 0, sbase, 0, tid);
    CP_COMMIT();
    attn_prefetch(qv, rpb, b, h, q0, 64, sbase, 1, tid);
    CP_COMMIT();

    uint32_t qf[4][4];
    float oacc[8][4] = {};
    float m0 = -CUDART_INF_F, m1 = -CUDART_INF_F;
    float l0 = 0.f, l1 = 0.f;

    const int NCHUNK = NN / 64;
    for (int c = 0; c < NCHUNK; c++) {
        const int s = c % 3;
        const uint32_t stage = sbase + AT_STAGE + s * 16384;
        const uint32_t bstage = sbase + AT_BIAS + s * 1024;
        if (c + 1 < NCHUNK) { CP_WAIT1(); } else { CP_WAIT0(); }
        __syncthreads();

        if (c == 0) {
            #pragma unroll
            for (int kc = 0; kc < 4; kc++) {
                uint32_t off = sw128((uint32_t)((wid * 16 + rofs) * 128
                                                + (kc * 16 + kofs) * 2));
                ldsm4(qf[kc], sbase + AT_Q + off);
            }
        }

        // ---- S = Q K^T ----
        float sacc[8][4] = {};
        #pragma unroll
        for (int kc = 0; kc < 4; kc++) {
            #pragma unroll
            for (int npair = 0; npair < 4; npair++) {
                uint32_t off = sw128((uint32_t)((npair * 16 + rofs) * 128
                                                + (kc * 16 + kofs) * 2));
                uint32_t kf[4];
                ldsm4(kf, stage + off);
                #pragma unroll
                for (int p = 0; p < 2; p++) {
                    mma16816(sacc[npair * 2 + p], qf[kc], kf[p], kf[p + 2]);
                }
            }
        }

        // ---- bias + online softmax ----
        const int r0 = wid * 16 + (lane >> 2);
        const int cb = (lane & 3) * 2;
        float mx0 = -CUDART_INF_F, mx1 = -CUDART_INF_F;
        #pragma unroll
        for (int nt = 0; nt < 8; nt++) {
            const int kk = nt * 8 + cb;
            float bv0, bv1, bv2, bv3;
            asm volatile("ld.shared.f32 %0, [%1];" : "=f"(bv0)
                         : "r"(bstage + (kk - r0 + 127) * 4));
            asm volatile("ld.shared.f32 %0, [%1];" : "=f"(bv1)
                         : "r"(bstage + (kk + 1 - r0 + 127) * 4));
            asm volatile("ld.shared.f32 %0, [%1];" : "=f"(bv2)
                         : "r"(bstage + (kk - (r0 + 8) + 127) * 4));
            asm volatile("ld.shared.f32 %0, [%1];" : "=f"(bv3)
                         : "r"(bstage + (kk + 1 - (r0 + 8) + 127) * 4));
            sacc[nt][0] = fmaf(sacc[nt][0], 0.125f, bv0);
            sacc[nt][1] = fmaf(sacc[nt][1], 0.125f, bv1);
            sacc[nt][2] = fmaf(sacc[nt][2], 0.125f, bv2);
            sacc[nt][3] = fmaf(sacc[nt][3], 0.125f, bv3);
            mx0 = fmaxf(mx0, fmaxf(sacc[nt][0], sacc[nt][1]));
            mx1 = fmaxf(mx1, fmaxf(sacc[nt][2], sacc[nt][3]));
        }
        mx0 = fmaxf(mx0, __shfl_xor_sync(0xffffffffu, mx0, 1));
        mx0 = fmaxf(mx0, __shfl_xor_sync(0xffffffffu, mx0, 2));
        mx1 = fmaxf(mx1, __shfl_xor_sync(0xffffffffu, mx1, 1));
        mx1 = fmaxf(mx1, __shfl_xor_sync(0xffffffffu, mx1, 2));
        const float mn0 = fmaxf(m0, mx0);
        const float mn1 = fmaxf(m1, mx1);
        const float fac0 = __expf(m0 - mn0);
        const float fac1 = __expf(m1 - mn1);
        float sum0 = 0.f, sum1 = 0.f;
        #pragma unroll
        for (int nt = 0; nt < 8; nt++) {
            sacc[nt][0] = __expf(sacc[nt][0] - mn0);
            sacc[nt][1] = __expf(sacc[nt][1] - mn0);
            sacc[nt][2] = __expf(sacc[nt][2] - mn1);
            sacc[nt][3] = __expf(sacc[nt][3] - mn1);
            sum0 += sacc[nt][0] + sacc[nt][1];
            sum1 += sacc[nt][2] + sacc[nt][3];
        }
        sum0 += __shfl_xor_sync(0xffffffffu, sum0, 1);
        sum0 += __shfl_xor_sync(0xffffffffu, sum0, 2);
        sum1 += __shfl_xor_sync(0xffffffffu, sum1, 1);
        sum1 += __shfl_xor_sync(0xffffffffu, sum1, 2);
        l0 = l0 * fac0 + sum0;
        l1 = l1 * fac1 + sum1;
        m0 = mn0;
        m1 = mn1;
        #pragma unroll
        for (int nt = 0; nt < 8; nt++) {
            oacc[nt][0] *= fac0;
            oacc[nt][1] *= fac0;
            oacc[nt][2] *= fac1;
            oacc[nt][3] *= fac1;
        }

        // ---- O += P V, P fragments built in registers ----
        #pragma unroll
        for (int kc = 0; kc < 4; kc++) {
            uint32_t pA[4];
            #pragma unroll
            for (int g = 0; g < 2; g++) {
                const float* sv = sacc[2 * kc + g];
                pA[2 * g + 0] = pack_h2(sv[0], sv[1]);
                pA[2 * g + 1] = pack_h2(sv[2], sv[3]);
            }
            #pragma unroll
            for (int dp = 0; dp < 4; dp++) {
                const int g = lane >> 3;
                const int rr = lane & 7;
                uint32_t off = sw128((uint32_t)((kc * 16 + (g & 1) * 8 + rr) * 128
                                                + dp * 32 + (g >> 1) * 16));
                uint32_t vf[4];
                ldsm4t(vf, stage + 8192 + off);
                #pragma unroll
                for (int p = 0; p < 2; p++) {
                    mma16816(oacc[dp * 2 + p], pA, vf[2 * p], vf[2 * p + 1]);
                }
            }
        }

        if (c + 2 < NCHUNK) {
            attn_prefetch(qv, rpb, b, h, q0, (c + 2) * 64, sbase, (c + 2) % 3, tid);
            CP_COMMIT();
        }
    }

    // ---- epilogue ----
    const float il0 = 1.0f / l0;
    const float il1 = 1.0f / l1;
    const int row0 = b * NN + q0 + wid * 16 + (lane >> 2);
    const int colb = h * DH + (lane & 3) * 2;
    #pragma unroll
    for (int nt = 0; nt < 8; nt++) {
        const int col = colb + nt * 8;
        *(__half2*)(outH + (size_t)row0 * CC + col) =
            __floats2half2_rn(oacc[nt][0] * il0, oacc[nt][1] * il0);
        *(__half2*)(outH + (size_t)(row0 + 8) * CC + col) =
            __floats2half2_rn(oacc[nt][2] * il1, oacc[nt][3] * il1);
    }
}

// ---------------------------------------------------------------------------
// Launcher
// ---------------------------------------------------------------------------
extern "C" void kernel_launch(void* const* d_in, const int* in_sizes, int n_in,
                              void* d_out, int out_size) {
    const float* x      = (const float*)d_in[0];
    const float* qkv_w  = (const float*)d_in[1];
    const float* proj_w = (const float*)d_in[2];
    const float* proj_b = (const float*)d_in[3];
    const float* rpb    = (const float*)d_in[4];
    const float* n1_w   = (const float*)d_in[5];
    const float* n1_b   = (const float*)d_in[6];
    const float* n2_w   = (const float*)d_in[7];
    const float* n2_b   = (const float*)d_in[8];
    const float* fc1_w  = (const float*)d_in[9];
    const float* fc1_b  = (const float*)d_in[10];
    const float* fc2_w  = (const float*)d_in[11];
    const float* fc2_b  = (const float*)d_in[12];
    float* out = (float*)d_out;

    float *x1;
    __half *qv, *h1, *at, *h2, *hd, *wq, *wp, *w1, *w2;
    cudaGetSymbolAddress((void**)&x1, g_x1);
    cudaGetSymbolAddress((void**)&qv, g_qv);
    cudaGetSymbolAddress((void**)&h1, g_h1);
    cudaGetSymbolAddress((void**)&at, g_at);
    cudaGetSymbolAddress((void**)&h2, g_h2);
    cudaGetSymbolAddress((void**)&hd, g_hd);
    cudaGetSymbolAddress((void**)&wq, g_wq);
    cudaGetSymbolAddress((void**)&wp, g_wp);
    cudaGetSymbolAddress((void**)&w1, g_w1);
    cudaGetSymbolAddress((void**)&w2, g_w2);

    cudaFuncSetAttribute(gemm_tc<1>, cudaFuncAttributeMaxDynamicSharedMemorySize, GEMM_SMEM_BYTES);
    cudaFuncSetAttribute(gemm_tc<2>, cudaFuncAttributeMaxDynamicSharedMemorySize, GEMM_SMEM_BYTES);
    cudaFuncSetAttribute(gemm_tc<3>, cudaFuncAttributeMaxDynamicSharedMemorySize, GEMM_SMEM_BYTES);
    cudaFuncSetAttribute(attn_tc, cudaFuncAttributeMaxDynamicSharedMemorySize, AT_SMEM_BYTES);

    // Weight conversions (fp32 -> fp16)
    cvt_w<<<(C3 * CC) / 1024, 256>>>(qkv_w, wq, (C3 * CC) / 4);
    cvt_w<<<(CC * CC) / 1024, 256>>>(proj_w, wp, (CC * CC) / 4);
    cvt_w<<<(HID * CC) / 1024, 256>>>(fc1_w, w1, (HID * CC) / 4);
    cvt_w<<<(CC * HID) / 1024, 256>>>(fc2_w, w2, (CC * HID) / 4);

    // 1) ln1 -> h1
    ln_kernel<<<MROWS, 256>>>(x, n1_w, n1_b, h1);
    // 2) qkv = h1 @ qkv_w^T
    gemm_tc<3><<<dim3(C3 / 128, MROWS / 128), 256, GEMM_SMEM_BYTES>>>(
        h1, wq, nullptr, nullptr, nullptr, qv, MROWS, C3, CC);
    // 3) attention -> at
    attn_tc<<<dim3(NN / 128, BB * HH), 256, AT_SMEM_BYTES>>>(qv, rpb, at);
    // 4) x1 = x + at @ proj_w^T + proj_b
    gemm_tc<1><<<dim3(CC / 128, MROWS / 128), 256, GEMM_SMEM_BYTES>>>(
        at, wp, proj_b, x, x1, nullptr, MROWS, CC, CC);
    // 5) ln2 -> h2
    ln_kernel<<<MROWS, 256>>>(x1, n2_w, n2_b, h2);
    // 6) hd = gelu(h2 @ fc1_w^T + fc1_b)
    gemm_tc<2><<<dim3(HID / 128, MROWS / 128), 256, GEMM_SMEM_BYTES>>>(
        h2, w1, fc1_b, nullptr, nullptr, hd, MROWS, HID, CC);
    // 7) out = x1 + hd @ fc2_w^T + fc2_b
    gemm_tc<1><<<dim3(CC / 128, MROWS / 128), 256, GEMM_SMEM_BYTES>>>(
        hd, w2, fc2_b, x1, out, nullptr, MROWS, CC, HID);
}

// round 8
// speedup vs baseline: 7.0875x; 1.0031x over previous
#include <cuda_runtime.h>
#include <cuda_fp16.h>
#include <math.h>
#include <math_constants.h>
#include <stdint.h>

// Problem constants
#define BB    4
#define NN    2048
#define CC    512
#define HH    8
#define DH    64
#define HID   2048
#define MROWS (BB * NN)   // 8192
#define C3    (3 * CC)    // 1536

// ---------------------------------------------------------------------------
// Device scratch
// ---------------------------------------------------------------------------
__device__ float g_x1 [MROWS * CC];     // fp32 residual after attention

__device__ __half g_qv[MROWS * C3];
__device__ __half g_h1[MROWS * CC];
__device__ __half g_at[MROWS * CC];
__device__ __half g_h2[MROWS * CC];
__device__ __half g_hd[MROWS * HID];

__device__ __half g_wq[C3 * CC];
__device__ __half g_wp[CC * CC];
__device__ __half g_w1[HID * CC];
__device__ __half g_w2[CC * HID];

// ---------------------------------------------------------------------------
// PTX helpers
// ---------------------------------------------------------------------------
__device__ __forceinline__ uint32_t smem_u32(const void* p) {
    uint32_t a;
    asm("{ .reg .u64 t; cvta.to.shared.u64 t, %1; cvt.u32.u64 %0, t; }"
        : "=r"(a) : "l"(p));
    return a;
}

#define CP16(dst, src)                                                        \
    asm volatile("cp.async.cg.shared.global [%0], [%1], 16;"                  \
                 :: "r"(dst), "l"(src))
#define CP4(dst, src)                                                         \
    asm volatile("cp.async.ca.shared.global [%0], [%1], 4;"                   \
                 :: "r"(dst), "l"(src))
#define CP_COMMIT() asm volatile("cp.async.commit_group;" ::: "memory")
#define CP_WAIT1()  asm volatile("cp.async.wait_group 1;" ::: "memory")
#define CP_WAIT0()  asm volatile("cp.async.wait_group 0;" ::: "memory")

__device__ __forceinline__ void ldsm4(uint32_t* r, uint32_t addr) {
    asm volatile("ldmatrix.sync.aligned.m8n8.x4.shared.b16 {%0,%1,%2,%3}, [%4];"
                 : "=r"(r[0]), "=r"(r[1]), "=r"(r[2]), "=r"(r[3]) : "r"(addr));
}

__device__ __forceinline__ void ldsm4t(uint32_t* r, uint32_t addr) {
    asm volatile("ldmatrix.sync.aligned.m8n8.x4.trans.shared.b16 {%0,%1,%2,%3}, [%4];"
                 : "=r"(r[0]), "=r"(r[1]), "=r"(r[2]), "=r"(r[3]) : "r"(addr));
}

__device__ __forceinline__ void mma16816(float* d, const uint32_t* a,
                                         uint32_t b0, uint32_t b1) {
    asm volatile(
        "mma.sync.aligned.m16n8k16.row.col.f32.f16.f16.f32 "
        "{%0,%1,%2,%3}, {%4,%5,%6,%7}, {%8,%9}, {%0,%1,%2,%3};"
        : "+f"(d[0]), "+f"(d[1]), "+f"(d[2]), "+f"(d[3])
        : "r"(a[0]), "r"(a[1]), "r"(a[2]), "r"(a[3]), "r"(b0), "r"(b1));
}

__device__ __forceinline__ uint32_t sw128(uint32_t off) {
    return off ^ ((off >> 3) & 0x70u);
}

__device__ __forceinline__ uint32_t pack_h2(float a, float b) {
    __half2 p = __floats2half2_rn(a, b);
    return *(uint32_t*)&p;
}

// ---------------------------------------------------------------------------
// Weight conversion: fp32 -> fp16 (single weight)
// ---------------------------------------------------------------------------
__global__ void cvt_w(const float* __restrict__ x, __half* __restrict__ hi,
                      int n4) {
    int i = blockIdx.x * blockDim.x + threadIdx.x;
    if (i >= n4) return;
    float4 v = *(const float4*)(x + 4 * (size_t)i);
    __half2 p0 = __floats2half2_rn(v.x, v.y);
    __half2 p1 = __floats2half2_rn(v.z, v.w);
    *(__half2*)(hi + 4 * (size_t)i)     = p0;
    *(__half2*)(hi + 4 * (size_t)i + 2) = p1;
}

// Combined conversion of proj_w + fc1_w + fc2_w in one launch.
// Sizes (fp32 elems): wp 256K, w1 1M, w2 1M -> 2.25M elems = 576K float4.
#define WP_N4 ((CC * CC) / 4)         // 65536
#define W1_N4 ((HID * CC) / 4)        // 262144
#define W2_N4 ((CC * HID) / 4)        // 262144
#define CVT3_TOTAL (WP_N4 + W1_N4 + W2_N4)

__global__ void cvt3_w(const float* __restrict__ wp_f,
                       const float* __restrict__ w1_f,
                       const float* __restrict__ w2_f,
                       __half* __restrict__ wp_h,
                       __half* __restrict__ w1_h,
                       __half* __restrict__ w2_h) {
    int i = blockIdx.x * blockDim.x + threadIdx.x;
    if (i >= CVT3_TOTAL) return;
    const float* src;
    __half* dst;
    int idx;
    if (i < WP_N4) {
        src = wp_f; dst = wp_h; idx = i;
    } else if (i < WP_N4 + W1_N4) {
        src = w1_f; dst = w1_h; idx = i - WP_N4;
    } else {
        src = w2_f; dst = w2_h; idx = i - WP_N4 - W1_N4;
    }
    float4 v = *(const float4*)(src + 4 * (size_t)idx);
    __half2 p0 = __floats2half2_rn(v.x, v.y);
    __half2 p1 = __floats2half2_rn(v.z, v.w);
    *(__half2*)(dst + 4 * (size_t)idx)     = p0;
    *(__half2*)(dst + 4 * (size_t)idx + 2) = p1;
}

// ---------------------------------------------------------------------------
// LayerNorm -> fp16
// ---------------------------------------------------------------------------
__global__ void ln_kernel(const float* __restrict__ x,
                          const float* __restrict__ w,
                          const float* __restrict__ b,
                          __half* __restrict__ ohi) {
    const int row = blockIdx.x;
    const float* xr = x + (size_t)row * CC;
    const int t = threadIdx.x;

    float v0 = xr[t];
    float v1 = xr[t + 256];

    __shared__ float red1[8];
    __shared__ float red2[8];

    float s = v0 + v1;
    #pragma unroll
    for (int o = 16; o > 0; o >>= 1) s += __shfl_xor_sync(0xffffffffu, s, o);
    if ((t & 31) == 0) red1[t >> 5] = s;
    __syncthreads();
    float tot = 0.f;
    #pragma unroll
    for (int i = 0; i < 8; i++) tot += red1[i];
    const float mean = tot * (1.0f / CC);

    float d0 = v0 - mean, d1 = v1 - mean;
    float s2 = d0 * d0 + d1 * d1;
    #pragma unroll
    for (int o = 16; o > 0; o >>= 1) s2 += __shfl_xor_sync(0xffffffffu, s2, o);
    if ((t & 31) == 0) red2[t >> 5] = s2;
    __syncthreads();
    float tot2 = 0.f;
    #pragma unroll
    for (int i = 0; i < 8; i++) tot2 += red2[i];
    const float inv = rsqrtf(tot2 * (1.0f / CC) + 1e-5f);

    float y0 = d0 * inv * w[t]       + b[t];
    float y1 = d1 * inv * w[t + 256] + b[t + 256];

    ohi[(size_t)row * CC + t]       = __float2half_rn(y0);
    ohi[(size_t)row * CC + t + 256] = __float2half_rn(y1);
}

// ---------------------------------------------------------------------------
// mma.sync 1-pass fp16 NT GEMM:  C[M,Nn] = A[M,K] * W[Nn,K]^T
// CTA tile 128x128, BK=64, 8 warps (warp tile 64x32).
// 3-stage cp.async pipeline, ONE __syncthreads per k-iteration.
//   EPI 1: fp32 out = acc + bias[n] + res[m,n]
//   EPI 2: fp16 out = gelu(acc + bias[n])
//   EPI 3: fp16 out
// SMEM stage: [A 16K][B 16K], rows of 128B, SW128. 32K/stage, 3 stages.
// ---------------------------------------------------------------------------
#define GEMM_STAGE 32768
#define GEMM_SMEM_BYTES (3 * GEMM_STAGE)

__device__ __forceinline__ void load_chunk(
    const __half* __restrict__ A, const __half* __restrict__ B,
    int K, int m0, int n0, int kc, uint32_t sbuf, int tid) {
    #pragma unroll
    for (int j = 0; j < 8; j++) {
        const int linear = j * 256 + tid;
        const int arr = j >> 2;          // 0:A 1:B (compile-time)
        const int within = linear & 1023;
        const int r = within >> 3;
        const int c = within & 7;
        uint32_t sw = sw128((uint32_t)(r * 128 + c * 16));
        if (arr == 0) {
            CP16(sbuf + sw,
                 (const char*)(A + (size_t)(m0 + r) * K + (size_t)kc * 64 + c * 8));
        } else {
            CP16(sbuf + 16384 + sw,
                 (const char*)(B + (size_t)(n0 + r) * K + (size_t)kc * 64 + c * 8));
        }
    }
}

template <int EPI>
__global__ __launch_bounds__(256, 2)
void gemm_tc(const __half* __restrict__ A,
             const __half* __restrict__ B,
             const float* __restrict__ bias,
             const float* __restrict__ res,
             float* __restrict__ outF,
             __half* __restrict__ outH,
             int M, int Nn, int K) {
    extern __shared__ char dsm[];
    const uint32_t bufs = smem_u32(dsm);

    const int tid  = threadIdx.x;
    const int wid  = tid >> 5;
    const int lane = tid & 31;

    const int m0 = blockIdx.y * 128;
    const int n0 = blockIdx.x * 128;
    const int NK = K >> 6;

    const int warp_m = (wid & 1) * 64;
    const int warp_n = (wid >> 1) * 32;

    const int lrow = lane & 7;
    const int sel  = lane >> 3;
    const int rofs = lrow + ((sel & 1) ? 8 : 0);
    const int kofs = (sel & 2) ? 8 : 0;

    float d[4][4][4] = {};

    // Prologue: stages 0 and 1
    load_chunk(A, B, K, m0, n0, 0, bufs, tid);
    CP_COMMIT();
    load_chunk(A, B, K, m0, n0, 1, bufs + GEMM_STAGE, tid);
    CP_COMMIT();

    for (int kc = 0; kc < NK; kc++) {
        const uint32_t bufc = bufs + (kc % 3) * GEMM_STAGE;
        if (kc + 1 < NK) { CP_WAIT1(); } else { CP_WAIT0(); }
        __syncthreads();

        const uint32_t aS = bufc;
        const uint32_t bS = bufc + 16384;

        #pragma unroll
        for (int ks = 0; ks < 4; ks++) {
            const int kk = ks * 16 + kofs;
            uint32_t af[4][4], bf[2][4];
            #pragma unroll
            for (int mi = 0; mi < 4; mi++) {
                uint32_t off = sw128((uint32_t)((warp_m + 16 * mi + rofs) * 128 + kk * 2));
                ldsm4(af[mi], aS + off);
            }
            #pragma unroll
            for (int nj = 0; nj < 2; nj++) {
                uint32_t off = sw128((uint32_t)((warp_n + 16 * nj + rofs) * 128 + kk * 2));
                ldsm4(bf[nj], bS + off);
            }
            #pragma unroll
            for (int mi = 0; mi < 4; mi++) {
                #pragma unroll
                for (int nt = 0; nt < 4; nt++) {
                    const int nj = nt >> 1;
                    const int p  = nt & 1;
                    mma16816(d[mi][nt], af[mi], bf[nj][p], bf[nj][p + 2]);
                }
            }
        }

        if (kc + 2 < NK) {
            load_chunk(A, B, K, m0, n0, kc + 2,
                       bufs + ((kc + 2) % 3) * GEMM_STAGE, tid);
            CP_COMMIT();
        }
    }

    const int erow0 = m0 + warp_m + (lane >> 2);
    const int ecol0 = n0 + warp_n + (lane & 3) * 2;

    #pragma unroll
    for (int mi = 0; mi < 4; mi++) {
        #pragma unroll
        for (int nt = 0; nt < 4; nt++) {
            const int col = ecol0 + nt * 8;
            #pragma unroll
            for (int half = 0; half < 2; half++) {
                const int row = erow0 + mi * 16 + half * 8;
                float v0 = d[mi][nt][2 * half + 0];
                float v1 = d[mi][nt][2 * half + 1];
                const size_t ob = (size_t)row * Nn + col;
                if (EPI == 1) {
                    float2 rv = *(const float2*)(res + ob);
                    v0 += bias[col]     + rv.x;
                    v1 += bias[col + 1] + rv.y;
                    *(float2*)(outF + ob) = make_float2(v0, v1);
                } else if (EPI == 2) {
                    v0 += bias[col];
                    v1 += bias[col + 1];
                    float g0 = v0 * normcdff(v0);
                    float g1 = v1 * normcdff(v1);
                    *(__half2*)(outH + ob) = __floats2half2_rn(g0, g1);
                } else {
                    *(__half2*)(outH + ob) = __floats2half2_rn(v0, v1);
                }
            }
        }
    }
}

// ---------------------------------------------------------------------------
// Tensor-core flash attention, 1-pass fp16, 3-stage pipeline, occupancy 2.
// grid = (NN/128, BB*HH); block 256 (8 warps x 16 q-rows).
// SMEM: Q [128x64] (16K) + 3 stages of (K,V)[64x64] (16K each) + 3 bias (1K).
// ---------------------------------------------------------------------------
#define AT_Q      0
#define AT_STAGE  16384          // + s*16384 : K (8K), V (8K)
#define AT_BIAS   (16384 + 3 * 16384)   // + s*1024 : 192 floats
#define AT_SMEM_BYTES (AT_BIAS + 3 * 1024)

__device__ __forceinline__ void attn_prefetch(
    const __half* __restrict__ qv, const float* __restrict__ rpb,
    int b, int h, int q0, int k0, uint32_t sbase, int s, int tid) {
    const uint32_t stage = sbase + AT_STAGE + s * 16384;
    #pragma unroll
    for (int j = 0; j < 4; j++) {
        int linear = tid + j * 256;
        int arr = linear >> 9;            // 0:K 1:V
        int within = linear & 511;
        int row = within >> 3;
        int c = within & 7;
        uint32_t dst = stage + arr * 8192 + sw128((uint32_t)(row * 128 + c * 16));
        int colbase = arr ? (2 * CC) : CC;
        CP16(dst, (const char*)(qv + (size_t)(b * NN + k0 + row) * C3
                                + colbase + h * DH + c * 8));
    }
    if (tid < 192) {
        int idx = k0 - q0 + 1920 + tid;
        if (tid >= 191) idx = k0 - q0 + 1920;
        CP4(sbase + AT_BIAS + s * 1024 + tid * 4, rpb + (size_t)idx * HH + h);
    }
}

__global__ __launch_bounds__(256, 2)
void attn_tc(const __half* __restrict__ qv,
             const float* __restrict__ rpb,
             __half* __restrict__ outH) {
    extern __shared__ char dsm[];
    const uint32_t sbase = smem_u32(dsm);

    const int q0 = blockIdx.x * 128;
    const int bh = blockIdx.y;
    const int b = bh >> 3;
    const int h = bh & 7;

    const int tid  = threadIdx.x;
    const int wid  = tid >> 5;
    const int lane = tid & 31;

    const int lrow = lane & 7;
    const int sel  = lane >> 3;
    const int rofs = lrow + ((sel & 1) ? 8 : 0);
    const int kofs = (sel & 2) ? 8 : 0;

    // --- load Q tile (group 0, together with chunk-0 prefetch) ---
    #pragma unroll
    for (int j = 0; j < 4; j++) {
        int linear = tid + j * 256;
        int row = linear >> 3;
        int c = linear & 7;
        uint32_t dst = sbase + AT_Q + sw128((uint32_t)(row * 128 + c * 16));
        CP16(dst, (const char*)(qv + (size_t)(b * NN + q0 + row) * C3
                                + h * DH + c * 8));
    }
    attn_prefetch(qv, rpb, b, h, q0, 0, sbase, 0, tid);
    CP_COMMIT();
    attn_prefetch(qv, rpb, b, h, q0, 64, sbase, 1, tid);
    CP_COMMIT();

    uint32_t qf[4][4];
    float oacc[8][4] = {};
    float m0 = -CUDART_INF_F, m1 = -CUDART_INF_F;
    float l0 = 0.f, l1 = 0.f;

    const int NCHUNK = NN / 64;
    for (int c = 0; c < NCHUNK; c++) {
        const int s = c % 3;
        const uint32_t stage = sbase + AT_STAGE + s * 16384;
        const uint32_t bstage = sbase + AT_BIAS + s * 1024;
        if (c + 1 < NCHUNK) { CP_WAIT1(); } else { CP_WAIT0(); }
        __syncthreads();

        if (c == 0) {
            #pragma unroll
            for (int kc = 0; kc < 4; kc++) {
                uint32_t off = sw128((uint32_t)((wid * 16 + rofs) * 128
                                                + (kc * 16 + kofs) * 2));
                ldsm4(qf[kc], sbase + AT_Q + off);
            }
        }

        // ---- S = Q K^T ----
        float sacc[8][4] = {};
        #pragma unroll
        for (int kc = 0; kc < 4; kc++) {
            #pragma unroll
            for (int npair = 0; npair < 4; npair++) {
                uint32_t off = sw128((uint32_t)((npair * 16 + rofs) * 128
                                                + (kc * 16 + kofs) * 2));
                uint32_t kf[4];
                ldsm4(kf, stage + off);
                #pragma unroll
                for (int p = 0; p < 2; p++) {
                    mma16816(sacc[npair * 2 + p], qf[kc], kf[p], kf[p + 2]);
                }
            }
        }

        // ---- bias + online softmax ----
        const int r0 = wid * 16 + (lane >> 2);
        const int cb = (lane & 3) * 2;
        float mx0 = -CUDART_INF_F, mx1 = -CUDART_INF_F;
        #pragma unroll
        for (int nt = 0; nt < 8; nt++) {
            const int kk = nt * 8 + cb;
            float bv0, bv1, bv2, bv3;
            asm volatile("ld.shared.f32 %0, [%1];" : "=f"(bv0)
                         : "r"(bstage + (kk - r0 + 127) * 4));
            asm volatile("ld.shared.f32 %0, [%1];" : "=f"(bv1)
                         : "r"(bstage + (kk + 1 - r0 + 127) * 4));
            asm volatile("ld.shared.f32 %0, [%1];" : "=f"(bv2)
                         : "r"(bstage + (kk - (r0 + 8) + 127) * 4));
            asm volatile("ld.shared.f32 %0, [%1];" : "=f"(bv3)
                         : "r"(bstage + (kk + 1 - (r0 + 8) + 127) * 4));
            sacc[nt][0] = fmaf(sacc[nt][0], 0.125f, bv0);
            sacc[nt][1] = fmaf(sacc[nt][1], 0.125f, bv1);
            sacc[nt][2] = fmaf(sacc[nt][2], 0.125f, bv2);
            sacc[nt][3] = fmaf(sacc[nt][3], 0.125f, bv3);
            mx0 = fmaxf(mx0, fmaxf(sacc[nt][0], sacc[nt][1]));
            mx1 = fmaxf(mx1, fmaxf(sacc[nt][2], sacc[nt][3]));
        }
        mx0 = fmaxf(mx0, __shfl_xor_sync(0xffffffffu, mx0, 1));
        mx0 = fmaxf(mx0, __shfl_xor_sync(0xffffffffu, mx0, 2));
        mx1 = fmaxf(mx1, __shfl_xor_sync(0xffffffffu, mx1, 1));
        mx1 = fmaxf(mx1, __shfl_xor_sync(0xffffffffu, mx1, 2));
        const float mn0 = fmaxf(m0, mx0);
        const float mn1 = fmaxf(m1, mx1);
        const float fac0 = __expf(m0 - mn0);
        const float fac1 = __expf(m1 - mn1);
        float sum0 = 0.f, sum1 = 0.f;
        #pragma unroll
        for (int nt = 0; nt < 8; nt++) {
            sacc[nt][0] = __expf(sacc[nt][0] - mn0);
            sacc[nt][1] = __expf(sacc[nt][1] - mn0);
            sacc[nt][2] = __expf(sacc[nt][2] - mn1);
            sacc[nt][3] = __expf(sacc[nt][3] - mn1);
            sum0 += sacc[nt][0] + sacc[nt][1];
            sum1 += sacc[nt][2] + sacc[nt][3];
        }
        sum0 += __shfl_xor_sync(0xffffffffu, sum0, 1);
        sum0 += __shfl_xor_sync(0xffffffffu, sum0, 2);
        sum1 += __shfl_xor_sync(0xffffffffu, sum1, 1);
        sum1 += __shfl_xor_sync(0xffffffffu, sum1, 2);
        l0 = l0 * fac0 + sum0;
        l1 = l1 * fac1 + sum1;
        m0 = mn0;
        m1 = mn1;
        #pragma unroll
        for (int nt = 0; nt < 8; nt++) {
            oacc[nt][0] *= fac0;
            oacc[nt][1] *= fac0;
            oacc[nt][2] *= fac1;
            oacc[nt][3] *= fac1;
        }

        // ---- O += P V, P fragments built in registers ----
        #pragma unroll
        for (int kc = 0; kc < 4; kc++) {
            uint32_t pA[4];
            #pragma unroll
            for (int g = 0; g < 2; g++) {
                const float* sv = sacc[2 * kc + g];
                pA[2 * g + 0] = pack_h2(sv[0], sv[1]);
                pA[2 * g + 1] = pack_h2(sv[2], sv[3]);
            }
            #pragma unroll
            for (int dp = 0; dp < 4; dp++) {
                const int g = lane >> 3;
                const int rr = lane & 7;
                uint32_t off = sw128((uint32_t)((kc * 16 + (g & 1) * 8 + rr) * 128
                                                + dp * 32 + (g >> 1) * 16));
                uint32_t vf[4];
                ldsm4t(vf, stage + 8192 + off);
                #pragma unroll
                for (int p = 0; p < 2; p++) {
                    mma16816(oacc[dp * 2 + p], pA, vf[2 * p], vf[2 * p + 1]);
                }
            }
        }

        if (c + 2 < NCHUNK) {
            attn_prefetch(qv, rpb, b, h, q0, (c + 2) * 64, sbase, (c + 2) % 3, tid);
            CP_COMMIT();
        }
    }

    // ---- epilogue ----
    const float il0 = 1.0f / l0;
    const float il1 = 1.0f / l1;
    const int row0 = b * NN + q0 + wid * 16 + (lane >> 2);
    const int colb = h * DH + (lane & 3) * 2;
    #pragma unroll
    for (int nt = 0; nt < 8; nt++) {
        const int col = colb + nt * 8;
        *(__half2*)(outH + (size_t)row0 * CC + col) =
            __floats2half2_rn(oacc[nt][0] * il0, oacc[nt][1] * il0);
        *(__half2*)(outH + (size_t)(row0 + 8) * CC + col) =
            __floats2half2_rn(oacc[nt][2] * il1, oacc[nt][3] * il1);
    }
}

// ---------------------------------------------------------------------------
// Launcher — fork/join graph: weight converts overlap ln1/qkv/attention.
// ---------------------------------------------------------------------------
extern "C" void kernel_launch(void* const* d_in, const int* in_sizes, int n_in,
                              void* d_out, int out_size) {
    const float* x      = (const float*)d_in[0];
    const float* qkv_w  = (const float*)d_in[1];
    const float* proj_w = (const float*)d_in[2];
    const float* proj_b = (const float*)d_in[3];
    const float* rpb    = (const float*)d_in[4];
    const float* n1_w   = (const float*)d_in[5];
    const float* n1_b   = (const float*)d_in[6];
    const float* n2_w   = (const float*)d_in[7];
    const float* n2_b   = (const float*)d_in[8];
    const float* fc1_w  = (const float*)d_in[9];
    const float* fc1_b  = (const float*)d_in[10];
    const float* fc2_w  = (const float*)d_in[11];
    const float* fc2_b  = (const float*)d_in[12];
    float* out = (float*)d_out;

    float *x1;
    __half *qv, *h1, *at, *h2, *hd, *wq, *wp, *w1, *w2;
    cudaGetSymbolAddress((void**)&x1, g_x1);
    cudaGetSymbolAddress((void**)&qv, g_qv);
    cudaGetSymbolAddress((void**)&h1, g_h1);
    cudaGetSymbolAddress((void**)&at, g_at);
    cudaGetSymbolAddress((void**)&h2, g_h2);
    cudaGetSymbolAddress((void**)&hd, g_hd);
    cudaGetSymbolAddress((void**)&wq, g_wq);
    cudaGetSymbolAddress((void**)&wp, g_wp);
    cudaGetSymbolAddress((void**)&w1, g_w1);
    cudaGetSymbolAddress((void**)&w2, g_w2);

    cudaFuncSetAttribute(gemm_tc<1>, cudaFuncAttributeMaxDynamicSharedMemorySize, GEMM_SMEM_BYTES);
    cudaFuncSetAttribute(gemm_tc<2>, cudaFuncAttributeMaxDynamicSharedMemorySize, GEMM_SMEM_BYTES);
    cudaFuncSetAttribute(gemm_tc<3>, cudaFuncAttributeMaxDynamicSharedMemorySize, GEMM_SMEM_BYTES);
    cudaFuncSetAttribute(attn_tc, cudaFuncAttributeMaxDynamicSharedMemorySize, AT_SMEM_BYTES);

    // Side stream for weight conversion, forked/joined via events so the
    // whole thing is a branch in the captured graph.
    cudaStream_t side;
    cudaEvent_t e_fork, e_wq, e_rest;
    cudaStreamCreateWithFlags(&side, cudaStreamNonBlocking);
    cudaEventCreateWithFlags(&e_fork, cudaEventDisableTiming);
    cudaEventCreateWithFlags(&e_wq,   cudaEventDisableTiming);
    cudaEventCreateWithFlags(&e_rest, cudaEventDisableTiming);

    // Fork
    cudaEventRecord(e_fork, 0);
    cudaStreamWaitEvent(side, e_fork, 0);

    // Side: convert qkv_w first (needed soonest), then the rest in one launch.
    cvt_w<<<(C3 * CC) / 1024, 256, 0, side>>>(qkv_w, wq, (C3 * CC) / 4);
    cudaEventRecord(e_wq, side);
    cvt3_w<<<(CVT3_TOTAL + 255) / 256, 256, 0, side>>>(proj_w, fc1_w, fc2_w,
                                                       wp, w1, w2);
    cudaEventRecord(e_rest, side);

    // Main: ln1 overlaps the converts.
    ln_kernel<<<MROWS, 256>>>(x, n1_w, n1_b, h1);

    // qkv needs wq
    cudaStreamWaitEvent(0, e_wq, 0);
    gemm_tc<3><<<dim3(C3 / 128, MROWS / 128), 256, GEMM_SMEM_BYTES>>>(
        h1, wq, nullptr, nullptr, nullptr, qv, MROWS, C3, CC);

    // attention (cvt3 overlaps here)
    attn_tc<<<dim3(NN / 128, BB * HH), 256, AT_SMEM_BYTES>>>(qv, rpb, at);

    // proj needs wp (and the rest follow)
    cudaStreamWaitEvent(0, e_rest, 0);
    gemm_tc<1><<<dim3(CC / 128, MROWS / 128), 256, GEMM_SMEM_BYTES>>>(
        at, wp, proj_b, x, x1, nullptr, MROWS, CC, CC);
    ln_kernel<<<MROWS, 256>>>(x1, n2_w, n2_b, h2);
    gemm_tc<2><<<dim3(HID / 128, MROWS / 128), 256, GEMM_SMEM_BYTES>>>(
        h2, w1, fc1_b, nullptr, nullptr, hd, MROWS, HID, CC);
    gemm_tc<1><<<dim3(CC / 128, MROWS / 128), 256, GEMM_SMEM_BYTES>>>(
        hd, w2, fc2_b, x1, out, nullptr, MROWS, CC, HID);

    // Cleanup host-side handles (side stream is joined into the main stream's
    // dependency chain via e_rest; no pending work remains un-joined).
    cudaEventDestroy(e_fork);
    cudaEventDestroy(e_wq);
    cudaEventDestroy(e_rest);
    cudaStreamDestroy(side);
}

// round 9
// speedup vs baseline: 7.2177x; 1.0184x over previous
#include <cuda_runtime.h>
#include <cuda_fp16.h>
#include <math.h>
#include <math_constants.h>
#include <stdint.h>

// Problem constants
#define BB    4
#define NN    2048
#define CC    512
#define HH    8
#define DH    64
#define HID   2048
#define MROWS (BB * NN)   // 8192
#define C3    (3 * CC)    // 1536

// ---------------------------------------------------------------------------
// Device scratch
// ---------------------------------------------------------------------------
__device__ float g_x1 [MROWS * CC];     // fp32 residual after attention

__device__ __half g_qv[MROWS * C3];
__device__ __half g_h1[MROWS * CC];
__device__ __half g_at[MROWS * CC];
__device__ __half g_h2[MROWS * CC];
__device__ __half g_hd[MROWS * HID];

__device__ __half g_wq[C3 * CC];
__device__ __half g_wp[CC * CC];
__device__ __half g_w1[HID * CC];
__device__ __half g_w2[CC * HID];

// ---------------------------------------------------------------------------
// PTX helpers
// ---------------------------------------------------------------------------
__device__ __forceinline__ uint32_t smem_u32(const void* p) {
    uint32_t a;
    asm("{ .reg .u64 t; cvta.to.shared.u64 t, %1; cvt.u32.u64 %0, t; }"
        : "=r"(a) : "l"(p));
    return a;
}

#define CP16(dst, src)                                                        \
    asm volatile("cp.async.cg.shared.global [%0], [%1], 16;"                  \
                 :: "r"(dst), "l"(src))
#define CP4(dst, src)                                                         \
    asm volatile("cp.async.ca.shared.global [%0], [%1], 4;"                   \
                 :: "r"(dst), "l"(src))
#define CP_COMMIT() asm volatile("cp.async.commit_group;" ::: "memory")
#define CP_WAIT1()  asm volatile("cp.async.wait_group 1;" ::: "memory")
#define CP_WAIT0()  asm volatile("cp.async.wait_group 0;" ::: "memory")

__device__ __forceinline__ void ldsm4(uint32_t* r, uint32_t addr) {
    asm volatile("ldmatrix.sync.aligned.m8n8.x4.shared.b16 {%0,%1,%2,%3}, [%4];"
                 : "=r"(r[0]), "=r"(r[1]), "=r"(r[2]), "=r"(r[3]) : "r"(addr));
}

__device__ __forceinline__ void ldsm4t(uint32_t* r, uint32_t addr) {
    asm volatile("ldmatrix.sync.aligned.m8n8.x4.trans.shared.b16 {%0,%1,%2,%3}, [%4];"
                 : "=r"(r[0]), "=r"(r[1]), "=r"(r[2]), "=r"(r[3]) : "r"(addr));
}

__device__ __forceinline__ void mma16816(float* d, const uint32_t* a,
                                         uint32_t b0, uint32_t b1) {
    asm volatile(
        "mma.sync.aligned.m16n8k16.row.col.f32.f16.f16.f32 "
        "{%0,%1,%2,%3}, {%4,%5,%6,%7}, {%8,%9}, {%0,%1,%2,%3};"
        : "+f"(d[0]), "+f"(d[1]), "+f"(d[2]), "+f"(d[3])
        : "r"(a[0]), "r"(a[1]), "r"(a[2]), "r"(a[3]), "r"(b0), "r"(b1));
}

__device__ __forceinline__ uint32_t sw128(uint32_t off) {
    return off ^ ((off >> 3) & 0x70u);
}

__device__ __forceinline__ uint32_t pack_h2(float a, float b) {
    __half2 p = __floats2half2_rn(a, b);
    return *(uint32_t*)&p;
}

// ---------------------------------------------------------------------------
// Weight conversion: fp32 -> fp16 (single weight)
// ---------------------------------------------------------------------------
__global__ void cvt_w(const float* __restrict__ x, __half* __restrict__ hi,
                      int n4) {
    int i = blockIdx.x * blockDim.x + threadIdx.x;
    if (i >= n4) return;
    float4 v = *(const float4*)(x + 4 * (size_t)i);
    __half2 p0 = __floats2half2_rn(v.x, v.y);
    __half2 p1 = __floats2half2_rn(v.z, v.w);
    *(__half2*)(hi + 4 * (size_t)i)     = p0;
    *(__half2*)(hi + 4 * (size_t)i + 2) = p1;
}

// Combined conversion of proj_w + fc1_w + fc2_w in one launch.
#define WP_N4 ((CC * CC) / 4)         // 65536
#define W1_N4 ((HID * CC) / 4)        // 262144
#define W2_N4 ((CC * HID) / 4)        // 262144
#define CVT3_TOTAL (WP_N4 + W1_N4 + W2_N4)

__global__ void cvt3_w(const float* __restrict__ wp_f,
                       const float* __restrict__ w1_f,
                       const float* __restrict__ w2_f,
                       __half* __restrict__ wp_h,
                       __half* __restrict__ w1_h,
                       __half* __restrict__ w2_h) {
    int i = blockIdx.x * blockDim.x + threadIdx.x;
    if (i >= CVT3_TOTAL) return;
    const float* src;
    __half* dst;
    int idx;
    if (i < WP_N4) {
        src = wp_f; dst = wp_h; idx = i;
    } else if (i < WP_N4 + W1_N4) {
        src = w1_f; dst = w1_h; idx = i - WP_N4;
    } else {
        src = w2_f; dst = w2_h; idx = i - WP_N4 - W1_N4;
    }
    float4 v = *(const float4*)(src + 4 * (size_t)idx);
    __half2 p0 = __floats2half2_rn(v.x, v.y);
    __half2 p1 = __floats2half2_rn(v.z, v.w);
    *(__half2*)(dst + 4 * (size_t)idx)     = p0;
    *(__half2*)(dst + 4 * (size_t)idx + 2) = p1;
}

// ---------------------------------------------------------------------------
// LayerNorm -> fp16
// ---------------------------------------------------------------------------
__global__ void ln_kernel(const float* __restrict__ x,
                          const float* __restrict__ w,
                          const float* __restrict__ b,
                          __half* __restrict__ ohi) {
    const int row = blockIdx.x;
    const float* xr = x + (size_t)row * CC;
    const int t = threadIdx.x;

    float v0 = xr[t];
    float v1 = xr[t + 256];

    __shared__ float red1[8];
    __shared__ float red2[8];

    float s = v0 + v1;
    #pragma unroll
    for (int o = 16; o > 0; o >>= 1) s += __shfl_xor_sync(0xffffffffu, s, o);
    if ((t & 31) == 0) red1[t >> 5] = s;
    __syncthreads();
    float tot = 0.f;
    #pragma unroll
    for (int i = 0; i < 8; i++) tot += red1[i];
    const float mean = tot * (1.0f / CC);

    float d0 = v0 - mean, d1 = v1 - mean;
    float s2 = d0 * d0 + d1 * d1;
    #pragma unroll
    for (int o = 16; o > 0; o >>= 1) s2 += __shfl_xor_sync(0xffffffffu, s2, o);
    if ((t & 31) == 0) red2[t >> 5] = s2;
    __syncthreads();
    float tot2 = 0.f;
    #pragma unroll
    for (int i = 0; i < 8; i++) tot2 += red2[i];
    const float inv = rsqrtf(tot2 * (1.0f / CC) + 1e-5f);

    float y0 = d0 * inv * w[t]       + b[t];
    float y1 = d1 * inv * w[t + 256] + b[t + 256];

    ohi[(size_t)row * CC + t]       = __float2half_rn(y0);
    ohi[(size_t)row * CC + t + 256] = __float2half_rn(y1);
}

// ---------------------------------------------------------------------------
// mma.sync 1-pass fp16 NT GEMM with register-double-buffered fragments.
// CTA tile 128x128, BK=64, 8 warps (warp tile 64x32), 3-stage cp.async.
// ---------------------------------------------------------------------------
#define GEMM_STAGE 32768
#define GEMM_SMEM_BYTES (3 * GEMM_STAGE)

__device__ __forceinline__ void load_chunk(
    const __half* __restrict__ A, const __half* __restrict__ B,
    int K, int m0, int n0, int kc, uint32_t sbuf, int tid) {
    #pragma unroll
    for (int j = 0; j < 8; j++) {
        const int linear = j * 256 + tid;
        const int arr = j >> 2;
        const int within = linear & 1023;
        const int r = within >> 3;
        const int c = within & 7;
        uint32_t sw = sw128((uint32_t)(r * 128 + c * 16));
        if (arr == 0) {
            CP16(sbuf + sw,
                 (const char*)(A + (size_t)(m0 + r) * K + (size_t)kc * 64 + c * 8));
        } else {
            CP16(sbuf + 16384 + sw,
                 (const char*)(B + (size_t)(n0 + r) * K + (size_t)kc * 64 + c * 8));
        }
    }
}

#define G_LOAD(KS, AF, BF) do {                                               \
    const int kk_ = (KS) * 16 + kofs;                                         \
    _Pragma("unroll")                                                         \
    for (int mi_ = 0; mi_ < 4; mi_++) {                                       \
        uint32_t off_ = sw128((uint32_t)((warp_m + 16 * mi_ + rofs) * 128     \
                                         + kk_ * 2));                         \
        ldsm4((AF)[mi_], aS + off_);                                          \
    }                                                                         \
    _Pragma("unroll")                                                         \
    for (int nj_ = 0; nj_ < 2; nj_++) {                                       \
        uint32_t off_ = sw128((uint32_t)((warp_n + 16 * nj_ + rofs) * 128     \
                                         + kk_ * 2));                         \
        ldsm4((BF)[nj_], bS + off_);                                          \
    }                                                                         \
} while (0)

#define G_MMA(AF, BF) do {                                                    \
    _Pragma("unroll")                                                         \
    for (int mi_ = 0; mi_ < 4; mi_++) {                                       \
        _Pragma("unroll")                                                     \
        for (int nt_ = 0; nt_ < 4; nt_++) {                                   \
            const int nj_ = nt_ >> 1;                                         \
            const int p_  = nt_ & 1;                                          \
            mma16816(d[mi_][nt_], (AF)[mi_], (BF)[nj_][p_],                   \
                     (BF)[nj_][p_ + 2]);                                      \
        }                                                                     \
    }                                                                         \
} while (0)

template <int EPI>
__global__ __launch_bounds__(256, 2)
void gemm_tc(const __half* __restrict__ A,
             const __half* __restrict__ B,
             const float* __restrict__ bias,
             const float* __restrict__ res,
             float* __restrict__ outF,
             __half* __restrict__ outH,
             int M, int Nn, int K) {
    extern __shared__ char dsm[];
    const uint32_t bufs = smem_u32(dsm);

    const int tid  = threadIdx.x;
    const int wid  = tid >> 5;
    const int lane = tid & 31;

    const int m0 = blockIdx.y * 128;
    const int n0 = blockIdx.x * 128;
    const int NK = K >> 6;

    const int warp_m = (wid & 1) * 64;
    const int warp_n = (wid >> 1) * 32;

    const int lrow = lane & 7;
    const int sel  = lane >> 3;
    const int rofs = lrow + ((sel & 1) ? 8 : 0);
    const int kofs = (sel & 2) ? 8 : 0;

    float d[4][4][4] = {};

    load_chunk(A, B, K, m0, n0, 0, bufs, tid);
    CP_COMMIT();
    load_chunk(A, B, K, m0, n0, 1, bufs + GEMM_STAGE, tid);
    CP_COMMIT();

    for (int kc = 0; kc < NK; kc++) {
        const uint32_t bufc = bufs + (kc % 3) * GEMM_STAGE;
        if (kc + 1 < NK) { CP_WAIT1(); } else { CP_WAIT0(); }
        __syncthreads();

        const uint32_t aS = bufc;
        const uint32_t bS = bufc + 16384;

        // Register-double-buffered fragment pipeline over the 4 k-steps.
        uint32_t af0[4][4], bf0[2][4], af1[4][4], bf1[2][4];
        G_LOAD(0, af0, bf0);
        G_LOAD(1, af1, bf1);
        G_MMA(af0, bf0);
        G_LOAD(2, af0, bf0);
        G_MMA(af1, bf1);
        G_LOAD(3, af1, bf1);
        G_MMA(af0, bf0);
        G_MMA(af1, bf1);

        if (kc + 2 < NK) {
            load_chunk(A, B, K, m0, n0, kc + 2,
                       bufs + ((kc + 2) % 3) * GEMM_STAGE, tid);
            CP_COMMIT();
        }
    }

    const int erow0 = m0 + warp_m + (lane >> 2);
    const int ecol0 = n0 + warp_n + (lane & 3) * 2;

    #pragma unroll
    for (int mi = 0; mi < 4; mi++) {
        #pragma unroll
        for (int nt = 0; nt < 4; nt++) {
            const int col = ecol0 + nt * 8;
            #pragma unroll
            for (int half = 0; half < 2; half++) {
                const int row = erow0 + mi * 16 + half * 8;
                float v0 = d[mi][nt][2 * half + 0];
                float v1 = d[mi][nt][2 * half + 1];
                const size_t ob = (size_t)row * Nn + col;
                if (EPI == 1) {
                    float2 rv = *(const float2*)(res + ob);
                    v0 += bias[col]     + rv.x;
                    v1 += bias[col + 1] + rv.y;
                    *(float2*)(outF + ob) = make_float2(v0, v1);
                } else if (EPI == 2) {
                    v0 += bias[col];
                    v1 += bias[col + 1];
                    float g0 = v0 * normcdff(v0);
                    float g1 = v1 * normcdff(v1);
                    *(__half2*)(outH + ob) = __floats2half2_rn(g0, g1);
                } else {
                    *(__half2*)(outH + ob) = __floats2half2_rn(v0, v1);
                }
            }
        }
    }
}

// ---------------------------------------------------------------------------
// Tensor-core flash attention, 1-pass fp16, 3-stage pipeline, occupancy 2,
// register-double-buffered K/V fragments.
// ---------------------------------------------------------------------------
#define AT_Q      0
#define AT_STAGE  16384
#define AT_BIAS   (16384 + 3 * 16384)
#define AT_SMEM_BYTES (AT_BIAS + 3 * 1024)

__device__ __forceinline__ void attn_prefetch(
    const __half* __restrict__ qv, const float* __restrict__ rpb,
    int b, int h, int q0, int k0, uint32_t sbase, int s, int tid) {
    const uint32_t stage = sbase + AT_STAGE + s * 16384;
    #pragma unroll
    for (int j = 0; j < 4; j++) {
        int linear = tid + j * 256;
        int arr = linear >> 9;
        int within = linear & 511;
        int row = within >> 3;
        int c = within & 7;
        uint32_t dst = stage + arr * 8192 + sw128((uint32_t)(row * 128 + c * 16));
        int colbase = arr ? (2 * CC) : CC;
        CP16(dst, (const char*)(qv + (size_t)(b * NN + k0 + row) * C3
                                + colbase + h * DH + c * 8));
    }
    if (tid < 192) {
        int idx = k0 - q0 + 1920 + tid;
        if (tid >= 191) idx = k0 - q0 + 1920;
        CP4(sbase + AT_BIAS + s * 1024 + tid * 4, rpb + (size_t)idx * HH + h);
    }
}

__global__ __launch_bounds__(256, 2)
void attn_tc(const __half* __restrict__ qv,
             const float* __restrict__ rpb,
             __half* __restrict__ outH) {
    extern __shared__ char dsm[];
    const uint32_t sbase = smem_u32(dsm);

    const int q0 = blockIdx.x * 128;
    const int bh = blockIdx.y;
    const int b = bh >> 3;
    const int h = bh & 7;

    const int tid  = threadIdx.x;
    const int wid  = tid >> 5;
    const int lane = tid & 31;

    const int lrow = lane & 7;
    const int sel  = lane >> 3;
    const int rofs = lrow + ((sel & 1) ? 8 : 0);
    const int kofs = (sel & 2) ? 8 : 0;

    #pragma unroll
    for (int j = 0; j < 4; j++) {
        int linear = tid + j * 256;
        int row = linear >> 3;
        int c = linear & 7;
        uint32_t dst = sbase + AT_Q + sw128((uint32_t)(row * 128 + c * 16));
        CP16(dst, (const char*)(qv + (size_t)(b * NN + q0 + row) * C3
                                + h * DH + c * 8));
    }
    attn_prefetch(qv, rpb, b, h, q0, 0, sbase, 0, tid);
    CP_COMMIT();
    attn_prefetch(qv, rpb, b, h, q0, 64, sbase, 1, tid);
    CP_COMMIT();

    uint32_t qf[4][4];
    float oacc[8][4] = {};
    float m0 = -CUDART_INF_F, m1 = -CUDART_INF_F;
    float l0 = 0.f, l1 = 0.f;

    const int NCHUNK = NN / 64;
    for (int c = 0; c < NCHUNK; c++) {
        const int s = c % 3;
        const uint32_t stage = sbase + AT_STAGE + s * 16384;
        const uint32_t bstage = sbase + AT_BIAS + s * 1024;
        if (c + 1 < NCHUNK) { CP_WAIT1(); } else { CP_WAIT0(); }
        __syncthreads();

        if (c == 0) {
            #pragma unroll
            for (int kc = 0; kc < 4; kc++) {
                uint32_t off = sw128((uint32_t)((wid * 16 + rofs) * 128
                                                + (kc * 16 + kofs) * 2));
                ldsm4(qf[kc], sbase + AT_Q + off);
            }
        }

        // ---- S = Q K^T (K-frags double-buffered per kc) ----
        float sacc[8][4] = {};
        #pragma unroll
        for (int kc = 0; kc < 4; kc++) {
            const int kb = (kc * 16 + kofs) * 2;
            uint32_t kfA[4], kfB[4];
            ldsm4(kfA, stage + sw128((uint32_t)((0 * 16 + rofs) * 128 + kb)));
            ldsm4(kfB, stage + sw128((uint32_t)((1 * 16 + rofs) * 128 + kb)));
            mma16816(sacc[0], qf[kc], kfA[0], kfA[2]);
            mma16816(sacc[1], qf[kc], kfA[1], kfA[3]);
            ldsm4(kfA, stage + sw128((uint32_t)((2 * 16 + rofs) * 128 + kb)));
            mma16816(sacc[2], qf[kc], kfB[0], kfB[2]);
            mma16816(sacc[3], qf[kc], kfB[1], kfB[3]);
            ldsm4(kfB, stage + sw128((uint32_t)((3 * 16 + rofs) * 128 + kb)));
            mma16816(sacc[4], qf[kc], kfA[0], kfA[2]);
            mma16816(sacc[5], qf[kc], kfA[1], kfA[3]);
            mma16816(sacc[6], qf[kc], kfB[0], kfB[2]);
            mma16816(sacc[7], qf[kc], kfB[1], kfB[3]);
        }

        // ---- bias + online softmax ----
        const int r0 = wid * 16 + (lane >> 2);
        const int cb = (lane & 3) * 2;
        float mx0 = -CUDART_INF_F, mx1 = -CUDART_INF_F;
        #pragma unroll
        for (int nt = 0; nt < 8; nt++) {
            const int kk = nt * 8 + cb;
            float bv0, bv1, bv2, bv3;
            asm volatile("ld.shared.f32 %0, [%1];" : "=f"(bv0)
                         : "r"(bstage + (kk - r0 + 127) * 4));
            asm volatile("ld.shared.f32 %0, [%1];" : "=f"(bv1)
                         : "r"(bstage + (kk + 1 - r0 + 127) * 4));
            asm volatile("ld.shared.f32 %0, [%1];" : "=f"(bv2)
                         : "r"(bstage + (kk - (r0 + 8) + 127) * 4));
            asm volatile("ld.shared.f32 %0, [%1];" : "=f"(bv3)
                         : "r"(bstage + (kk + 1 - (r0 + 8) + 127) * 4));
            sacc[nt][0] = fmaf(sacc[nt][0], 0.125f, bv0);
            sacc[nt][1] = fmaf(sacc[nt][1], 0.125f, bv1);
            sacc[nt][2] = fmaf(sacc[nt][2], 0.125f, bv2);
            sacc[nt][3] = fmaf(sacc[nt][3], 0.125f, bv3);
            mx0 = fmaxf(mx0, fmaxf(sacc[nt][0], sacc[nt][1]));
            mx1 = fmaxf(mx1, fmaxf(sacc[nt][2], sacc[nt][3]));
        }
        mx0 = fmaxf(mx0, __shfl_xor_sync(0xffffffffu, mx0, 1));
        mx0 = fmaxf(mx0, __shfl_xor_sync(0xffffffffu, mx0, 2));
        mx1 = fmaxf(mx1, __shfl_xor_sync(0xffffffffu, mx1, 1));
        mx1 = fmaxf(mx1, __shfl_xor_sync(0xffffffffu, mx1, 2));
        const float mn0 = fmaxf(m0, mx0);
        const float mn1 = fmaxf(m1, mx1);
        const float fac0 = __expf(m0 - mn0);
        const float fac1 = __expf(m1 - mn1);
        float sum0 = 0.f, sum1 = 0.f;
        #pragma unroll
        for (int nt = 0; nt < 8; nt++) {
            sacc[nt][0] = __expf(sacc[nt][0] - mn0);
            sacc[nt][1] = __expf(sacc[nt][1] - mn0);
            sacc[nt][2] = __expf(sacc[nt][2] - mn1);
            sacc[nt][3] = __expf(sacc[nt][3] - mn1);
            sum0 += sacc[nt][0] + sacc[nt][1];
            sum1 += sacc[nt][2] + sacc[nt][3];
        }
        sum0 += __shfl_xor_sync(0xffffffffu, sum0, 1);
        sum0 += __shfl_xor_sync(0xffffffffu, sum0, 2);
        sum1 += __shfl_xor_sync(0xffffffffu, sum1, 1);
        sum1 += __shfl_xor_sync(0xffffffffu, sum1, 2);
        l0 = l0 * fac0 + sum0;
        l1 = l1 * fac1 + sum1;
        m0 = mn0;
        m1 = mn1;
        #pragma unroll
        for (int nt = 0; nt < 8; nt++) {
            oacc[nt][0] *= fac0;
            oacc[nt][1] *= fac0;
            oacc[nt][2] *= fac1;
            oacc[nt][3] *= fac1;
        }

        // ---- O += P V (V-frags double-buffered per kc) ----
        const int g = lane >> 3;
        const int rr = lane & 7;
        const uint32_t vbase = stage + 8192;
        #pragma unroll
        for (int kc = 0; kc < 4; kc++) {
            uint32_t pA[4];
            #pragma unroll
            for (int gg = 0; gg < 2; gg++) {
                const float* sv = sacc[2 * kc + gg];
                pA[2 * gg + 0] = pack_h2(sv[0], sv[1]);
                pA[2 * gg + 1] = pack_h2(sv[2], sv[3]);
            }
            const int vrow = (kc * 16 + (g & 1) * 8 + rr) * 128 + (g >> 1) * 16;
            uint32_t vfA[4], vfB[4];
            ldsm4t(vfA, vbase + sw128((uint32_t)(vrow + 0 * 32)));
            ldsm4t(vfB, vbase + sw128((uint32_t)(vrow + 1 * 32)));
            mma16816(oacc[0], pA, vfA[0], vfA[1]);
            mma16816(oacc[1], pA, vfA[2], vfA[3]);
            ldsm4t(vfA, vbase + sw128((uint32_t)(vrow + 2 * 32)));
            mma16816(oacc[2], pA, vfB[0], vfB[1]);
            mma16816(oacc[3], pA, vfB[2], vfB[3]);
            ldsm4t(vfB, vbase + sw128((uint32_t)(vrow + 3 * 32)));
            mma16816(oacc[4], pA, vfA[0], vfA[1]);
            mma16816(oacc[5], pA, vfA[2], vfA[3]);
            mma16816(oacc[6], pA, vfB[0], vfB[1]);
            mma16816(oacc[7], pA, vfB[2], vfB[3]);
        }

        if (c + 2 < NCHUNK) {
            attn_prefetch(qv, rpb, b, h, q0, (c + 2) * 64, sbase, (c + 2) % 3, tid);
            CP_COMMIT();
        }
    }

    // ---- epilogue ----
    const float il0 = 1.0f / l0;
    const float il1 = 1.0f / l1;
    const int row0 = b * NN + q0 + wid * 16 + (lane >> 2);
    const int colb = h * DH + (lane & 3) * 2;
    #pragma unroll
    for (int nt = 0; nt < 8; nt++) {
        const int col = colb + nt * 8;
        *(__half2*)(outH + (size_t)row0 * CC + col) =
            __floats2half2_rn(oacc[nt][0] * il0, oacc[nt][1] * il0);
        *(__half2*)(outH + (size_t)(row0 + 8) * CC + col) =
            __floats2half2_rn(oacc[nt][2] * il1, oacc[nt][3] * il1);
    }
}

// ---------------------------------------------------------------------------
// Launcher — fork/join graph: weight converts overlap ln1/qkv/attention.
// ---------------------------------------------------------------------------
extern "C" void kernel_launch(void* const* d_in, const int* in_sizes, int n_in,
                              void* d_out, int out_size) {
    const float* x      = (const float*)d_in[0];
    const float* qkv_w  = (const float*)d_in[1];
    const float* proj_w = (const float*)d_in[2];
    const float* proj_b = (const float*)d_in[3];
    const float* rpb    = (const float*)d_in[4];
    const float* n1_w   = (const float*)d_in[5];
    const float* n1_b   = (const float*)d_in[6];
    const float* n2_w   = (const float*)d_in[7];
    const float* n2_b   = (const float*)d_in[8];
    const float* fc1_w  = (const float*)d_in[9];
    const float* fc1_b  = (const float*)d_in[10];
    const float* fc2_w  = (const float*)d_in[11];
    const float* fc2_b  = (const float*)d_in[12];
    float* out = (float*)d_out;

    float *x1;
    __half *qv, *h1, *at, *h2, *hd, *wq, *wp, *w1, *w2;
    cudaGetSymbolAddress((void**)&x1, g_x1);
    cudaGetSymbolAddress((void**)&qv, g_qv);
    cudaGetSymbolAddress((void**)&h1, g_h1);
    cudaGetSymbolAddress((void**)&at, g_at);
    cudaGetSymbolAddress((void**)&h2, g_h2);
    cudaGetSymbolAddress((void**)&hd, g_hd);
    cudaGetSymbolAddress((void**)&wq, g_wq);
    cudaGetSymbolAddress((void**)&wp, g_wp);
    cudaGetSymbolAddress((void**)&w1, g_w1);
    cudaGetSymbolAddress((void**)&w2, g_w2);

    cudaFuncSetAttribute(gemm_tc<1>, cudaFuncAttributeMaxDynamicSharedMemorySize, GEMM_SMEM_BYTES);
    cudaFuncSetAttribute(gemm_tc<2>, cudaFuncAttributeMaxDynamicSharedMemorySize, GEMM_SMEM_BYTES);
    cudaFuncSetAttribute(gemm_tc<3>, cudaFuncAttributeMaxDynamicSharedMemorySize, GEMM_SMEM_BYTES);
    cudaFuncSetAttribute(attn_tc, cudaFuncAttributeMaxDynamicSharedMemorySize, AT_SMEM_BYTES);

    cudaStream_t side;
    cudaEvent_t e_fork, e_wq, e_rest;
    cudaStreamCreateWithFlags(&side, cudaStreamNonBlocking);
    cudaEventCreateWithFlags(&e_fork, cudaEventDisableTiming);
    cudaEventCreateWithFlags(&e_wq,   cudaEventDisableTiming);
    cudaEventCreateWithFlags(&e_rest, cudaEventDisableTiming);

    cudaEventRecord(e_fork, 0);
    cudaStreamWaitEvent(side, e_fork, 0);

    cvt_w<<<(C3 * CC) / 1024, 256, 0, side>>>(qkv_w, wq, (C3 * CC) / 4);
    cudaEventRecord(e_wq, side);
    cvt3_w<<<(CVT3_TOTAL + 255) / 256, 256, 0, side>>>(proj_w, fc1_w, fc2_w,
                                                       wp, w1, w2);
    cudaEventRecord(e_rest, side);

    ln_kernel<<<MROWS, 256>>>(x, n1_w, n1_b, h1);

    cudaStreamWaitEvent(0, e_wq, 0);
    gemm_tc<3><<<dim3(C3 / 128, MROWS / 128), 256, GEMM_SMEM_BYTES>>>(
        h1, wq, nullptr, nullptr, nullptr, qv, MROWS, C3, CC);

    attn_tc<<<dim3(NN / 128, BB * HH), 256, AT_SMEM_BYTES>>>(qv, rpb, at);

    cudaStreamWaitEvent(0, e_rest, 0);
    gemm_tc<1><<<dim3(CC / 128, MROWS / 128), 256, GEMM_SMEM_BYTES>>>(
        at, wp, proj_b, x, x1, nullptr, MROWS, CC, CC);
    ln_kernel<<<MROWS, 256>>>(x1, n2_w, n2_b, h2);
    gemm_tc<2><<<dim3(HID / 128, MROWS / 128), 256, GEMM_SMEM_BYTES>>>(
        h2, w1, fc1_b, nullptr, nullptr, hd, MROWS, HID, CC);
    gemm_tc<1><<<dim3(CC / 128, MROWS / 128), 256, GEMM_SMEM_BYTES>>>(
        hd, w2, fc2_b, x1, out, nullptr, MROWS, CC, HID);

    cudaEventDestroy(e_fork);
    cudaEventDestroy(e_wq);
    cudaEventDestroy(e_rest);
    cudaStreamDestroy(side);
}

// round 10
// speedup vs baseline: 7.5841x; 1.0508x over previous
#include <cuda_runtime.h>
#include <cuda_fp16.h>
#include <math.h>
#include <math_constants.h>
#include <stdint.h>

// Problem constants
#define BB    4
#define NN    2048
#define CC    512
#define HH    8
#define DH    64
#define HID   2048
#define MROWS (BB * NN)   // 8192
#define C3    (3 * CC)    // 1536

// ---------------------------------------------------------------------------
// Device scratch
// ---------------------------------------------------------------------------
__device__ float g_x1 [MROWS * CC];

__device__ __half g_qv[MROWS * C3];
__device__ __half g_h1[MROWS * CC];
__device__ __half g_at[MROWS * CC];
__device__ __half g_h2[MROWS * CC];
__device__ __half g_hd[MROWS * HID];

__device__ __half g_wq[C3 * CC];
__device__ __half g_wp[CC * CC];
__device__ __half g_w1[HID * CC];
__device__ __half g_w2[CC * HID];

// ---------------------------------------------------------------------------
// PTX helpers
// ---------------------------------------------------------------------------
__device__ __forceinline__ uint32_t smem_u32(const void* p) {
    uint32_t a;
    asm("{ .reg .u64 t; cvta.to.shared.u64 t, %1; cvt.u32.u64 %0, t; }"
        : "=r"(a) : "l"(p));
    return a;
}

#define CP16(dst, src)                                                        \
    asm volatile("cp.async.cg.shared.global [%0], [%1], 16;"                  \
                 :: "r"(dst), "l"(src))
#define CP4(dst, src)                                                         \
    asm volatile("cp.async.ca.shared.global [%0], [%1], 4;"                   \
                 :: "r"(dst), "l"(src))
#define CP_COMMIT() asm volatile("cp.async.commit_group;" ::: "memory")
#define CP_WAIT1()  asm volatile("cp.async.wait_group 1;" ::: "memory")
#define CP_WAIT0()  asm volatile("cp.async.wait_group 0;" ::: "memory")

__device__ __forceinline__ void ldsm4(uint32_t* r, uint32_t addr) {
    asm volatile("ldmatrix.sync.aligned.m8n8.x4.shared.b16 {%0,%1,%2,%3}, [%4];"
                 : "=r"(r[0]), "=r"(r[1]), "=r"(r[2]), "=r"(r[3]) : "r"(addr));
}

__device__ __forceinline__ void ldsm4t(uint32_t* r, uint32_t addr) {
    asm volatile("ldmatrix.sync.aligned.m8n8.x4.trans.shared.b16 {%0,%1,%2,%3}, [%4];"
                 : "=r"(r[0]), "=r"(r[1]), "=r"(r[2]), "=r"(r[3]) : "r"(addr));
}

__device__ __forceinline__ void mma16816(float* d, const uint32_t* a,
                                         uint32_t b0, uint32_t b1) {
    asm volatile(
        "mma.sync.aligned.m16n8k16.row.col.f32.f16.f16.f32 "
        "{%0,%1,%2,%3}, {%4,%5,%6,%7}, {%8,%9}, {%0,%1,%2,%3};"
        : "+f"(d[0]), "+f"(d[1]), "+f"(d[2]), "+f"(d[3])
        : "r"(a[0]), "r"(a[1]), "r"(a[2]), "r"(a[3]), "r"(b0), "r"(b1));
}

__device__ __forceinline__ uint32_t sw128(uint32_t off) {
    return off ^ ((off >> 3) & 0x70u);
}

__device__ __forceinline__ uint32_t pack_h2(float a, float b) {
    __half2 p = __floats2half2_rn(a, b);
    return *(uint32_t*)&p;
}

// ---------------------------------------------------------------------------
// Weight conversion
// ---------------------------------------------------------------------------
__global__ void cvt_w(const float* __restrict__ x, __half* __restrict__ hi,
                      int n4) {
    int i = blockIdx.x * blockDim.x + threadIdx.x;
    if (i >= n4) return;
    float4 v = *(const float4*)(x + 4 * (size_t)i);
    __half2 p0 = __floats2half2_rn(v.x, v.y);
    __half2 p1 = __floats2half2_rn(v.z, v.w);
    *(__half2*)(hi + 4 * (size_t)i)     = p0;
    *(__half2*)(hi + 4 * (size_t)i + 2) = p1;
}

#define WP_N4 ((CC * CC) / 4)
#define W1_N4 ((HID * CC) / 4)
#define W2_N4 ((CC * HID) / 4)
#define CVT3_TOTAL (WP_N4 + W1_N4 + W2_N4)

__global__ void cvt3_w(const float* __restrict__ wp_f,
                       const float* __restrict__ w1_f,
                       const float* __restrict__ w2_f,
                       __half* __restrict__ wp_h,
                       __half* __restrict__ w1_h,
                       __half* __restrict__ w2_h) {
    int i = blockIdx.x * blockDim.x + threadIdx.x;
    if (i >= CVT3_TOTAL) return;
    const float* src;
    __half* dst;
    int idx;
    if (i < WP_N4) {
        src = wp_f; dst = wp_h; idx = i;
    } else if (i < WP_N4 + W1_N4) {
        src = w1_f; dst = w1_h; idx = i - WP_N4;
    } else {
        src = w2_f; dst = w2_h; idx = i - WP_N4 - W1_N4;
    }
    float4 v = *(const float4*)(src + 4 * (size_t)idx);
    __half2 p0 = __floats2half2_rn(v.x, v.y);
    __half2 p1 = __floats2half2_rn(v.z, v.w);
    *(__half2*)(dst + 4 * (size_t)idx)     = p0;
    *(__half2*)(dst + 4 * (size_t)idx + 2) = p1;
}

// ---------------------------------------------------------------------------
// LayerNorm -> fp16.  One warp per row, float4 loads, shuffle-only reduction.
// block = 256 (8 warps = 8 rows), grid = MROWS/8.
// ---------------------------------------------------------------------------
__global__ void ln_kernel(const float* __restrict__ x,
                          const float* __restrict__ w,
                          const float* __restrict__ b,
                          __half* __restrict__ ohi) {
    const int warp = threadIdx.x >> 5;
    const int lane = threadIdx.x & 31;
    const int row  = blockIdx.x * 8 + warp;
    const float* xr = x + (size_t)row * CC;

    float4 v[4];
    #pragma unroll
    for (int k = 0; k < 4; k++)
        v[k] = *(const float4*)(xr + (k * 32 + lane) * 4);

    float s = 0.f;
    #pragma unroll
    for (int k = 0; k < 4; k++) s += v[k].x + v[k].y + v[k].z + v[k].w;
    #pragma unroll
    for (int o = 16; o > 0; o >>= 1) s += __shfl_xor_sync(0xffffffffu, s, o);
    const float mean = s * (1.0f / CC);

    float s2 = 0.f;
    #pragma unroll
    for (int k = 0; k < 4; k++) {
        float d0 = v[k].x - mean, d1 = v[k].y - mean;
        float d2 = v[k].z - mean, d3 = v[k].w - mean;
        s2 += d0 * d0 + d1 * d1 + d2 * d2 + d3 * d3;
    }
    #pragma unroll
    for (int o = 16; o > 0; o >>= 1) s2 += __shfl_xor_sync(0xffffffffu, s2, o);
    const float inv = rsqrtf(s2 * (1.0f / CC) + 1e-5f);

    #pragma unroll
    for (int k = 0; k < 4; k++) {
        const int col = (k * 32 + lane) * 4;
        float4 wv = *(const float4*)(w + col);
        float4 bv = *(const float4*)(b + col);
        float y0 = (v[k].x - mean) * inv * wv.x + bv.x;
        float y1 = (v[k].y - mean) * inv * wv.y + bv.y;
        float y2 = (v[k].z - mean) * inv * wv.z + bv.z;
        float y3 = (v[k].w - mean) * inv * wv.w + bv.w;
        uint2 o;
        o.x = pack_h2(y0, y1);
        o.y = pack_h2(y2, y3);
        *(uint2*)(ohi + (size_t)row * CC + col) = o;
    }
}

// ---------------------------------------------------------------------------
// mma.sync 1-pass fp16 NT GEMM, precomputed swizzle addressing.
// CTA tile 128x128, BK=64, 8 warps (warp tile 64x32), 3-stage cp.async.
// ---------------------------------------------------------------------------
#define GEMM_STAGE 32768
#define GEMM_SMEM_BYTES (3 * GEMM_STAGE)

__device__ __forceinline__ void load_chunk(
    const __half* __restrict__ A, const __half* __restrict__ B,
    int K, int m0, int n0, int kc, uint32_t sbuf, int tid) {
    #pragma unroll
    for (int j = 0; j < 8; j++) {
        const int linear = j * 256 + tid;
        const int arr = j >> 2;
        const int within = linear & 1023;
        const int r = within >> 3;
        const int c = within & 7;
        uint32_t sw = sw128((uint32_t)(r * 128 + c * 16));
        if (arr == 0) {
            CP16(sbuf + sw,
                 (const char*)(A + (size_t)(m0 + r) * K + (size_t)kc * 64 + c * 8));
        } else {
            CP16(sbuf + 16384 + sw,
                 (const char*)(B + (size_t)(n0 + r) * K + (size_t)kc * 64 + c * 8));
        }
    }
}

#define G_LOAD(KS, AF, BF) do {                                               \
    _Pragma("unroll")                                                         \
    for (int mi_ = 0; mi_ < 4; mi_++)                                         \
        ldsm4((AF)[mi_], aS + aoff[mi_] + ccol[KS]);                          \
    _Pragma("unroll")                                                         \
    for (int nj_ = 0; nj_ < 2; nj_++)                                         \
        ldsm4((BF)[nj_], bS + boff[nj_] + ccol[KS]);                          \
} while (0)

#define G_MMA(AF, BF) do {                                                    \
    _Pragma("unroll")                                                         \
    for (int mi_ = 0; mi_ < 4; mi_++) {                                       \
        _Pragma("unroll")                                                     \
        for (int nt_ = 0; nt_ < 4; nt_++) {                                   \
            const int nj_ = nt_ >> 1;                                         \
            const int p_  = nt_ & 1;                                          \
            mma16816(d[mi_][nt_], (AF)[mi_], (BF)[nj_][p_],                   \
                     (BF)[nj_][p_ + 2]);                                      \
        }                                                                     \
    }                                                                         \
} while (0)

template <int EPI>
__global__ __launch_bounds__(256, 2)
void gemm_tc(const __half* __restrict__ A,
             const __half* __restrict__ B,
             const float* __restrict__ bias,
             const float* __restrict__ res,
             float* __restrict__ outF,
             __half* __restrict__ outH,
             int M, int Nn, int K) {
    extern __shared__ char dsm[];
    const uint32_t bufs = smem_u32(dsm);

    const int tid  = threadIdx.x;
    const int wid  = tid >> 5;
    const int lane = tid & 31;

    const int m0 = blockIdx.y * 128;
    const int n0 = blockIdx.x * 128;
    const int NK = K >> 6;

    const int warp_m = (wid & 1) * 64;
    const int warp_n = (wid >> 1) * 32;

    const int lrow = lane & 7;
    const int sel  = lane >> 3;
    const int rofs = lrow + ((sel & 1) ? 8 : 0);
    const int kofs = (sel & 2) ? 8 : 0;

    // Precomputed swizzle addressing: sw128(r*128+c) = r*128 + (c ^ (lrow<<4))
    const uint32_t rxor = (uint32_t)lrow << 4;
    uint32_t aoff[4], boff[2], ccol[4];
    #pragma unroll
    for (int mi = 0; mi < 4; mi++)
        aoff[mi] = (uint32_t)((warp_m + 16 * mi + rofs) * 128);
    #pragma unroll
    for (int nj = 0; nj < 2; nj++)
        boff[nj] = (uint32_t)((warp_n + 16 * nj + rofs) * 128);
    #pragma unroll
    for (int ks = 0; ks < 4; ks++)
        ccol[ks] = ((uint32_t)((ks * 16 + kofs) * 2)) ^ rxor;

    float d[4][4][4] = {};

    load_chunk(A, B, K, m0, n0, 0, bufs, tid);
    CP_COMMIT();
    load_chunk(A, B, K, m0, n0, 1, bufs + GEMM_STAGE, tid);
    CP_COMMIT();

    for (int kc = 0; kc < NK; kc++) {
        const uint32_t bufc = bufs + (kc % 3) * GEMM_STAGE;
        if (kc + 1 < NK) { CP_WAIT1(); } else { CP_WAIT0(); }
        __syncthreads();

        const uint32_t aS = bufc;
        const uint32_t bS = bufc + 16384;

        uint32_t af0[4][4], bf0[2][4], af1[4][4], bf1[2][4];
        G_LOAD(0, af0, bf0);
        G_LOAD(1, af1, bf1);
        G_MMA(af0, bf0);
        G_LOAD(2, af0, bf0);
        G_MMA(af1, bf1);
        G_LOAD(3, af1, bf1);
        G_MMA(af0, bf0);
        G_MMA(af1, bf1);

        if (kc + 2 < NK) {
            load_chunk(A, B, K, m0, n0, kc + 2,
                       bufs + ((kc + 2) % 3) * GEMM_STAGE, tid);
            CP_COMMIT();
        }
    }

    const int erow0 = m0 + warp_m + (lane >> 2);
    const int ecol0 = n0 + warp_n + (lane & 3) * 2;

    #pragma unroll
    for (int mi = 0; mi < 4; mi++) {
        #pragma unroll
        for (int nt = 0; nt < 4; nt++) {
            const int col = ecol0 + nt * 8;
            #pragma unroll
            for (int half = 0; half < 2; half++) {
                const int row = erow0 + mi * 16 + half * 8;
                float v0 = d[mi][nt][2 * half + 0];
                float v1 = d[mi][nt][2 * half + 1];
                const size_t ob = (size_t)row * Nn + col;
                if (EPI == 1) {
                    float2 rv = *(const float2*)(res + ob);
                    v0 += bias[col]     + rv.x;
                    v1 += bias[col + 1] + rv.y;
                    *(float2*)(outF + ob) = make_float2(v0, v1);
                } else if (EPI == 2) {
                    v0 += bias[col];
                    v1 += bias[col + 1];
                    float g0 = v0 * normcdff(v0);
                    float g1 = v1 * normcdff(v1);
                    *(__half2*)(outH + ob) = __floats2half2_rn(g0, g1);
                } else {
                    *(__half2*)(outH + ob) = __floats2half2_rn(v0, v1);
                }
            }
        }
    }
}

// ---------------------------------------------------------------------------
// Tensor-core flash attention, precomputed swizzle addressing.
// ---------------------------------------------------------------------------
#define AT_Q      0
#define AT_STAGE  16384
#define AT_BIAS   (16384 + 3 * 16384)
#define AT_SMEM_BYTES (AT_BIAS + 3 * 1024)

__device__ __forceinline__ void attn_prefetch(
    const __half* __restrict__ qv, const float* __restrict__ rpb,
    int b, int h, int q0, int k0, uint32_t sbase, int s, int tid) {
    const uint32_t stage = sbase + AT_STAGE + s * 16384;
    #pragma unroll
    for (int j = 0; j < 4; j++) {
        int linear = tid + j * 256;
        int arr = linear >> 9;
        int within = linear & 511;
        int row = within >> 3;
        int c = within & 7;
        uint32_t dst = stage + arr * 8192 + sw128((uint32_t)(row * 128 + c * 16));
        int colbase = arr ? (2 * CC) : CC;
        CP16(dst, (const char*)(qv + (size_t)(b * NN + k0 + row) * C3
                                + colbase + h * DH + c * 8));
    }
    if (tid < 192) {
        int idx = k0 - q0 + 1920 + tid;
        if (tid >= 191) idx = k0 - q0 + 1920;
        CP4(sbase + AT_BIAS + s * 1024 + tid * 4, rpb + (size_t)idx * HH + h);
    }
}

__global__ __launch_bounds__(256, 2)
void attn_tc(const __half* __restrict__ qv,
             const float* __restrict__ rpb,
             __half* __restrict__ outH) {
    extern __shared__ char dsm[];
    const uint32_t sbase = smem_u32(dsm);

    const int q0 = blockIdx.x * 128;
    const int bh = blockIdx.y;
    const int b = bh >> 3;
    const int h = bh & 7;

    const int tid  = threadIdx.x;
    const int wid  = tid >> 5;
    const int lane = tid & 31;

    const int lrow = lane & 7;
    const int sel  = lane >> 3;
    const int rofs = lrow + ((sel & 1) ? 8 : 0);
    const int kofs = (sel & 2) ? 8 : 0;

    // Precomputed addressing for QK (normal ldsm) and PV (trans ldsm)
    const uint32_t rxor = (uint32_t)lrow << 4;
    uint32_t krow[4], ccol[4];
    #pragma unroll
    for (int np = 0; np < 4; np++)
        krow[np] = (uint32_t)((np * 16 + rofs) * 128);
    #pragma unroll
    for (int kc = 0; kc < 4; kc++)
        ccol[kc] = ((uint32_t)((kc * 16 + kofs) * 2)) ^ rxor;

    const int g  = lane >> 3;
    const int rr = lane & 7;
    uint32_t vrow[4], vcol[4];
    #pragma unroll
    for (int kc = 0; kc < 4; kc++)
        vrow[kc] = (uint32_t)((kc * 16 + (g & 1) * 8 + rr) * 128);
    #pragma unroll
    for (int dp = 0; dp < 4; dp++)
        vcol[dp] = ((uint32_t)(dp * 32 + (g >> 1) * 16)) ^ ((uint32_t)rr << 4);

    #pragma unroll
    for (int j = 0; j < 4; j++) {
        int linear = tid + j * 256;
        int row = linear >> 3;
        int c = linear & 7;
        uint32_t dst = sbase + AT_Q + sw128((uint32_t)(row * 128 + c * 16));
        CP16(dst, (const char*)(qv + (size_t)(b * NN + q0 + row) * C3
                                + h * DH + c * 8));
    }
    attn_prefetch(qv, rpb, b, h, q0, 0, sbase, 0, tid);
    CP_COMMIT();
    attn_prefetch(qv, rpb, b, h, q0, 64, sbase, 1, tid);
    CP_COMMIT();

    uint32_t qf[4][4];
    float oacc[8][4] = {};
    float m0 = -CUDART_INF_F, m1 = -CUDART_INF_F;
    float l0 = 0.f, l1 = 0.f;

    const int NCHUNK = NN / 64;
    for (int c = 0; c < NCHUNK; c++) {
        const int s = c % 3;
        const uint32_t stage = sbase + AT_STAGE + s * 16384;
        const uint32_t bstage = sbase + AT_BIAS + s * 1024;
        if (c + 1 < NCHUNK) { CP_WAIT1(); } else { CP_WAIT0(); }
        __syncthreads();

        if (c == 0) {
            #pragma unroll
            for (int kc = 0; kc < 4; kc++)
                ldsm4(qf[kc], sbase + AT_Q
                      + (uint32_t)((wid * 16 + rofs) * 128) + ccol[kc]);
        }

        // ---- S = Q K^T ----
        float sacc[8][4] = {};
        #pragma unroll
        for (int kc = 0; kc < 4; kc++) {
            uint32_t kfA[4], kfB[4];
            ldsm4(kfA, stage + krow[0] + ccol[kc]);
            ldsm4(kfB, stage + krow[1] + ccol[kc]);
            mma16816(sacc[0], qf[kc], kfA[0], kfA[2]);
            mma16816(sacc[1], qf[kc], kfA[1], kfA[3]);
            ldsm4(kfA, stage + krow[2] + ccol[kc]);
            mma16816(sacc[2], qf[kc], kfB[0], kfB[2]);
            mma16816(sacc[3], qf[kc], kfB[1], kfB[3]);
            ldsm4(kfB, stage + krow[3] + ccol[kc]);
            mma16816(sacc[4], qf[kc], kfA[0], kfA[2]);
            mma16816(sacc[5], qf[kc], kfA[1], kfA[3]);
            mma16816(sacc[6], qf[kc], kfB[0], kfB[2]);
            mma16816(sacc[7], qf[kc], kfB[1], kfB[3]);
        }

        // ---- bias + online softmax ----
        const int r0 = wid * 16 + (lane >> 2);
        const int cb = (lane & 3) * 2;
        float mx0 = -CUDART_INF_F, mx1 = -CUDART_INF_F;
        #pragma unroll
        for (int nt = 0; nt < 8; nt++) {
            const int kk = nt * 8 + cb;
            float bv0, bv1, bv2, bv3;
            asm volatile("ld.shared.f32 %0, [%1];" : "=f"(bv0)
                         : "r"(bstage + (kk - r0 + 127) * 4));
            asm volatile("ld.shared.f32 %0, [%1];" : "=f"(bv1)
                         : "r"(bstage + (kk + 1 - r0 + 127) * 4));
            asm volatile("ld.shared.f32 %0, [%1];" : "=f"(bv2)
                         : "r"(bstage + (kk - (r0 + 8) + 127) * 4));
            asm volatile("ld.shared.f32 %0, [%1];" : "=f"(bv3)
                         : "r"(bstage + (kk + 1 - (r0 + 8) + 127) * 4));
            sacc[nt][0] = fmaf(sacc[nt][0], 0.125f, bv0);
            sacc[nt][1] = fmaf(sacc[nt][1], 0.125f, bv1);
            sacc[nt][2] = fmaf(sacc[nt][2], 0.125f, bv2);
            sacc[nt][3] = fmaf(sacc[nt][3], 0.125f, bv3);
            mx0 = fmaxf(mx0, fmaxf(sacc[nt][0], sacc[nt][1]));
            mx1 = fmaxf(mx1, fmaxf(sacc[nt][2], sacc[nt][3]));
        }
        mx0 = fmaxf(mx0, __shfl_xor_sync(0xffffffffu, mx0, 1));
        mx0 = fmaxf(mx0, __shfl_xor_sync(0xffffffffu, mx0, 2));
        mx1 = fmaxf(mx1, __shfl_xor_sync(0xffffffffu, mx1, 1));
        mx1 = fmaxf(mx1, __shfl_xor_sync(0xffffffffu, mx1, 2));
        const float mn0 = fmaxf(m0, mx0);
        const float mn1 = fmaxf(m1, mx1);
        const float fac0 = __expf(m0 - mn0);
        const float fac1 = __expf(m1 - mn1);
        float sum0 = 0.f, sum1 = 0.f;
        #pragma unroll
        for (int nt = 0; nt < 8; nt++) {
            sacc[nt][0] = __expf(sacc[nt][0] - mn0);
            sacc[nt][1] = __expf(sacc[nt][1] - mn0);
            sacc[nt][2] = __expf(sacc[nt][2] - mn1);
            sacc[nt][3] = __expf(sacc[nt][3] - mn1);
            sum0 += sacc[nt][0] + sacc[nt][1];
            sum1 += sacc[nt][2] + sacc[nt][3];
        }
        sum0 += __shfl_xor_sync(0xffffffffu, sum0, 1);
        sum0 += __shfl_xor_sync(0xffffffffu, sum0, 2);
        sum1 += __shfl_xor_sync(0xffffffffu, sum1, 1);
        sum1 += __shfl_xor_sync(0xffffffffu, sum1, 2);
        l0 = l0 * fac0 + sum0;
        l1 = l1 * fac1 + sum1;
        m0 = mn0;
        m1 = mn1;
        #pragma unroll
        for (int nt = 0; nt < 8; nt++) {
            oacc[nt][0] *= fac0;
            oacc[nt][1] *= fac0;
            oacc[nt][2] *= fac1;
            oacc[nt][3] *= fac1;
        }

        // ---- O += P V ----
        const uint32_t vbase = stage + 8192;
        #pragma unroll
        for (int kc = 0; kc < 4; kc++) {
            uint32_t pA[4];
            #pragma unroll
            for (int gg = 0; gg < 2; gg++) {
                const float* sv = sacc[2 * kc + gg];
                pA[2 * gg + 0] = pack_h2(sv[0], sv[1]);
                pA[2 * gg + 1] = pack_h2(sv[2], sv[3]);
            }
            uint32_t vfA[4], vfB[4];
            ldsm4t(vfA, vbase + vrow[kc] + vcol[0]);
            ldsm4t(vfB, vbase + vrow[kc] + vcol[1]);
            mma16816(oacc[0], pA, vfA[0], vfA[1]);
            mma16816(oacc[1], pA, vfA[2], vfA[3]);
            ldsm4t(vfA, vbase + vrow[kc] + vcol[2]);
            mma16816(oacc[2], pA, vfB[0], vfB[1]);
            mma16816(oacc[3], pA, vfB[2], vfB[3]);
            ldsm4t(vfB, vbase + vrow[kc] + vcol[3]);
            mma16816(oacc[4], pA, vfA[0], vfA[1]);
            mma16816(oacc[5], pA, vfA[2], vfA[3]);
            mma16816(oacc[6], pA, vfB[0], vfB[1]);
            mma16816(oacc[7], pA, vfB[2], vfB[3]);
        }

        if (c + 2 < NCHUNK) {
            attn_prefetch(qv, rpb, b, h, q0, (c + 2) * 64, sbase, (c + 2) % 3, tid);
            CP_COMMIT();
        }
    }

    // ---- epilogue ----
    const float il0 = 1.0f / l0;
    const float il1 = 1.0f / l1;
    const int row0 = b * NN + q0 + wid * 16 + (lane >> 2);
    const int colb = h * DH + (lane & 3) * 2;
    #pragma unroll
    for (int nt = 0; nt < 8; nt++) {
        const int col = colb + nt * 8;
        *(__half2*)(outH + (size_t)row0 * CC + col) =
            __floats2half2_rn(oacc[nt][0] * il0, oacc[nt][1] * il0);
        *(__half2*)(outH + (size_t)(row0 + 8) * CC + col) =
            __floats2half2_rn(oacc[nt][2] * il1, oacc[nt][3] * il1);
    }
}

// ---------------------------------------------------------------------------
// Launcher — fork/join graph
// ---------------------------------------------------------------------------
extern "C" void kernel_launch(void* const* d_in, const int* in_sizes, int n_in,
                              void* d_out, int out_size) {
    const float* x      = (const float*)d_in[0];
    const float* qkv_w  = (const float*)d_in[1];
    const float* proj_w = (const float*)d_in[2];
    const float* proj_b = (const float*)d_in[3];
    const float* rpb    = (const float*)d_in[4];
    const float* n1_w   = (const float*)d_in[5];
    const float* n1_b   = (const float*)d_in[6];
    const float* n2_w   = (const float*)d_in[7];
    const float* n2_b   = (const float*)d_in[8];
    const float* fc1_w  = (const float*)d_in[9];
    const float* fc1_b  = (const float*)d_in[10];
    const float* fc2_w  = (const float*)d_in[11];
    const float* fc2_b  = (const float*)d_in[12];
    float* out = (float*)d_out;

    float *x1;
    __half *qv, *h1, *at, *h2, *hd, *wq, *wp, *w1, *w2;
    cudaGetSymbolAddress((void**)&x1, g_x1);
    cudaGetSymbolAddress((void**)&qv, g_qv);
    cudaGetSymbolAddress((void**)&h1, g_h1);
    cudaGetSymbolAddress((void**)&at, g_at);
    cudaGetSymbolAddress((void**)&h2, g_h2);
    cudaGetSymbolAddress((void**)&hd, g_hd);
    cudaGetSymbolAddress((void**)&wq, g_wq);
    cudaGetSymbolAddress((void**)&wp, g_wp);
    cudaGetSymbolAddress((void**)&w1, g_w1);
    cudaGetSymbolAddress((void**)&w2, g_w2);

    cudaFuncSetAttribute(gemm_tc<1>, cudaFuncAttributeMaxDynamicSharedMemorySize, GEMM_SMEM_BYTES);
    cudaFuncSetAttribute(gemm_tc<2>, cudaFuncAttributeMaxDynamicSharedMemorySize, GEMM_SMEM_BYTES);
    cudaFuncSetAttribute(gemm_tc<3>, cudaFuncAttributeMaxDynamicSharedMemorySize, GEMM_SMEM_BYTES);
    cudaFuncSetAttribute(attn_tc, cudaFuncAttributeMaxDynamicSharedMemorySize, AT_SMEM_BYTES);

    cudaStream_t side;
    cudaEvent_t e_fork, e_wq, e_rest;
    cudaStreamCreateWithFlags(&side, cudaStreamNonBlocking);
    cudaEventCreateWithFlags(&e_fork, cudaEventDisableTiming);
    cudaEventCreateWithFlags(&e_wq,   cudaEventDisableTiming);
    cudaEventCreateWithFlags(&e_rest, cudaEventDisableTiming);

    cudaEventRecord(e_fork, 0);
    cudaStreamWaitEvent(side, e_fork, 0);

    cvt_w<<<(C3 * CC) / 1024, 256, 0, side>>>(qkv_w, wq, (C3 * CC) / 4);
    cudaEventRecord(e_wq, side);
    cvt3_w<<<(CVT3_TOTAL + 255) / 256, 256, 0, side>>>(proj_w, fc1_w, fc2_w,
                                                       wp, w1, w2);
    cudaEventRecord(e_rest, side);

    ln_kernel<<<MROWS / 8, 256>>>(x, n1_w, n1_b, h1);

    cudaStreamWaitEvent(0, e_wq, 0);
    gemm_tc<3><<<dim3(C3 / 128, MROWS / 128), 256, GEMM_SMEM_BYTES>>>(
        h1, wq, nullptr, nullptr, nullptr, qv, MROWS, C3, CC);

    attn_tc<<<dim3(NN / 128, BB * HH), 256, AT_SMEM_BYTES>>>(qv, rpb, at);

    cudaStreamWaitEvent(0, e_rest, 0);
    gemm_tc<1><<<dim3(CC / 128, MROWS / 128), 256, GEMM_SMEM_BYTES>>>(
        at, wp, proj_b, x, x1, nullptr, MROWS, CC, CC);
    ln_kernel<<<MROWS / 8, 256>>>(x1, n2_w, n2_b, h2);
    gemm_tc<2><<<dim3(HID / 128, MROWS / 128), 256, GEMM_SMEM_BYTES>>>(
        h2, w1, fc1_b, nullptr, nullptr, hd, MROWS, HID, CC);
    gemm_tc<1><<<dim3(CC / 128, MROWS / 128), 256, GEMM_SMEM_BYTES>>>(
        hd, w2, fc2_b, x1, out, nullptr, MROWS, CC, HID);

    cudaEventDestroy(e_fork);
    cudaEventDestroy(e_wq);
    cudaEventDestroy(e_rest);
    cudaStreamDestroy(side);
}